// round 2
// baseline (speedup 1.0000x reference)
#include <cuda_runtime.h>
#include <cuda_bf16.h>
#include <math.h>

// ---------------------------------------------------------------------------
// Shapes
// ---------------------------------------------------------------------------
#define BB 32
#define LL 128
#define NN 512
#define JJ 21
#define HAND_DIM 99
#define DD 512
#define HH 8
#define DHH 64
#define DFF 2048
#define CAT 1249
#define CATP 1280         // padded K for fc GEMM (16-aligned, float4-aligned)
#define SS 256            // 2*L
#define ROWS 4096         // B*L
#define TROWS 8192        // B*S

// feature layout offsets
#define F_X 0
#define F_J 99
#define F_MC 162
#define F_PCN 674
#define F_ATT 1186

// ---------------------------------------------------------------------------
// Scratch (device globals)
// ---------------------------------------------------------------------------
__device__ float g_feat_l[ROWS * CATP];
__device__ float g_feat_r[ROWS * CATP];
__device__ float g_x [TROWS * DD];
__device__ float g_q [TROWS * DD];
__device__ float g_k [TROWS * DD];
__device__ float g_v [TROWS * DD];
__device__ float g_ao [TROWS * DD];
__device__ float g_proj[TROWS * DD];
__device__ float g_x1 [TROWS * DD];
__device__ float g_h [TROWS * DFF];
__device__ float g_f [TROWS * DD];
__device__ float g_x2 [TROWS * DD];

// ---------------------------------------------------------------------------
// Kernel 1: build feature rows [x(99) | j(63) | mc(512) | pcn(512) | att(63)]
// ---------------------------------------------------------------------------
__global__ void build_features_kernel(
    const float* __restrict__ x_l, const float* __restrict__ x_r,
    const float* __restrict__ j_l, const float* __restrict__ j_r,
    const float* __restrict__ m_contact, const float* __restrict__ pc,
    float* __restrict__ feat_l, float* __restrict__ feat_r)
{
    int m = blockIdx.x;            // b*128 + l
    int b = m >> 7;
    __shared__ float px[NN], py[NN], pz[NN];
    int tid = threadIdx.x;

    const float* pcb = pc + (size_t)m * NN * 3;
    for (int n = tid; n < NN; n += 256) {
        px[n] = pcb[n*3+0];
        py[n] = pcb[n*3+1];
        pz[n] = pcb[n*3+2];
    }
    __syncthreads();

    float* fl = feat_l + (size_t)m * CATP;
    float* fr = feat_r + (size_t)m * CATP;

    for (int i = tid; i < HAND_DIM; i += 256) {
        fl[F_X+i] = x_l[(size_t)m*HAND_DIM + i];
        fr[F_X+i] = x_r[(size_t)m*HAND_DIM + i];
    }
    for (int i = tid; i < JJ*3; i += 256) {
        fl[F_J+i] = j_l[(size_t)m*JJ*3 + i];
        fr[F_J+i] = j_r[(size_t)m*JJ*3 + i];
    }
    for (int n = tid; n < NN; n += 256) {
        float mc = m_contact[b*NN + n];
        fl[F_MC+n] = mc; fr[F_MC+n] = mc;
        float nm = sqrtf(px[n]*px[n] + py[n]*py[n] + pz[n]*pz[n]);
        fl[F_PCN+n] = nm; fr[F_PCN+n] = nm;
    }
    // zero the K padding so the padded GEMM needs no A-guard
    for (int i = CAT + tid; i < CATP; i += 256) { fl[i] = 0.f; fr[i] = 0.f; }

    int w = tid >> 5, lane = tid & 31;
    for (int task = w; task < 2*JJ; task += 8) {
        int hand = task / JJ, joint = task % JJ;
        const float* jb = (hand == 0 ? j_l : j_r) + ((size_t)m*JJ + joint)*3;
        float jx = jb[0], jy = jb[1], jz = jb[2];
        float best = 3.402823466e+38f; int bi = 0;
        for (int n = lane; n < NN; n += 32) {
            float dx = jx - px[n], dy = jy - py[n], dz = jz - pz[n];
            float d2 = dx*dx + dy*dy + dz*dz;
            if (d2 < best) { best = d2; bi = n; }
        }
        for (int off = 16; off; off >>= 1) {
            float ob = __shfl_xor_sync(0xffffffffu, best, off);
            int   oi = __shfl_xor_sync(0xffffffffu, bi, off);
            if (ob < best || (ob == best && oi < bi)) { best = ob; bi = oi; }
        }
        if (lane == 0) {
            float dx = jx - px[bi], dy = jy - py[bi], dz = jz - pz[bi];
            float* f = (hand == 0 ? fl : fr);
            f[F_ATT + joint*3 + 0] = expf(-50.f * dx * dx);
            f[F_ATT + joint*3 + 1] = expf(-50.f * dy * dy);
            f[F_ATT + joint*3 + 2] = expf(-50.f * dz * dz);
        }
    }
}

// ---------------------------------------------------------------------------
// Epilogue params shared by GEMMs
// ---------------------------------------------------------------------------
struct EpiParams {
    const float* bias;
    const float* mask;           // [4096]
    const unsigned char* pad;    // [8192] bool
    int hand;
    int relu;
};

#define LN10000 9.2103403719761827f

template<int EPI>
__device__ __forceinline__ float apply_epi(float v, int row, int col, const EpiParams& ep)
{
    if (EPI == 0) {
        if (ep.bias) v += ep.bias[col];
        if (ep.relu) v = fmaxf(v, 0.f);
    } else if (EPI == 1) {
        int l = row & 127;
        int ii = col >> 1;
        float freq = expf(-LN10000 * (float)ii * (1.f/256.f));
        float angF = (float)l * freq;
        float angA = (float)ep.hand * freq;
        float pe = (col & 1) ? (cosf(angF) + cosf(angA))
                             : (sinf(angF) + sinf(angA));
        float mv = ep.mask[row] * (ep.pad[2*row + ep.hand] ? 0.f : 1.f);
        v = (v + ep.bias[col] + pe) * mv;
    } else { // EPI == 2
        float mv = ep.mask[row] * (ep.pad[2*row + ep.hand] ? 0.f : 1.f);
        v = (v + ep.bias[col]) * mv;
    }
    return v;
}

// ---------------------------------------------------------------------------
// 3xTF32 tensor-core GEMM. Block 128x128, BK=16, 8 warps (64x32 warp tiles).
// Smem holds A/B in exact mma fragment layout (hi+lo), double buffered.
// Requires: M%128==0, N%128==0, lda%4==0, A zero-padded up to ceil16(Kreal).
// ---------------------------------------------------------------------------
#define TG_SMEM (16384 * 4)   // 2 bufs * 8192 floats

__device__ __forceinline__ float totf32(float v) {
    unsigned u;
    asm("cvt.rna.tf32.f32 %0, %1;" : "=r"(u) : "f"(v));
    return __uint_as_float(u);
}

__device__ __forceinline__ void mma8(float* c, const float4& a, const float2& b) {
    asm volatile(
        "mma.sync.aligned.m16n8k8.row.col.f32.tf32.tf32.f32 "
        "{%0,%1,%2,%3}, {%4,%5,%6,%7}, {%8,%9}, {%0,%1,%2,%3};"
        : "+f"(c[0]), "+f"(c[1]), "+f"(c[2]), "+f"(c[3])
        : "r"(__float_as_uint(a.x)), "r"(__float_as_uint(a.y)),
          "r"(__float_as_uint(a.z)), "r"(__float_as_uint(a.w)),
          "r"(__float_as_uint(b.x)), "r"(__float_as_uint(b.y)));
}

template<int EPI>
__global__ __launch_bounds__(256, 1)
void tgemm(const float* __restrict__ A, int lda,
           const float* __restrict__ B, int ldb,
           float* __restrict__ C, int ldc,
           int M, int N, int Kreal, EpiParams ep)
{
    extern __shared__ float sm[];
    int tid = threadIdx.x;
    int lane = tid & 31, wid = tid >> 5;
    int warp_m = wid & 1, warp_n = wid >> 1;
    int wm0 = warp_m * 64, wn0 = warp_n * 32, wn4 = warp_n * 4;
    int m0 = blockIdx.y * 128, n0 = blockIdx.x * 128;
    int g = lane >> 2, t = lane & 3;

    float acc[4][4][4];
    #pragma unroll
    for (int i = 0; i < 4; i++)
        #pragma unroll
        for (int j = 0; j < 4; j++)
            #pragma unroll
            for (int e = 0; e < 4; e++) acc[i][j][e] = 0.f;

    // precompute scatter indices (thread-invariant across k-tiles)
    int idxA[2][4], idxB[2][4];
    int arow[2], acol[2], brow[2], bcol[2];
    #pragma unroll
    for (int i = 0; i < 2; i++) {
        int f = tid + 256*i;
        {
            int r = f >> 2, c4 = f & 3;
            arow[i] = r; acol[i] = c4 * 4;
            int mt = r >> 4, top = (r >> 3) & 1, gg = r & 7;
            #pragma unroll
            for (int e = 0; e < 4; e++) {
                int c = c4*4 + e;
                int ks = c >> 3, half = (c >> 2) & 1, tt = c & 3;
                idxA[i][e] = ((mt*2 + ks)*32 + gg*4 + tt)*4 + top + 2*half;
            }
        }
        {
            int r = f >> 5, c4 = f & 31;
            brow[i] = r; bcol[i] = c4 * 4;
            int ks = r >> 3, tt = r & 3, comp = (r >> 2) & 1;
            #pragma unroll
            for (int e = 0; e < 4; e++) {
                int c = c4*4 + e;
                int nt = c >> 3, gg = c & 7;
                idxB[i][e] = ((ks*16 + nt)*32 + gg*4 + tt)*2 + comp;
            }
        }
    }

    int nk = (Kreal + 15) >> 4;
    float4 ra[2], rb[2];

    auto load_tile = [&](int kt) {
        int k0 = kt * 16;
        #pragma unroll
        for (int i = 0; i < 2; i++) {
            ra[i] = *(const float4*)(A + (size_t)(m0 + arow[i])*lda + k0 + acol[i]);
            int k = k0 + brow[i];
            if (k < Kreal)
                rb[i] = *(const float4*)(B + (size_t)k*ldb + n0 + bcol[i]);
            else
                rb[i] = make_float4(0.f, 0.f, 0.f, 0.f);
        }
    };
    auto store_tile = [&](int buf) {
        float* bs = sm + buf * 8192;
        #pragma unroll
        for (int i = 0; i < 2; i++) {
            float va[4] = {ra[i].x, ra[i].y, ra[i].z, ra[i].w};
            #pragma unroll
            for (int e = 0; e < 4; e++) {
                float hi = totf32(va[e]);
                float lo = totf32(va[e] - hi);
                bs[idxA[i][e]]        = hi;
                bs[idxA[i][e] + 2048] = lo;
            }
            float vb[4] = {rb[i].x, rb[i].y, rb[i].z, rb[i].w};
            #pragma unroll
            for (int e = 0; e < 4; e++) {
                float hi = totf32(vb[e]);
                float lo = totf32(vb[e] - hi);
                bs[4096 + idxB[i][e]]        = hi;
                bs[4096 + idxB[i][e] + 2048] = lo;
            }
        }
    };

    load_tile(0);
    store_tile(0);
    __syncthreads();

    for (int kt = 0; kt < nk; kt++) {
        if (kt + 1 < nk) load_tile(kt + 1);

        int buf = kt & 1;
        const float4* A4h = (const float4*)(sm + buf*8192);
        const float4* A4l = (const float4*)(sm + buf*8192 + 2048);
        const float2* B2h = (const float2*)(sm + buf*8192 + 4096);
        const float2* B2l = (const float2*)(sm + buf*8192 + 6144);

        #pragma unroll
        for (int ks = 0; ks < 2; ks++) {
            float4 ah[4], al[4];
            float2 bh[4], bl[4];
            #pragma unroll
            for (int mt = 0; mt < 4; mt++) {
                int ai = ((warp_m*4 + mt)*2 + ks)*32 + lane;
                // warp_m offset: A fragment tiles are per-block (8 m16 tiles);
                // this warp's tiles are warp_m*4 .. warp_m*4+3
                ah[mt] = A4h[ai];
                al[mt] = A4l[ai];
            }
            #pragma unroll
            for (int nt = 0; nt < 4; nt++) {
                int bi = (ks*16 + wn4 + nt)*32 + lane;
                bh[nt] = B2h[bi];
                bl[nt] = B2l[bi];
            }
            #pragma unroll
            for (int mt = 0; mt < 4; mt++)
                #pragma unroll
                for (int nt = 0; nt < 4; nt++) {
                    mma8(acc[mt][nt], ah[mt], bh[nt]);
                    mma8(acc[mt][nt], al[mt], bh[nt]);
                    mma8(acc[mt][nt], ah[mt], bl[nt]);
                }
        }

        if (kt + 1 < nk) store_tile((kt + 1) & 1);
        __syncthreads();
    }

    // epilogue
    #pragma unroll
    for (int mt = 0; mt < 4; mt++) {
        int row0 = m0 + wm0 + mt*16 + g;
        #pragma unroll
        for (int nt = 0; nt < 4; nt++) {
            int col = n0 + wn0 + nt*8 + t*2;
            float* c = acc[mt][nt];
            float v0 = apply_epi<EPI>(c[0], row0,     col,     ep);
            float v1 = apply_epi<EPI>(c[1], row0,     col + 1, ep);
            float v2 = apply_epi<EPI>(c[2], row0 + 8, col,     ep);
            float v3 = apply_epi<EPI>(c[3], row0 + 8, col + 1, ep);
            *(float2*)(C + (size_t)row0*ldc + col)       = make_float2(v0, v1);
            *(float2*)(C + (size_t)(row0 + 8)*ldc + col) = make_float2(v2, v3);
        }
    }
}

// NOTE on A fragment indexing above: the A staging stores all 8 m16 tiles of the
// 128-row block tile; index mt within a warp maps to block tile warp_m*4+mt.

// ---------------------------------------------------------------------------
// fp32 fallback GEMM (used only for the small N=99 output heads)
// ---------------------------------------------------------------------------
template<int EPI>
__global__ __launch_bounds__(256)
void gemm128(const float* __restrict__ A, int lda,
             const float* __restrict__ B, int ldb,
             float* __restrict__ C, int ldc,
             int M, int N, int K, EpiParams ep)
{
    __shared__ float As[8][128];
    __shared__ float Bs[8][128];
    int tid = threadIdx.x;
    int tx = tid & 15, ty = tid >> 4;
    int m0 = blockIdx.y * 128, n0 = blockIdx.x * 128;

    float acc[8][8];
    #pragma unroll
    for (int i = 0; i < 8; i++)
        #pragma unroll
        for (int j = 0; j < 8; j++) acc[i][j] = 0.f;

    int arow = tid >> 1;
    int ak   = (tid & 1) * 4;

    for (int k0 = 0; k0 < K; k0 += 8) {
        #pragma unroll
        for (int i = 0; i < 4; i++) {
            int k = k0 + ak + i;
            As[ak+i][arow] = (k < K) ? A[(size_t)(m0+arow)*lda + k] : 0.f;
        }
        #pragma unroll
        for (int i = 0; i < 4; i++) {
            int idx = tid + 256*i;
            int r = idx >> 7, c = idx & 127;
            int k = k0 + r;
            Bs[r][c] = (k < K && (n0 + c) < N) ? B[(size_t)k*ldb + n0 + c] : 0.f;
        }
        __syncthreads();
        #pragma unroll
        for (int k = 0; k < 8; k++) {
            float4 a0 = *(const float4*)&As[k][ty*8];
            float4 a1 = *(const float4*)&As[k][ty*8+4];
            float4 b0 = *(const float4*)&Bs[k][tx*8];
            float4 b1 = *(const float4*)&Bs[k][tx*8+4];
            float ra_[8] = {a0.x,a0.y,a0.z,a0.w,a1.x,a1.y,a1.z,a1.w};
            float rb_[8] = {b0.x,b0.y,b0.z,b0.w,b1.x,b1.y,b1.z,b1.w};
            #pragma unroll
            for (int i = 0; i < 8; i++)
                #pragma unroll
                for (int j = 0; j < 8; j++)
                    acc[i][j] += ra_[i]*rb_[j];
        }
        __syncthreads();
    }

    #pragma unroll
    for (int i = 0; i < 8; i++) {
        int row = m0 + ty*8 + i;
        if (row >= M) continue;
        #pragma unroll
        for (int j = 0; j < 8; j++) {
            int col = n0 + tx*8 + j;
            if (col >= N) continue;
            C[(size_t)row*ldc + col] = apply_epi<EPI>(acc[i][j], row, col, ep);
        }
    }
}

// ---------------------------------------------------------------------------
// Fused attention (unchanged)
// ---------------------------------------------------------------------------
#define KV_PITCH 65
#define ATT_SMEM ((2*256*KV_PITCH + 8*256 + 8*64 + 256) * (int)sizeof(float))

__global__ void attention_kernel(const float* __restrict__ qb,
                                 const float* __restrict__ kb,
                                 const float* __restrict__ vb,
                                 const unsigned char* __restrict__ pad,
                                 float* __restrict__ ob)
{
    int bh = blockIdx.x;
    int b = bh >> 3, h = bh & 7;
    extern __shared__ float sm[];
    float* Ks = sm;
    float* Vs = Ks + 256*KV_PITCH;
    float* Ps = Vs + 256*KV_PITCH;
    float* Qs = Ps + 8*256;
    float* Bsb = Qs + 8*64;

    int tid = threadIdx.x, lane = tid & 31, w = tid >> 5;
    const float* kbase = kb + (size_t)(b*SS)*DD + h*DHH;
    const float* vbase = vb + (size_t)(b*SS)*DD + h*DHH;

    for (int idx = tid; idx < 256*64; idx += 256) {
        int r = idx >> 6, c = idx & 63;
        Ks[r*KV_PITCH + c] = kbase[(size_t)r*DD + c];
        Vs[r*KV_PITCH + c] = vbase[(size_t)r*DD + c];
    }
    if (tid < 256) Bsb[tid] = pad[b*SS + tid] ? -1e9f : 0.f;
    __syncthreads();

    float* Pw = Ps + w*256;
    float* Qw = Qs + w*64;

    for (int qi = w; qi < SS; qi += 8) {
        const float* qrow = qb + (size_t)(b*SS + qi)*DD + h*DHH;
        Qw[lane]      = qrow[lane];
        Qw[lane + 32] = qrow[lane + 32];
        __syncwarp();

        float s[8];
        float mx = -3.402823466e+38f;
        #pragma unroll
        for (int k8 = 0; k8 < 8; k8++) {
            int j = lane + 32*k8;
            const float* kr = Ks + j*KV_PITCH;
            float acc = 0.f;
            #pragma unroll
            for (int d = 0; d < 64; d++) acc += Qw[d]*kr[d];
            acc = acc * 0.125f + Bsb[j];
            s[k8] = acc;
            mx = fmaxf(mx, acc);
        }
        for (int off = 16; off; off >>= 1)
            mx = fmaxf(mx, __shfl_xor_sync(0xffffffffu, mx, off));
        float sum = 0.f;
        #pragma unroll
        for (int k8 = 0; k8 < 8; k8++) { s[k8] = __expf(s[k8]-mx); sum += s[k8]; }
        for (int off = 16; off; off >>= 1)
            sum += __shfl_xor_sync(0xffffffffu, sum, off);
        float inv = 1.f / sum;
        #pragma unroll
        for (int k8 = 0; k8 < 8; k8++) Pw[lane + 32*k8] = s[k8]*inv;
        __syncwarp();

        float o0 = 0.f, o1 = 0.f;
        for (int j = 0; j < 256; j++) {
            float p = Pw[j];
            o0 += p * Vs[j*KV_PITCH + lane];
            o1 += p * Vs[j*KV_PITCH + lane + 32];
        }
        float* orow = ob + (size_t)(b*SS + qi)*DD + h*DHH;
        orow[lane]      = o0;
        orow[lane + 32] = o1;
        __syncwarp();
    }
}

// ---------------------------------------------------------------------------
// Residual add + LayerNorm
// ---------------------------------------------------------------------------
__global__ void ln_kernel(const float* __restrict__ x, const float* __restrict__ add,
                          const float* __restrict__ g, const float* __restrict__ bv,
                          float* __restrict__ out)
{
    int t = blockIdx.x;
    int tid = threadIdx.x;            // 128
    const float* xr = x   + (size_t)t*DD;
    const float* ar = add + (size_t)t*DD;
    float v[4];
    float s = 0.f, ss = 0.f;
    #pragma unroll
    for (int i = 0; i < 4; i++) {
        float u = xr[tid + 128*i] + ar[tid + 128*i];
        v[i] = u; s += u; ss += u*u;
    }
    for (int off = 16; off; off >>= 1) {
        s  += __shfl_xor_sync(0xffffffffu, s,  off);
        ss += __shfl_xor_sync(0xffffffffu, ss, off);
    }
    __shared__ float rs[4], rss[4];
    int w = tid >> 5, lane = tid & 31;
    if (lane == 0) { rs[w] = s; rss[w] = ss; }
    __syncthreads();
    s  = rs[0]+rs[1]+rs[2]+rs[3];
    ss = rss[0]+rss[1]+rss[2]+rss[3];
    float mean = s * (1.f/512.f);
    float var  = ss * (1.f/512.f) - mean*mean;
    float rstd = rsqrtf(var + 1e-5f);
    #pragma unroll
    for (int i = 0; i < 4; i++) {
        int c = tid + 128*i;
        out[(size_t)t*DD + c] = (v[i]-mean)*rstd*g[c] + bv[c];
    }
}

// ---------------------------------------------------------------------------
// Launch
// ---------------------------------------------------------------------------
extern "C" void kernel_launch(void* const* d_in, const int* in_sizes, int n_in,
                              void* d_out, int out_size)
{
    const float* x_l  = (const float*)d_in[0];
    const float* x_r  = (const float*)d_in[1];
    const float* j_l  = (const float*)d_in[2];
    const float* j_r  = (const float*)d_in[3];
    const float* mcon = (const float*)d_in[4];
    const float* pc   = (const float*)d_in[5];
    const float* mask_l = (const float*)d_in[6];
    const float* mask_r = (const float*)d_in[7];
    const unsigned char* pad = (const unsigned char*)d_in[8];
    const float* W_fc_l = (const float*)d_in[9];
    const float* b_fc_l = (const float*)d_in[10];
    const float* W_fc_r = (const float*)d_in[11];
    const float* b_fc_r = (const float*)d_in[12];
    const float* Wq = (const float*)d_in[13];
    const float* Wk = (const float*)d_in[14];
    const float* Wv = (const float*)d_in[15];
    const float* Wo = (const float*)d_in[16];
    const float* W1 = (const float*)d_in[17];
    const float* b1 = (const float*)d_in[18];
    const float* W2 = (const float*)d_in[19];
    const float* b2 = (const float*)d_in[20];
    const float* ln1g = (const float*)d_in[21];
    const float* ln1b = (const float*)d_in[22];
    const float* ln2g = (const float*)d_in[23];
    const float* ln2b = (const float*)d_in[24];
    const float* W_out_l = (const float*)d_in[25];
    const float* b_out_l = (const float*)d_in[26];
    const float* W_out_r = (const float*)d_in[27];
    const float* b_out_r = (const float*)d_in[28];
    float* outp = (float*)d_out;

    float *pfl, *pfr, *px, *pq, *pk, *pv, *pao, *pproj, *px1, *ph, *pf, *px2;
    cudaGetSymbolAddress((void**)&pfl,  g_feat_l);
    cudaGetSymbolAddress((void**)&pfr,  g_feat_r);
    cudaGetSymbolAddress((void**)&px,   g_x);
    cudaGetSymbolAddress((void**)&pq,   g_q);
    cudaGetSymbolAddress((void**)&pk,   g_k);
    cudaGetSymbolAddress((void**)&pv,   g_v);
    cudaGetSymbolAddress((void**)&pao,  g_ao);
    cudaGetSymbolAddress((void**)&pproj,g_proj);
    cudaGetSymbolAddress((void**)&px1,  g_x1);
    cudaGetSymbolAddress((void**)&ph,   g_h);
    cudaGetSymbolAddress((void**)&pf,   g_f);
    cudaGetSymbolAddress((void**)&px2,  g_x2);

    cudaFuncSetAttribute(tgemm<0>, cudaFuncAttributeMaxDynamicSharedMemorySize, TG_SMEM);
    cudaFuncSetAttribute(tgemm<1>, cudaFuncAttributeMaxDynamicSharedMemorySize, TG_SMEM);
    cudaFuncSetAttribute(attention_kernel,
                         cudaFuncAttributeMaxDynamicSharedMemorySize, ATT_SMEM);

    // 1. features (padded K layout)
    build_features_kernel<<<ROWS, 256>>>(x_l, x_r, j_l, j_r, mcon, pc, pfl, pfr);

    // 2. fc projections -> interleaved x with PE + masks   (K=1249, A padded)
    EpiParams fc_el = {b_fc_l, mask_l, pad, 0, 0};
    EpiParams fc_er = {b_fc_r, mask_r, pad, 1, 0};
    tgemm<1><<<dim3(4,32), 256, TG_SMEM>>>(pfl, CATP, W_fc_l, DD, px,      2*DD, ROWS, DD, CAT, fc_el);
    tgemm<1><<<dim3(4,32), 256, TG_SMEM>>>(pfr, CATP, W_fc_r, DD, px + DD, 2*DD, ROWS, DD, CAT, fc_er);

    // 3. QKV
    EpiParams none = {nullptr, nullptr, nullptr, 0, 0};
    tgemm<0><<<dim3(4,64), 256, TG_SMEM>>>(px, DD, Wq, DD, pq, DD, TROWS, DD, DD, none);
    tgemm<0><<<dim3(4,64), 256, TG_SMEM>>>(px, DD, Wk, DD, pk, DD, TROWS, DD, DD, none);
    tgemm<0><<<dim3(4,64), 256, TG_SMEM>>>(px, DD, Wv, DD, pv, DD, TROWS, DD, DD, none);

    // 4. fused attention
    attention_kernel<<<BB*HH, 256, ATT_SMEM>>>(pq, pk, pv, pad, pao);

    // 5. output projection + LN1
    tgemm<0><<<dim3(4,64), 256, TG_SMEM>>>(pao, DD, Wo, DD, pproj, DD, TROWS, DD, DD, none);
    ln_kernel<<<TROWS, 128>>>(px, pproj, ln1g, ln1b, px1);

    // 6. FFN + LN2
    EpiParams e1 = {b1, nullptr, nullptr, 0, 1};
    EpiParams e2 = {b2, nullptr, nullptr, 0, 0};
    tgemm<0><<<dim3(16,64), 256, TG_SMEM>>>(px1, DD, W1, DFF, ph, DFF, TROWS, DFF, DD, e1);
    tgemm<0><<<dim3(4,64),  256, TG_SMEM>>>(ph, DFF, W2, DD, pf, DD, TROWS, DD, DFF, e2);
    ln_kernel<<<TROWS, 128>>>(px1, pf, ln2g, ln2b, px2);

    // 7. per-hand output heads (small, fp32 path)
    EpiParams ol = {b_out_l, mask_l, pad, 0, 0};
    EpiParams orr= {b_out_r, mask_r, pad, 1, 0};
    gemm128<2><<<dim3(1,32), 256>>>(px2,      2*DD, W_out_l, HAND_DIM,
                                    outp,                 HAND_DIM, ROWS, HAND_DIM, DD, ol);
    gemm128<2><<<dim3(1,32), 256>>>(px2 + DD, 2*DD, W_out_r, HAND_DIM,
                                    outp + ROWS*HAND_DIM, HAND_DIM, ROWS, HAND_DIM, DD, orr);
}

// round 3
// speedup vs baseline: 2.5783x; 2.5783x over previous
#include <cuda_runtime.h>
#include <cuda_bf16.h>
#include <math.h>

// ---------------------------------------------------------------------------
// Shapes
// ---------------------------------------------------------------------------
#define BB 32
#define LL 128
#define NN 512
#define JJ 21
#define HAND_DIM 99
#define DD 512
#define HH 8
#define DHH 64
#define DFF 2048
#define CAT 1249
#define CATP 1280         // padded K for fc GEMM (32-aligned)
#define SS 256            // 2*L
#define ROWS 4096         // B*L
#define TROWS 8192        // B*S

// feature layout offsets
#define F_X 0
#define F_J 99
#define F_MC 162
#define F_PCN 674
#define F_ATT 1186

// ---------------------------------------------------------------------------
// Scratch (device globals)
// ---------------------------------------------------------------------------
__device__ float g_feat_l[ROWS * CATP];
__device__ float g_feat_r[ROWS * CATP];
__device__ float g_x [TROWS * DD];
__device__ float g_q [TROWS * DD];
__device__ float g_k [TROWS * DD];
__device__ float g_v [TROWS * DD];
__device__ float g_ao [TROWS * DD];
__device__ float g_proj[TROWS * DD];
__device__ float g_x1 [TROWS * DD];
__device__ float g_h [TROWS * DFF];
__device__ float g_f [TROWS * DD];
__device__ float g_x2 [TROWS * DD];

// ---------------------------------------------------------------------------
// Kernel 1: build feature rows
// ---------------------------------------------------------------------------
__global__ void build_features_kernel(
    const float* __restrict__ x_l, const float* __restrict__ x_r,
    const float* __restrict__ j_l, const float* __restrict__ j_r,
    const float* __restrict__ m_contact, const float* __restrict__ pc,
    float* __restrict__ feat_l, float* __restrict__ feat_r)
{
    int m = blockIdx.x;            // b*128 + l
    int b = m >> 7;
    __shared__ float px[NN], py[NN], pz[NN];
    int tid = threadIdx.x;

    const float* pcb = pc + (size_t)m * NN * 3;
    for (int n = tid; n < NN; n += 256) {
        px[n] = pcb[n*3+0];
        py[n] = pcb[n*3+1];
        pz[n] = pcb[n*3+2];
    }
    __syncthreads();

    float* fl = feat_l + (size_t)m * CATP;
    float* fr = feat_r + (size_t)m * CATP;

    for (int i = tid; i < HAND_DIM; i += 256) {
        fl[F_X+i] = x_l[(size_t)m*HAND_DIM + i];
        fr[F_X+i] = x_r[(size_t)m*HAND_DIM + i];
    }
    for (int i = tid; i < JJ*3; i += 256) {
        fl[F_J+i] = j_l[(size_t)m*JJ*3 + i];
        fr[F_J+i] = j_r[(size_t)m*JJ*3 + i];
    }
    for (int n = tid; n < NN; n += 256) {
        float mc = m_contact[b*NN + n];
        fl[F_MC+n] = mc; fr[F_MC+n] = mc;
        float nm = sqrtf(px[n]*px[n] + py[n]*py[n] + pz[n]*pz[n]);
        fl[F_PCN+n] = nm; fr[F_PCN+n] = nm;
    }
    for (int i = CAT + tid; i < CATP; i += 256) { fl[i] = 0.f; fr[i] = 0.f; }

    int w = tid >> 5, lane = tid & 31;
    for (int task = w; task < 2*JJ; task += 8) {
        int hand = task / JJ, joint = task % JJ;
        const float* jb = (hand == 0 ? j_l : j_r) + ((size_t)m*JJ + joint)*3;
        float jx = jb[0], jy = jb[1], jz = jb[2];
        float best = 3.402823466e+38f; int bi = 0;
        for (int n = lane; n < NN; n += 32) {
            float dx = jx - px[n], dy = jy - py[n], dz = jz - pz[n];
            float d2 = dx*dx + dy*dy + dz*dz;
            if (d2 < best) { best = d2; bi = n; }
        }
        for (int off = 16; off; off >>= 1) {
            float ob = __shfl_xor_sync(0xffffffffu, best, off);
            int   oi = __shfl_xor_sync(0xffffffffu, bi, off);
            if (ob < best || (ob == best && oi < bi)) { best = ob; bi = oi; }
        }
        if (lane == 0) {
            float dx = jx - px[bi], dy = jy - py[bi], dz = jz - pz[bi];
            float* f = (hand == 0 ? fl : fr);
            f[F_ATT + joint*3 + 0] = expf(-50.f * dx * dx);
            f[F_ATT + joint*3 + 1] = expf(-50.f * dy * dy);
            f[F_ATT + joint*3 + 2] = expf(-50.f * dz * dz);
        }
    }
}

// ---------------------------------------------------------------------------
// Epilogues
// ---------------------------------------------------------------------------
struct EpiParams {
    const float* bias;
    const float* mask;           // [4096]
    const unsigned char* pad;    // [8192] bool
    int hand;
    int relu;
};

#define LN10000 9.2103403719761827f

template<int EPI>
__device__ __forceinline__ float apply_epi(float v, int row, int col, const EpiParams& ep)
{
    if (EPI == 0) {
        if (ep.bias) v += ep.bias[col];
        if (ep.relu) v = fmaxf(v, 0.f);
    } else if (EPI == 1) {
        int l = row & 127;
        int ii = col >> 1;
        float freq = expf(-LN10000 * (float)ii * (1.f/256.f));
        float angF = (float)l * freq;
        float angA = (float)ep.hand * freq;
        float pe = (col & 1) ? (cosf(angF) + cosf(angA))
                             : (sinf(angF) + sinf(angA));
        float mv = ep.mask[row] * (ep.pad[2*row + ep.hand] ? 0.f : 1.f);
        v = (v + ep.bias[col] + pe) * mv;
    } else { // EPI == 2
        float mv = ep.mask[row] * (ep.pad[2*row + ep.hand] ? 0.f : 1.f);
        v = (v + ep.bias[col]) * mv;
    }
    return v;
}

// ---------------------------------------------------------------------------
// bf16x3 tensor-core GEMM.
// Block 128x128, BK=32, 8 warps (warp tile 64x32: warp_m in {0,1}, warp_n 0..3).
// A,B staged in smem as row-major bf16 hi/lo tiles; fragments via ldmatrix.
// Requires M%128==0, N%128==0, lda%4==0, A zero-padded to 32-multiple K.
// ---------------------------------------------------------------------------
#define PA 80                         // A tile pitch bytes (40 bf16; 5 granules, odd -> conflict-free)
#define PB 272                        // B tile pitch bytes (136 bf16; 17 granules)
#define A_BYTES (128*PA)              // 10240
#define B_BYTES (32*PB)               // 8704
#define OFF_AH 0
#define OFF_AL (A_BYTES)
#define OFF_BH (2*A_BYTES)
#define OFF_BL (2*A_BYTES + B_BYTES)
#define BUF_BYTES (2*A_BYTES + 2*B_BYTES)   // 37888
#define TG_SMEM (2*BUF_BYTES)               // 75776

__device__ __forceinline__ unsigned smem_u32(const void* p) {
    return (unsigned)__cvta_generic_to_shared(p);
}

__device__ __forceinline__ void ldsm4(unsigned* r, unsigned addr) {
    asm volatile("ldmatrix.sync.aligned.m8n8.x4.shared.b16 {%0,%1,%2,%3}, [%4];"
        : "=r"(r[0]), "=r"(r[1]), "=r"(r[2]), "=r"(r[3]) : "r"(addr));
}
__device__ __forceinline__ void ldsm4t(unsigned* r, unsigned addr) {
    asm volatile("ldmatrix.sync.aligned.m8n8.x4.trans.shared.b16 {%0,%1,%2,%3}, [%4];"
        : "=r"(r[0]), "=r"(r[1]), "=r"(r[2]), "=r"(r[3]) : "r"(addr));
}
__device__ __forceinline__ void mma16816(float* c, const unsigned* a, unsigned b0, unsigned b1) {
    asm volatile(
        "mma.sync.aligned.m16n8k16.row.col.f32.bf16.bf16.f32 "
        "{%0,%1,%2,%3}, {%4,%5,%6,%7}, {%8,%9}, {%0,%1,%2,%3};"
        : "+f"(c[0]), "+f"(c[1]), "+f"(c[2]), "+f"(c[3])
        : "r"(a[0]), "r"(a[1]), "r"(a[2]), "r"(a[3]), "r"(b0), "r"(b1));
}

__device__ __forceinline__ void cvt4(const float4& v, uint2& hp, uint2& lp) {
    float vv[4] = {v.x, v.y, v.z, v.w};
    unsigned short hs[4], ls[4];
    #pragma unroll
    for (int e = 0; e < 4; e++) {
        __nv_bfloat16 h = __float2bfloat16_rn(vv[e]);
        float r = vv[e] - __bfloat162float(h);   // exact
        __nv_bfloat16 l = __float2bfloat16_rn(r);
        hs[e] = __bfloat16_as_ushort(h);
        ls[e] = __bfloat16_as_ushort(l);
    }
    hp.x = (unsigned)hs[0] | ((unsigned)hs[1] << 16);
    hp.y = (unsigned)hs[2] | ((unsigned)hs[3] << 16);
    lp.x = (unsigned)ls[0] | ((unsigned)ls[1] << 16);
    lp.y = (unsigned)ls[2] | ((unsigned)ls[3] << 16);
}

template<int EPI>
__global__ __launch_bounds__(256, 1)
void tgemm(const float* __restrict__ A, int lda,
           const float* __restrict__ B, int ldb,
           float* __restrict__ C, int ldc,
           int M, int N, int Kreal, EpiParams ep)
{
    extern __shared__ unsigned char smraw[];
    unsigned sbase = smem_u32(smraw);
    int tid = threadIdx.x, lane = tid & 31, wid = tid >> 5;
    int warp_m = wid & 1, warp_n = wid >> 1;
    int m0 = blockIdx.y * 128, n0 = blockIdx.x * 128;
    int g = lane >> 2, t = lane & 3;

    float acc[4][4][4];
    #pragma unroll
    for (int i = 0; i < 4; i++)
        #pragma unroll
        for (int j = 0; j < 4; j++)
            #pragma unroll
            for (int e = 0; e < 4; e++) acc[i][j][e] = 0.f;

    // staging coordinates: A tile 128x32 floats, B tile 32x128 floats; 4 float4 each
    int ar[4], ak[4], br[4], bn[4];
    #pragma unroll
    for (int i = 0; i < 4; i++) {
        int f = tid + 256*i;
        ar[i] = f >> 3;  ak[i] = (f & 7) * 4;
        br[i] = f >> 5;  bn[i] = (f & 31) * 4;
    }

    // ldmatrix per-lane address components
    int aRow = lane & 15;
    int aKof = ((lane >> 4) & 1) * 8;    // k offset within 16-chunk
    int bRow = lane & 15;                // k row within 16-chunk
    int bNof = ((lane >> 4) & 1) * 8;    // n offset within 16-chunk

    int nk = (Kreal + 31) >> 5;
    float4 ra[4], rb[4];

    auto load_g = [&](int kt) {
        int k0 = kt * 32;
        #pragma unroll
        for (int i = 0; i < 4; i++)
            ra[i] = *(const float4*)(A + (size_t)(m0 + ar[i])*lda + k0 + ak[i]);
        #pragma unroll
        for (int i = 0; i < 4; i++) {
            int k = k0 + br[i];
            rb[i] = (k < Kreal) ? *(const float4*)(B + (size_t)k*ldb + n0 + bn[i])
                                : make_float4(0.f, 0.f, 0.f, 0.f);
        }
    };
    auto cvt_store = [&](int buf) {
        unsigned char* bp = smraw + buf * BUF_BYTES;
        #pragma unroll
        for (int i = 0; i < 4; i++) {
            uint2 hp, lp;
            cvt4(ra[i], hp, lp);
            int off = ar[i]*PA + ak[i]*2;
            *(uint2*)(bp + OFF_AH + off) = hp;
            *(uint2*)(bp + OFF_AL + off) = lp;
        }
        #pragma unroll
        for (int i = 0; i < 4; i++) {
            uint2 hp, lp;
            cvt4(rb[i], hp, lp);
            int off = br[i]*PB + bn[i]*2;
            *(uint2*)(bp + OFF_BH + off) = hp;
            *(uint2*)(bp + OFF_BL + off) = lp;
        }
    };

    load_g(0);
    cvt_store(0);
    __syncthreads();

    for (int kt = 0; kt < nk; kt++) {
        if (kt + 1 < nk) load_g(kt + 1);

        unsigned base = sbase + (kt & 1) * BUF_BYTES;
        #pragma unroll
        for (int ks = 0; ks < 2; ks++) {
            unsigned aAddrBase = base + (ks*16 + aKof) * 2;
            unsigned bAddrBase = base + (ks*16 + bRow) * PB;

            unsigned ah[4][4], bh[2][4];
            #pragma unroll
            for (int mt = 0; mt < 4; mt++)
                ldsm4(ah[mt], aAddrBase + OFF_AH + (warp_m*64 + mt*16 + aRow)*PA);
            #pragma unroll
            for (int np = 0; np < 2; np++)
                ldsm4t(bh[np], bAddrBase + OFF_BH + (warp_n*32 + np*16 + bNof)*2);

            // pass 1: Ah * Bh
            #pragma unroll
            for (int mt = 0; mt < 4; mt++)
                #pragma unroll
                for (int nt = 0; nt < 4; nt++)
                    mma16816(acc[mt][nt], ah[mt], bh[nt>>1][(nt&1)*2], bh[nt>>1][(nt&1)*2+1]);

            // pass 2: Ah * Bl
            unsigned bl[2][4];
            #pragma unroll
            for (int np = 0; np < 2; np++)
                ldsm4t(bl[np], bAddrBase + OFF_BL + (warp_n*32 + np*16 + bNof)*2);
            #pragma unroll
            for (int mt = 0; mt < 4; mt++)
                #pragma unroll
                for (int nt = 0; nt < 4; nt++)
                    mma16816(acc[mt][nt], ah[mt], bl[nt>>1][(nt&1)*2], bl[nt>>1][(nt&1)*2+1]);

            // pass 3: Al * Bh
            unsigned al[4][4];
            #pragma unroll
            for (int mt = 0; mt < 4; mt++)
                ldsm4(al[mt], aAddrBase + OFF_AL + (warp_m*64 + mt*16 + aRow)*PA);
            #pragma unroll
            for (int mt = 0; mt < 4; mt++)
                #pragma unroll
                for (int nt = 0; nt < 4; nt++)
                    mma16816(acc[mt][nt], al[mt], bh[nt>>1][(nt&1)*2], bh[nt>>1][(nt&1)*2+1]);
        }

        if (kt + 1 < nk) cvt_store((kt + 1) & 1);
        __syncthreads();
    }

    // epilogue: acc[mt][nt] -> rows (m0+warp_m*64+mt*16+g, +8), cols (n0+warp_n*32+nt*8+2t, +1)
    #pragma unroll
    for (int mt = 0; mt < 4; mt++) {
        int row0 = m0 + warp_m*64 + mt*16 + g;
        #pragma unroll
        for (int nt = 0; nt < 4; nt++) {
            int col = n0 + warp_n*32 + nt*8 + t*2;
            float* c = acc[mt][nt];
            float v0 = apply_epi<EPI>(c[0], row0,     col,     ep);
            float v1 = apply_epi<EPI>(c[1], row0,     col + 1, ep);
            float v2 = apply_epi<EPI>(c[2], row0 + 8, col,     ep);
            float v3 = apply_epi<EPI>(c[3], row0 + 8, col + 1, ep);
            *(float2*)(C + (size_t)row0*ldc + col)       = make_float2(v0, v1);
            *(float2*)(C + (size_t)(row0 + 8)*ldc + col) = make_float2(v2, v3);
        }
    }
}

// ---------------------------------------------------------------------------
// fp32 fallback GEMM (small N=99 output heads only)
// ---------------------------------------------------------------------------
template<int EPI>
__global__ __launch_bounds__(256)
void gemm128(const float* __restrict__ A, int lda,
             const float* __restrict__ B, int ldb,
             float* __restrict__ C, int ldc,
             int M, int N, int K, EpiParams ep)
{
    __shared__ float As[8][128];
    __shared__ float Bs[8][128];
    int tid = threadIdx.x;
    int tx = tid & 15, ty = tid >> 4;
    int m0 = blockIdx.y * 128, n0 = blockIdx.x * 128;

    float acc[8][8];
    #pragma unroll
    for (int i = 0; i < 8; i++)
        #pragma unroll
        for (int j = 0; j < 8; j++) acc[i][j] = 0.f;

    int arow = tid >> 1;
    int ak   = (tid & 1) * 4;

    for (int k0 = 0; k0 < K; k0 += 8) {
        #pragma unroll
        for (int i = 0; i < 4; i++) {
            int k = k0 + ak + i;
            As[ak+i][arow] = (k < K) ? A[(size_t)(m0+arow)*lda + k] : 0.f;
        }
        #pragma unroll
        for (int i = 0; i < 4; i++) {
            int idx = tid + 256*i;
            int r = idx >> 7, c = idx & 127;
            int k = k0 + r;
            Bs[r][c] = (k < K && (n0 + c) < N) ? B[(size_t)k*ldb + n0 + c] : 0.f;
        }
        __syncthreads();
        #pragma unroll
        for (int k = 0; k < 8; k++) {
            float4 a0 = *(const float4*)&As[k][ty*8];
            float4 a1 = *(const float4*)&As[k][ty*8+4];
            float4 b0 = *(const float4*)&Bs[k][tx*8];
            float4 b1 = *(const float4*)&Bs[k][tx*8+4];
            float ra_[8] = {a0.x,a0.y,a0.z,a0.w,a1.x,a1.y,a1.z,a1.w};
            float rb_[8] = {b0.x,b0.y,b0.z,b0.w,b1.x,b1.y,b1.z,b1.w};
            #pragma unroll
            for (int i = 0; i < 8; i++)
                #pragma unroll
                for (int j = 0; j < 8; j++)
                    acc[i][j] += ra_[i]*rb_[j];
        }
        __syncthreads();
    }

    #pragma unroll
    for (int i = 0; i < 8; i++) {
        int row = m0 + ty*8 + i;
        if (row >= M) continue;
        #pragma unroll
        for (int j = 0; j < 8; j++) {
            int col = n0 + tx*8 + j;
            if (col >= N) continue;
            C[(size_t)row*ldc + col] = apply_epi<EPI>(acc[i][j], row, col, ep);
        }
    }
}

// ---------------------------------------------------------------------------
// Fused attention
// ---------------------------------------------------------------------------
#define KV_PITCH 65
#define ATT_SMEM ((2*256*KV_PITCH + 8*256 + 8*64 + 256) * (int)sizeof(float))

__global__ void attention_kernel(const float* __restrict__ qb,
                                 const float* __restrict__ kb,
                                 const float* __restrict__ vb,
                                 const unsigned char* __restrict__ pad,
                                 float* __restrict__ ob)
{
    int bh = blockIdx.x;
    int b = bh >> 3, h = bh & 7;
    extern __shared__ float sm[];
    float* Ks = sm;
    float* Vs = Ks + 256*KV_PITCH;
    float* Ps = Vs + 256*KV_PITCH;
    float* Qs = Ps + 8*256;
    float* Bsb = Qs + 8*64;

    int tid = threadIdx.x, lane = tid & 31, w = tid >> 5;
    const float* kbase = kb + (size_t)(b*SS)*DD + h*DHH;
    const float* vbase = vb + (size_t)(b*SS)*DD + h*DHH;

    for (int idx = tid; idx < 256*64; idx += 256) {
        int r = idx >> 6, c = idx & 63;
        Ks[r*KV_PITCH + c] = kbase[(size_t)r*DD + c];
        Vs[r*KV_PITCH + c] = vbase[(size_t)r*DD + c];
    }
    if (tid < 256) Bsb[tid] = pad[b*SS + tid] ? -1e9f : 0.f;
    __syncthreads();

    float* Pw = Ps + w*256;
    float* Qw = Qs + w*64;

    for (int qi = w; qi < SS; qi += 8) {
        const float* qrow = qb + (size_t)(b*SS + qi)*DD + h*DHH;
        Qw[lane]      = qrow[lane];
        Qw[lane + 32] = qrow[lane + 32];
        __syncwarp();

        float s[8];
        float mx = -3.402823466e+38f;
        #pragma unroll
        for (int k8 = 0; k8 < 8; k8++) {
            int j = lane + 32*k8;
            const float* kr = Ks + j*KV_PITCH;
            float acc = 0.f;
            #pragma unroll
            for (int d = 0; d < 64; d++) acc += Qw[d]*kr[d];
            acc = acc * 0.125f + Bsb[j];
            s[k8] = acc;
            mx = fmaxf(mx, acc);
        }
        for (int off = 16; off; off >>= 1)
            mx = fmaxf(mx, __shfl_xor_sync(0xffffffffu, mx, off));
        float sum = 0.f;
        #pragma unroll
        for (int k8 = 0; k8 < 8; k8++) { s[k8] = __expf(s[k8]-mx); sum += s[k8]; }
        for (int off = 16; off; off >>= 1)
            sum += __shfl_xor_sync(0xffffffffu, sum, off);
        float inv = 1.f / sum;
        #pragma unroll
        for (int k8 = 0; k8 < 8; k8++) Pw[lane + 32*k8] = s[k8]*inv;
        __syncwarp();

        float o0 = 0.f, o1 = 0.f;
        for (int j = 0; j < 256; j++) {
            float p = Pw[j];
            o0 += p * Vs[j*KV_PITCH + lane];
            o1 += p * Vs[j*KV_PITCH + lane + 32];
        }
        float* orow = ob + (size_t)(b*SS + qi)*DD + h*DHH;
        orow[lane]      = o0;
        orow[lane + 32] = o1;
        __syncwarp();
    }
}

// ---------------------------------------------------------------------------
// Residual add + LayerNorm
// ---------------------------------------------------------------------------
__global__ void ln_kernel(const float* __restrict__ x, const float* __restrict__ add,
                          const float* __restrict__ g, const float* __restrict__ bv,
                          float* __restrict__ out)
{
    int t = blockIdx.x;
    int tid = threadIdx.x;            // 128
    const float* xr = x   + (size_t)t*DD;
    const float* ar = add + (size_t)t*DD;
    float v[4];
    float s = 0.f, ss = 0.f;
    #pragma unroll
    for (int i = 0; i < 4; i++) {
        float u = xr[tid + 128*i] + ar[tid + 128*i];
        v[i] = u; s += u; ss += u*u;
    }
    for (int off = 16; off; off >>= 1) {
        s  += __shfl_xor_sync(0xffffffffu, s,  off);
        ss += __shfl_xor_sync(0xffffffffu, ss, off);
    }
    __shared__ float rs[4], rss[4];
    int w = tid >> 5, lane = tid & 31;
    if (lane == 0) { rs[w] = s; rss[w] = ss; }
    __syncthreads();
    s  = rs[0]+rs[1]+rs[2]+rs[3];
    ss = rss[0]+rss[1]+rss[2]+rss[3];
    float mean = s * (1.f/512.f);
    float var  = ss * (1.f/512.f) - mean*mean;
    float rstd = rsqrtf(var + 1e-5f);
    #pragma unroll
    for (int i = 0; i < 4; i++) {
        int c = tid + 128*i;
        out[(size_t)t*DD + c] = (v[i]-mean)*rstd*g[c] + bv[c];
    }
}

// ---------------------------------------------------------------------------
// Launch
// ---------------------------------------------------------------------------
extern "C" void kernel_launch(void* const* d_in, const int* in_sizes, int n_in,
                              void* d_out, int out_size)
{
    const float* x_l  = (const float*)d_in[0];
    const float* x_r  = (const float*)d_in[1];
    const float* j_l  = (const float*)d_in[2];
    const float* j_r  = (const float*)d_in[3];
    const float* mcon = (const float*)d_in[4];
    const float* pc   = (const float*)d_in[5];
    const float* mask_l = (const float*)d_in[6];
    const float* mask_r = (const float*)d_in[7];
    const unsigned char* pad = (const unsigned char*)d_in[8];
    const float* W_fc_l = (const float*)d_in[9];
    const float* b_fc_l = (const float*)d_in[10];
    const float* W_fc_r = (const float*)d_in[11];
    const float* b_fc_r = (const float*)d_in[12];
    const float* Wq = (const float*)d_in[13];
    const float* Wk = (const float*)d_in[14];
    const float* Wv = (const float*)d_in[15];
    const float* Wo = (const float*)d_in[16];
    const float* W1 = (const float*)d_in[17];
    const float* b1 = (const float*)d_in[18];
    const float* W2 = (const float*)d_in[19];
    const float* b2 = (const float*)d_in[20];
    const float* ln1g = (const float*)d_in[21];
    const float* ln1b = (const float*)d_in[22];
    const float* ln2g = (const float*)d_in[23];
    const float* ln2b = (const float*)d_in[24];
    const float* W_out_l = (const float*)d_in[25];
    const float* b_out_l = (const float*)d_in[26];
    const float* W_out_r = (const float*)d_in[27];
    const float* b_out_r = (const float*)d_in[28];
    float* outp = (float*)d_out;

    float *pfl, *pfr, *px, *pq, *pk, *pv, *pao, *pproj, *px1, *ph, *pf, *px2;
    cudaGetSymbolAddress((void**)&pfl,  g_feat_l);
    cudaGetSymbolAddress((void**)&pfr,  g_feat_r);
    cudaGetSymbolAddress((void**)&px,   g_x);
    cudaGetSymbolAddress((void**)&pq,   g_q);
    cudaGetSymbolAddress((void**)&pk,   g_k);
    cudaGetSymbolAddress((void**)&pv,   g_v);
    cudaGetSymbolAddress((void**)&pao,  g_ao);
    cudaGetSymbolAddress((void**)&pproj,g_proj);
    cudaGetSymbolAddress((void**)&px1,  g_x1);
    cudaGetSymbolAddress((void**)&ph,   g_h);
    cudaGetSymbolAddress((void**)&pf,   g_f);
    cudaGetSymbolAddress((void**)&px2,  g_x2);

    cudaFuncSetAttribute(tgemm<0>, cudaFuncAttributeMaxDynamicSharedMemorySize, TG_SMEM);
    cudaFuncSetAttribute(tgemm<1>, cudaFuncAttributeMaxDynamicSharedMemorySize, TG_SMEM);
    cudaFuncSetAttribute(attention_kernel,
                         cudaFuncAttributeMaxDynamicSharedMemorySize, ATT_SMEM);

    // 1. features (padded K layout)
    build_features_kernel<<<ROWS, 256>>>(x_l, x_r, j_l, j_r, mcon, pc, pfl, pfr);

    // 2. fc projections -> interleaved x with PE + masks
    EpiParams fc_el = {b_fc_l, mask_l, pad, 0, 0};
    EpiParams fc_er = {b_fc_r, mask_r, pad, 1, 0};
    tgemm<1><<<dim3(4,32), 256, TG_SMEM>>>(pfl, CATP, W_fc_l, DD, px,      2*DD, ROWS, DD, CAT, fc_el);
    tgemm<1><<<dim3(4,32), 256, TG_SMEM>>>(pfr, CATP, W_fc_r, DD, px + DD, 2*DD, ROWS, DD, CAT, fc_er);

    // 3. QKV
    EpiParams none = {nullptr, nullptr, nullptr, 0, 0};
    tgemm<0><<<dim3(4,64), 256, TG_SMEM>>>(px, DD, Wq, DD, pq, DD, TROWS, DD, DD, none);
    tgemm<0><<<dim3(4,64), 256, TG_SMEM>>>(px, DD, Wk, DD, pk, DD, TROWS, DD, DD, none);
    tgemm<0><<<dim3(4,64), 256, TG_SMEM>>>(px, DD, Wv, DD, pv, DD, TROWS, DD, DD, none);

    // 4. fused attention
    attention_kernel<<<BB*HH, 256, ATT_SMEM>>>(pq, pk, pv, pad, pao);

    // 5. output projection + LN1
    tgemm<0><<<dim3(4,64), 256, TG_SMEM>>>(pao, DD, Wo, DD, pproj, DD, TROWS, DD, DD, none);
    ln_kernel<<<TROWS, 128>>>(px, pproj, ln1g, ln1b, px1);

    // 6. FFN + LN2
    EpiParams e1 = {b1, nullptr, nullptr, 0, 1};
    EpiParams e2 = {b2, nullptr, nullptr, 0, 0};
    tgemm<0><<<dim3(16,64), 256, TG_SMEM>>>(px1, DD, W1, DFF, ph, DFF, TROWS, DFF, DD, e1);
    tgemm<0><<<dim3(4,64),  256, TG_SMEM>>>(ph, DFF, W2, DD, pf, DD, TROWS, DD, DFF, e2);
    ln_kernel<<<TROWS, 128>>>(px1, pf, ln2g, ln2b, px2);

    // 7. per-hand output heads (small, fp32 path)
    EpiParams ol = {b_out_l, mask_l, pad, 0, 0};
    EpiParams orr= {b_out_r, mask_r, pad, 1, 0};
    gemm128<2><<<dim3(1,32), 256>>>(px2,      2*DD, W_out_l, HAND_DIM,
                                    outp,                 HAND_DIM, ROWS, HAND_DIM, DD, ol);
    gemm128<2><<<dim3(1,32), 256>>>(px2 + DD, 2*DD, W_out_r, HAND_DIM,
                                    outp + ROWS*HAND_DIM, HAND_DIM, ROWS, HAND_DIM, DD, orr);
}

// round 6
// speedup vs baseline: 3.1376x; 1.2169x over previous
#include <cuda_runtime.h>
#include <cuda_bf16.h>
#include <math.h>

// ---------------------------------------------------------------------------
// Shapes
// ---------------------------------------------------------------------------
#define BB 32
#define LL 128
#define NN 512
#define JJ 21
#define HAND_DIM 99
#define DD 512
#define HH 8
#define DHH 64
#define DFF 2048
#define CAT 1249
#define CATP 1280
#define SS 256
#define ROWS 4096
#define TROWS 8192

#define F_X 0
#define F_J 99
#define F_MC 162
#define F_PCN 674
#define F_ATT 1186

// ---------------------------------------------------------------------------
// Scratch
// ---------------------------------------------------------------------------
__device__ float g_feat_l[ROWS * CATP];
__device__ float g_feat_r[ROWS * CATP];
__device__ float g_x [TROWS * DD];
__device__ float g_q [TROWS * DD];
__device__ float g_k [TROWS * DD];
__device__ float g_v [TROWS * DD];
__device__ float g_ao [TROWS * DD];
__device__ float g_proj[TROWS * DD];
__device__ float g_x1 [TROWS * DD];
__device__ float g_h [TROWS * DFF];
__device__ float g_f [TROWS * DD];
__device__ float g_x2 [TROWS * DD];

// ---------------------------------------------------------------------------
// Feature build
// ---------------------------------------------------------------------------
__global__ void build_features_kernel(
    const float* __restrict__ x_l, const float* __restrict__ x_r,
    const float* __restrict__ j_l, const float* __restrict__ j_r,
    const float* __restrict__ m_contact, const float* __restrict__ pc,
    float* __restrict__ feat_l, float* __restrict__ feat_r)
{
    int m = blockIdx.x;
    int b = m >> 7;
    __shared__ float px[NN], py[NN], pz[NN];
    int tid = threadIdx.x;

    const float* pcb = pc + (size_t)m * NN * 3;
    for (int n = tid; n < NN; n += 256) {
        px[n] = pcb[n*3+0]; py[n] = pcb[n*3+1]; pz[n] = pcb[n*3+2];
    }
    __syncthreads();

    float* fl = feat_l + (size_t)m * CATP;
    float* fr = feat_r + (size_t)m * CATP;

    for (int i = tid; i < HAND_DIM; i += 256) {
        fl[F_X+i] = x_l[(size_t)m*HAND_DIM + i];
        fr[F_X+i] = x_r[(size_t)m*HAND_DIM + i];
    }
    for (int i = tid; i < JJ*3; i += 256) {
        fl[F_J+i] = j_l[(size_t)m*JJ*3 + i];
        fr[F_J+i] = j_r[(size_t)m*JJ*3 + i];
    }
    for (int n = tid; n < NN; n += 256) {
        float mc = m_contact[b*NN + n];
        fl[F_MC+n] = mc; fr[F_MC+n] = mc;
        float nm = sqrtf(px[n]*px[n] + py[n]*py[n] + pz[n]*pz[n]);
        fl[F_PCN+n] = nm; fr[F_PCN+n] = nm;
    }
    for (int i = CAT + tid; i < CATP; i += 256) { fl[i] = 0.f; fr[i] = 0.f; }

    int w = tid >> 5, lane = tid & 31;
    for (int task = w; task < 2*JJ; task += 8) {
        int hand = task / JJ, joint = task % JJ;
        const float* jb = (hand == 0 ? j_l : j_r) + ((size_t)m*JJ + joint)*3;
        float jx = jb[0], jy = jb[1], jz = jb[2];
        float best = 3.402823466e+38f; int bi = 0;
        for (int n = lane; n < NN; n += 32) {
            float dx = jx - px[n], dy = jy - py[n], dz = jz - pz[n];
            float d2 = dx*dx + dy*dy + dz*dz;
            if (d2 < best) { best = d2; bi = n; }
        }
        for (int off = 16; off; off >>= 1) {
            float ob = __shfl_xor_sync(0xffffffffu, best, off);
            int   oi = __shfl_xor_sync(0xffffffffu, bi, off);
            if (ob < best || (ob == best && oi < bi)) { best = ob; bi = oi; }
        }
        if (lane == 0) {
            float dx = jx - px[bi], dy = jy - py[bi], dz = jz - pz[bi];
            float* f = (hand == 0 ? fl : fr);
            f[F_ATT + joint*3 + 0] = expf(-50.f * dx * dx);
            f[F_ATT + joint*3 + 1] = expf(-50.f * dy * dy);
            f[F_ATT + joint*3 + 2] = expf(-50.f * dz * dz);
        }
    }
}

// ---------------------------------------------------------------------------
// Epilogues
// ---------------------------------------------------------------------------
struct EpiParams {
    const float* bias;
    const float* mask;           // [4096]
    const unsigned char* pad;    // [8192] bool
    int hand;
    int relu;
};

#define LN10000 9.2103403719761827f

template<int EPI>
__device__ __forceinline__ float apply_epi(float v, int row, int col, const EpiParams& ep)
{
    if (EPI == 0) {
        if (ep.bias) v += ep.bias[col];
        if (ep.relu) v = fmaxf(v, 0.f);
    } else if (EPI == 1) {
        int l = row & 127;
        int ii = col >> 1;
        float freq = expf(-LN10000 * (float)ii * (1.f/256.f));
        float angF = (float)l * freq;
        float angA = (float)ep.hand * freq;
        float pe = (col & 1) ? (cosf(angF) + cosf(angA))
                             : (sinf(angF) + sinf(angA));
        float mv = ep.mask[row] * (ep.pad[2*row + ep.hand] ? 0.f : 1.f);
        v = (v + ep.bias[col] + pe) * mv;
    } else { // EPI == 2
        float mv = ep.mask[row] * (ep.pad[2*row + ep.hand] ? 0.f : 1.f);
        v = (v + ep.bias[col]) * mv;
    }
    return v;
}

// ---------------------------------------------------------------------------
// bf16x3 tensor-core GEMM (legacy mma.sync path, sm_100-safe).
// Block tile 128x64, BK=32, 8 warps: warp_m = wid&3 (32 rows), warp_n = wid>>2
// (32 cols). Warp tile 32x32 -> acc 32 floats -> ~120 regs -> 2 CTAs/SM.
// Smem: A/B row-major bf16 hi/lo, double-buffered; fragments via ldmatrix.
// Requires M%128==0, N%64==0, lda%4==0, A zero-padded to 32-multiple K.
// ---------------------------------------------------------------------------
#define PA 80                         // A pitch bytes (32 bf16 + 8 pad; 5 granules)
#define PB 144                        // B pitch bytes (64 bf16 + 8 pad; 9 granules)
#define A_BYTES (128*PA)              // 10240
#define B_BYTES (32*PB)               // 4608
#define OFF_AH 0
#define OFF_AL (A_BYTES)
#define OFF_BH (2*A_BYTES)
#define OFF_BL (2*A_BYTES + B_BYTES)
#define BUF_BYTES (2*A_BYTES + 2*B_BYTES)   // 29696
#define TG_SMEM (2*BUF_BYTES)               // 59392

__device__ __forceinline__ unsigned smem_u32(const void* p) {
    return (unsigned)__cvta_generic_to_shared(p);
}
__device__ __forceinline__ void ldsm4(unsigned* r, unsigned addr) {
    asm volatile("ldmatrix.sync.aligned.m8n8.x4.shared.b16 {%0,%1,%2,%3}, [%4];"
        : "=r"(r[0]), "=r"(r[1]), "=r"(r[2]), "=r"(r[3]) : "r"(addr));
}
__device__ __forceinline__ void ldsm4t(unsigned* r, unsigned addr) {
    asm volatile("ldmatrix.sync.aligned.m8n8.x4.trans.shared.b16 {%0,%1,%2,%3}, [%4];"
        : "=r"(r[0]), "=r"(r[1]), "=r"(r[2]), "=r"(r[3]) : "r"(addr));
}
__device__ __forceinline__ void mma16816(float* c, const unsigned* a, unsigned b0, unsigned b1) {
    asm volatile(
        "mma.sync.aligned.m16n8k16.row.col.f32.bf16.bf16.f32 "
        "{%0,%1,%2,%3}, {%4,%5,%6,%7}, {%8,%9}, {%0,%1,%2,%3};"
        : "+f"(c[0]), "+f"(c[1]), "+f"(c[2]), "+f"(c[3])
        : "r"(a[0]), "r"(a[1]), "r"(a[2]), "r"(a[3]), "r"(b0), "r"(b1));
}
__device__ __forceinline__ void cvt4(const float4& v, uint2& hp, uint2& lp) {
    float vv[4] = {v.x, v.y, v.z, v.w};
    unsigned short hs[4], ls[4];
    #pragma unroll
    for (int e = 0; e < 4; e++) {
        __nv_bfloat16 h = __float2bfloat16_rn(vv[e]);
        float r = vv[e] - __bfloat162float(h);   // exact
        __nv_bfloat16 l = __float2bfloat16_rn(r);
        hs[e] = __bfloat16_as_ushort(h);
        ls[e] = __bfloat16_as_ushort(l);
    }
    hp.x = (unsigned)hs[0] | ((unsigned)hs[1] << 16);
    hp.y = (unsigned)hs[2] | ((unsigned)hs[3] << 16);
    lp.x = (unsigned)ls[0] | ((unsigned)ls[1] << 16);
    lp.y = (unsigned)ls[2] | ((unsigned)ls[3] << 16);
}

template<int EPI>
__global__ __launch_bounds__(256, 2)
void tgemm(const float* __restrict__ A, int lda,
           const float* __restrict__ B, int ldb,
           float* __restrict__ C, int ldc,
           int M, int N, int Kreal, EpiParams ep)
{
    extern __shared__ unsigned char smraw[];
    unsigned sbase = smem_u32(smraw);
    int tid = threadIdx.x, lane = tid & 31, wid = tid >> 5;
    int warp_m = wid & 3, warp_n = wid >> 2;
    int m0 = blockIdx.y * 128, n0 = blockIdx.x * 64;
    int g = lane >> 2, t = lane & 3;

    float acc[2][4][4];
    #pragma unroll
    for (int i = 0; i < 2; i++)
        #pragma unroll
        for (int j = 0; j < 4; j++)
            #pragma unroll
            for (int e = 0; e < 4; e++) acc[i][j][e] = 0.f;

    // staging coords: A tile 128x32 floats (4 float4/thread), B 32x64 (2/thread)
    int ar[4], ak[4], br[2], bn[2];
    #pragma unroll
    for (int i = 0; i < 4; i++) {
        int f = tid + 256*i;
        ar[i] = f >> 3;  ak[i] = (f & 7) * 4;
    }
    #pragma unroll
    for (int i = 0; i < 2; i++) {
        int f = tid + 256*i;
        br[i] = f >> 4;  bn[i] = (f & 15) * 4;
    }

    int aRow = lane & 15;
    int aKof = ((lane >> 4) & 1) * 8;
    int bRow = lane & 15;
    int bNof = ((lane >> 4) & 1) * 8;

    int nk = (Kreal + 31) >> 5;
    float4 ra[4], rb[2];

    auto load_g = [&](int kt) {
        int k0 = kt * 32;
        #pragma unroll
        for (int i = 0; i < 4; i++)
            ra[i] = *(const float4*)(A + (size_t)(m0 + ar[i])*lda + k0 + ak[i]);
        #pragma unroll
        for (int i = 0; i < 2; i++) {
            int k = k0 + br[i];
            rb[i] = (k < Kreal) ? *(const float4*)(B + (size_t)k*ldb + n0 + bn[i])
                                : make_float4(0.f, 0.f, 0.f, 0.f);
        }
    };
    auto cvt_store = [&](int buf) {
        unsigned char* bp = smraw + buf * BUF_BYTES;
        #pragma unroll
        for (int i = 0; i < 4; i++) {
            uint2 hp, lp;
            cvt4(ra[i], hp, lp);
            int off = ar[i]*PA + ak[i]*2;
            *(uint2*)(bp + OFF_AH + off) = hp;
            *(uint2*)(bp + OFF_AL + off) = lp;
        }
        #pragma unroll
        for (int i = 0; i < 2; i++) {
            uint2 hp, lp;
            cvt4(rb[i], hp, lp);
            int off = br[i]*PB + bn[i]*2;
            *(uint2*)(bp + OFF_BH + off) = hp;
            *(uint2*)(bp + OFF_BL + off) = lp;
        }
    };

    load_g(0);
    cvt_store(0);
    __syncthreads();

    for (int kt = 0; kt < nk; kt++) {
        if (kt + 1 < nk) load_g(kt + 1);

        unsigned base = sbase + (kt & 1) * BUF_BYTES;
        #pragma unroll
        for (int ks = 0; ks < 2; ks++) {
            unsigned aAddrBase = base + (ks*16 + aKof) * 2;
            unsigned bAddrBase = base + (ks*16 + bRow) * PB;

            unsigned ah[2][4], bh[2][4];
            #pragma unroll
            for (int mt = 0; mt < 2; mt++)
                ldsm4(ah[mt], aAddrBase + OFF_AH + (warp_m*32 + mt*16 + aRow)*PA);
            #pragma unroll
            for (int np = 0; np < 2; np++)
                ldsm4t(bh[np], bAddrBase + OFF_BH + (warp_n*32 + np*16 + bNof)*2);

            // pass 1: Ah * Bh
            #pragma unroll
            for (int mt = 0; mt < 2; mt++)
                #pragma unroll
                for (int nt = 0; nt < 4; nt++)
                    mma16816(acc[mt][nt], ah[mt], bh[nt>>1][(nt&1)*2], bh[nt>>1][(nt&1)*2+1]);

            // pass 2: Ah * Bl
            unsigned bl[2][4];
            #pragma unroll
            for (int np = 0; np < 2; np++)
                ldsm4t(bl[np], bAddrBase + OFF_BL + (warp_n*32 + np*16 + bNof)*2);
            #pragma unroll
            for (int mt = 0; mt < 2; mt++)
                #pragma unroll
                for (int nt = 0; nt < 4; nt++)
                    mma16816(acc[mt][nt], ah[mt], bl[nt>>1][(nt&1)*2], bl[nt>>1][(nt&1)*2+1]);

            // pass 3: Al * Bh
            unsigned al[2][4];
            #pragma unroll
            for (int mt = 0; mt < 2; mt++)
                ldsm4(al[mt], aAddrBase + OFF_AL + (warp_m*32 + mt*16 + aRow)*PA);
            #pragma unroll
            for (int mt = 0; mt < 2; mt++)
                #pragma unroll
                for (int nt = 0; nt < 4; nt++)
                    mma16816(acc[mt][nt], al[mt], bh[nt>>1][(nt&1)*2], bh[nt>>1][(nt&1)*2+1]);
        }

        if (kt + 1 < nk) cvt_store((kt + 1) & 1);
        __syncthreads();
    }

    // epilogue: rows m0+warp_m*32+mt*16+g (+8), cols n0+warp_n*32+nt*8+2t (+1)
    #pragma unroll
    for (int mt = 0; mt < 2; mt++) {
        int row0 = m0 + warp_m*32 + mt*16 + g;
        #pragma unroll
        for (int nt = 0; nt < 4; nt++) {
            int col = n0 + warp_n*32 + nt*8 + t*2;
            float* c = acc[mt][nt];
            float v0 = apply_epi<EPI>(c[0], row0,     col,     ep);
            float v1 = apply_epi<EPI>(c[1], row0,     col + 1, ep);
            float v2 = apply_epi<EPI>(c[2], row0 + 8, col,     ep);
            float v3 = apply_epi<EPI>(c[3], row0 + 8, col + 1, ep);
            *(float2*)(C + (size_t)row0*ldc + col)       = make_float2(v0, v1);
            *(float2*)(C + (size_t)(row0 + 8)*ldc + col) = make_float2(v2, v3);
        }
    }
}

// ---------------------------------------------------------------------------
// fp32 GEMM for the small N=99 output heads
// ---------------------------------------------------------------------------
template<int EPI>
__global__ __launch_bounds__(256)
void gemm128(const float* __restrict__ A, int lda,
             const float* __restrict__ B, int ldb,
             float* __restrict__ C, int ldc,
             int M, int N, int K, EpiParams ep)
{
    __shared__ float As[8][128];
    __shared__ float Bs[8][128];
    int tid = threadIdx.x;
    int tx = tid & 15, ty = tid >> 4;
    int m0 = blockIdx.y * 128, n0 = blockIdx.x * 128;

    float acc[8][8];
    #pragma unroll
    for (int i = 0; i < 8; i++)
        #pragma unroll
        for (int j = 0; j < 8; j++) acc[i][j] = 0.f;

    int arow = tid >> 1;
    int ak   = (tid & 1) * 4;

    for (int k0 = 0; k0 < K; k0 += 8) {
        #pragma unroll
        for (int i = 0; i < 4; i++) {
            int k = k0 + ak + i;
            As[ak+i][arow] = (k < K) ? A[(size_t)(m0+arow)*lda + k] : 0.f;
        }
        #pragma unroll
        for (int i = 0; i < 4; i++) {
            int idx = tid + 256*i;
            int r = idx >> 7, c = idx & 127;
            int k = k0 + r;
            Bs[r][c] = (k < K && (n0 + c) < N) ? B[(size_t)k*ldb + n0 + c] : 0.f;
        }
        __syncthreads();
        #pragma unroll
        for (int k = 0; k < 8; k++) {
            float4 a0 = *(const float4*)&As[k][ty*8];
            float4 a1 = *(const float4*)&As[k][ty*8+4];
            float4 b0 = *(const float4*)&Bs[k][tx*8];
            float4 b1 = *(const float4*)&Bs[k][tx*8+4];
            float ra_[8] = {a0.x,a0.y,a0.z,a0.w,a1.x,a1.y,a1.z,a1.w};
            float rb_[8] = {b0.x,b0.y,b0.z,b0.w,b1.x,b1.y,b1.z,b1.w};
            #pragma unroll
            for (int i = 0; i < 8; i++)
                #pragma unroll
                for (int j = 0; j < 8; j++)
                    acc[i][j] += ra_[i]*rb_[j];
        }
        __syncthreads();
    }

    #pragma unroll
    for (int i = 0; i < 8; i++) {
        int row = m0 + ty*8 + i;
        if (row >= M) continue;
        #pragma unroll
        for (int j = 0; j < 8; j++) {
            int col = n0 + tx*8 + j;
            if (col >= N) continue;
            C[(size_t)row*ldc + col] = apply_epi<EPI>(acc[i][j], row, col, ep);
        }
    }
}

// ---------------------------------------------------------------------------
// Fused attention: 2 q-rows per warp pass
// ---------------------------------------------------------------------------
#define KV_PITCH 65
#define ATT_SMEM ((2*256*KV_PITCH + 16*256 + 8*128 + 256) * (int)sizeof(float))

__global__ void attention_kernel(const float* __restrict__ qb,
                                 const float* __restrict__ kb,
                                 const float* __restrict__ vb,
                                 const unsigned char* __restrict__ pad,
                                 float* __restrict__ ob)
{
    int bh = blockIdx.x;
    int b = bh >> 3, h = bh & 7;
    extern __shared__ float sm[];
    float* Ks = sm;
    float* Vs = Ks + 256*KV_PITCH;
    float* Ps = Vs + 256*KV_PITCH;     // [16][256]
    float* Qs = Ps + 16*256;           // [8][128]
    float* Bsb = Qs + 8*128;

    int tid = threadIdx.x, lane = tid & 31, w = tid >> 5;
    const float* kbase = kb + (size_t)(b*SS)*DD + h*DHH;
    const float* vbase = vb + (size_t)(b*SS)*DD + h*DHH;

    for (int idx = tid; idx < 256*64; idx += 256) {
        int r = idx >> 6, c = idx & 63;
        Ks[r*KV_PITCH + c] = kbase[(size_t)r*DD + c];
        Vs[r*KV_PITCH + c] = vbase[(size_t)r*DD + c];
    }
    if (tid < 256) Bsb[tid] = pad[b*SS + tid] ? -1e9f : 0.f;
    __syncthreads();

    float* Pw0 = Ps + (2*w + 0)*256;
    float* Pw1 = Ps + (2*w + 1)*256;
    float* Qw = Qs + w*128;

    for (int qi = 2*w; qi < SS; qi += 16) {
        const float* q0 = qb + (size_t)(b*SS + qi)*DD + h*DHH;
        Qw[lane]           = q0[lane];
        Qw[lane + 32]      = q0[lane + 32];
        Qw[64 + lane]      = q0[DD + lane];
        Qw[64 + lane + 32] = q0[DD + lane + 32];
        __syncwarp();

        float s0[8], s1[8];
        float mx0 = -3.402823466e+38f, mx1 = -3.402823466e+38f;
        #pragma unroll
        for (int k8 = 0; k8 < 8; k8++) {
            int j = lane + 32*k8;
            const float* kr = Ks + j*KV_PITCH;
            float a0 = 0.f, a1 = 0.f;
            #pragma unroll
            for (int d = 0; d < 64; d++) {
                float kv = kr[d];
                a0 += Qw[d]*kv;
                a1 += Qw[64 + d]*kv;
            }
            float bias = Bsb[j];
            a0 = a0 * 0.125f + bias;
            a1 = a1 * 0.125f + bias;
            s0[k8] = a0; s1[k8] = a1;
            mx0 = fmaxf(mx0, a0); mx1 = fmaxf(mx1, a1);
        }
        for (int off = 16; off; off >>= 1) {
            mx0 = fmaxf(mx0, __shfl_xor_sync(0xffffffffu, mx0, off));
            mx1 = fmaxf(mx1, __shfl_xor_sync(0xffffffffu, mx1, off));
        }
        float sm0 = 0.f, sm1 = 0.f;
        #pragma unroll
        for (int k8 = 0; k8 < 8; k8++) {
            s0[k8] = __expf(s0[k8] - mx0); sm0 += s0[k8];
            s1[k8] = __expf(s1[k8] - mx1); sm1 += s1[k8];
        }
        for (int off = 16; off; off >>= 1) {
            sm0 += __shfl_xor_sync(0xffffffffu, sm0, off);
            sm1 += __shfl_xor_sync(0xffffffffu, sm1, off);
        }
        float i0 = 1.f / sm0, i1 = 1.f / sm1;
        #pragma unroll
        for (int k8 = 0; k8 < 8; k8++) {
            Pw0[lane + 32*k8] = s0[k8]*i0;
            Pw1[lane + 32*k8] = s1[k8]*i1;
        }
        __syncwarp();

        float o00 = 0.f, o01 = 0.f, o10 = 0.f, o11 = 0.f;
        for (int j = 0; j < 256; j++) {
            float p0 = Pw0[j], p1 = Pw1[j];
            float v0 = Vs[j*KV_PITCH + lane];
            float v1 = Vs[j*KV_PITCH + lane + 32];
            o00 += p0*v0; o01 += p0*v1;
            o10 += p1*v0; o11 += p1*v1;
        }
        float* orow = ob + (size_t)(b*SS + qi)*DD + h*DHH;
        orow[lane]           = o00;
        orow[lane + 32]      = o01;
        orow[DD + lane]      = o10;
        orow[DD + lane + 32] = o11;
        __syncwarp();
    }
}

// ---------------------------------------------------------------------------
// Residual add + LayerNorm
// ---------------------------------------------------------------------------
__global__ void ln_kernel(const float* __restrict__ x, const float* __restrict__ add,
                          const float* __restrict__ g, const float* __restrict__ bv,
                          float* __restrict__ out)
{
    int t = blockIdx.x;
    int tid = threadIdx.x;
    const float* xr = x   + (size_t)t*DD;
    const float* ar = add + (size_t)t*DD;
    float v[4];
    float s = 0.f, ss = 0.f;
    #pragma unroll
    for (int i = 0; i < 4; i++) {
        float u = xr[tid + 128*i] + ar[tid + 128*i];
        v[i] = u; s += u; ss += u*u;
    }
    for (int off = 16; off; off >>= 1) {
        s  += __shfl_xor_sync(0xffffffffu, s,  off);
        ss += __shfl_xor_sync(0xffffffffu, ss, off);
    }
    __shared__ float rs[4], rss[4];
    int w = tid >> 5, lane = tid & 31;
    if (lane == 0) { rs[w] = s; rss[w] = ss; }
    __syncthreads();
    s  = rs[0]+rs[1]+rs[2]+rs[3];
    ss = rss[0]+rss[1]+rss[2]+rss[3];
    float mean = s * (1.f/512.f);
    float var  = ss * (1.f/512.f) - mean*mean;
    float rstd = rsqrtf(var + 1e-5f);
    #pragma unroll
    for (int i = 0; i < 4; i++) {
        int c = tid + 128*i;
        out[(size_t)t*DD + c] = (v[i]-mean)*rstd*g[c] + bv[c];
    }
}

// ---------------------------------------------------------------------------
// Launch
// ---------------------------------------------------------------------------
extern "C" void kernel_launch(void* const* d_in, const int* in_sizes, int n_in,
                              void* d_out, int out_size)
{
    const float* x_l  = (const float*)d_in[0];
    const float* x_r  = (const float*)d_in[1];
    const float* j_l  = (const float*)d_in[2];
    const float* j_r  = (const float*)d_in[3];
    const float* mcon = (const float*)d_in[4];
    const float* pc   = (const float*)d_in[5];
    const float* mask_l = (const float*)d_in[6];
    const float* mask_r = (const float*)d_in[7];
    const unsigned char* pad = (const unsigned char*)d_in[8];
    const float* W_fc_l = (const float*)d_in[9];
    const float* b_fc_l = (const float*)d_in[10];
    const float* W_fc_r = (const float*)d_in[11];
    const float* b_fc_r = (const float*)d_in[12];
    const float* Wq = (const float*)d_in[13];
    const float* Wk = (const float*)d_in[14];
    const float* Wv = (const float*)d_in[15];
    const float* Wo = (const float*)d_in[16];
    const float* W1 = (const float*)d_in[17];
    const float* b1 = (const float*)d_in[18];
    const float* W2 = (const float*)d_in[19];
    const float* b2 = (const float*)d_in[20];
    const float* ln1g = (const float*)d_in[21];
    const float* ln1b = (const float*)d_in[22];
    const float* ln2g = (const float*)d_in[23];
    const float* ln2b = (const float*)d_in[24];
    const float* W_out_l = (const float*)d_in[25];
    const float* b_out_l = (const float*)d_in[26];
    const float* W_out_r = (const float*)d_in[27];
    const float* b_out_r = (const float*)d_in[28];
    float* outp = (float*)d_out;

    float *pfl, *pfr, *px, *pq, *pk, *pv, *pao, *pproj, *px1, *ph, *pf, *px2;
    cudaGetSymbolAddress((void**)&pfl,  g_feat_l);
    cudaGetSymbolAddress((void**)&pfr,  g_feat_r);
    cudaGetSymbolAddress((void**)&px,   g_x);
    cudaGetSymbolAddress((void**)&pq,   g_q);
    cudaGetSymbolAddress((void**)&pk,   g_k);
    cudaGetSymbolAddress((void**)&pv,   g_v);
    cudaGetSymbolAddress((void**)&pao,  g_ao);
    cudaGetSymbolAddress((void**)&pproj,g_proj);
    cudaGetSymbolAddress((void**)&px1,  g_x1);
    cudaGetSymbolAddress((void**)&ph,   g_h);
    cudaGetSymbolAddress((void**)&pf,   g_f);
    cudaGetSymbolAddress((void**)&px2,  g_x2);

    cudaFuncSetAttribute(tgemm<0>, cudaFuncAttributeMaxDynamicSharedMemorySize, TG_SMEM);
    cudaFuncSetAttribute(tgemm<1>, cudaFuncAttributeMaxDynamicSharedMemorySize, TG_SMEM);
    cudaFuncSetAttribute(attention_kernel,
                         cudaFuncAttributeMaxDynamicSharedMemorySize, ATT_SMEM);

    // 1. features (padded K layout)
    build_features_kernel<<<ROWS, 256>>>(x_l, x_r, j_l, j_r, mcon, pc, pfl, pfr);

    // 2. fc projections -> interleaved x with PE + masks
    EpiParams fc_el = {b_fc_l, mask_l, pad, 0, 0};
    EpiParams fc_er = {b_fc_r, mask_r, pad, 1, 0};
    tgemm<1><<<dim3(8,32), 256, TG_SMEM>>>(pfl, CATP, W_fc_l, DD, px,      2*DD, ROWS, DD, CAT, fc_el);
    tgemm<1><<<dim3(8,32), 256, TG_SMEM>>>(pfr, CATP, W_fc_r, DD, px + DD, 2*DD, ROWS, DD, CAT, fc_er);

    // 3. QKV
    EpiParams none = {nullptr, nullptr, nullptr, 0, 0};
    tgemm<0><<<dim3(8,64), 256, TG_SMEM>>>(px, DD, Wq, DD, pq, DD, TROWS, DD, DD, none);
    tgemm<0><<<dim3(8,64), 256, TG_SMEM>>>(px, DD, Wk, DD, pk, DD, TROWS, DD, DD, none);
    tgemm<0><<<dim3(8,64), 256, TG_SMEM>>>(px, DD, Wv, DD, pv, DD, TROWS, DD, DD, none);

    // 4. fused attention
    attention_kernel<<<BB*HH, 256, ATT_SMEM>>>(pq, pk, pv, pad, pao);

    // 5. output projection + LN1
    tgemm<0><<<dim3(8,64), 256, TG_SMEM>>>(pao, DD, Wo, DD, pproj, DD, TROWS, DD, DD, none);
    ln_kernel<<<TROWS, 128>>>(px, pproj, ln1g, ln1b, px1);

    // 6. FFN + LN2
    EpiParams e1 = {b1, nullptr, nullptr, 0, 1};
    EpiParams e2 = {b2, nullptr, nullptr, 0, 0};
    tgemm<0><<<dim3(32,64), 256, TG_SMEM>>>(px1, DD, W1, DFF, ph, DFF, TROWS, DFF, DD, e1);
    tgemm<0><<<dim3(8,64),  256, TG_SMEM>>>(ph, DFF, W2, DD, pf, DD, TROWS, DD, DFF, e2);
    ln_kernel<<<TROWS, 128>>>(px1, pf, ln2g, ln2b, px2);

    // 7. per-hand output heads (fp32 path)
    EpiParams ol = {b_out_l, mask_l, pad, 0, 0};
    EpiParams orr= {b_out_r, mask_r, pad, 1, 0};
    gemm128<2><<<dim3(1,32), 256>>>(px2,      2*DD, W_out_l, HAND_DIM,
                                    outp,                 HAND_DIM, ROWS, HAND_DIM, DD, ol);
    gemm128<2><<<dim3(1,32), 256>>>(px2 + DD, 2*DD, W_out_r, HAND_DIM,
                                    outp + ROWS*HAND_DIM, HAND_DIM, ROWS, HAND_DIM, DD, orr);
}

// round 7
// speedup vs baseline: 3.7818x; 1.2053x over previous
#include <cuda_runtime.h>
#include <cuda_bf16.h>
#include <math.h>

// ---------------------------------------------------------------------------
// Shapes
// ---------------------------------------------------------------------------
#define BB 32
#define LL 128
#define NN 512
#define JJ 21
#define HAND_DIM 99
#define DD 512
#define HH 8
#define DHH 64
#define DFF 2048
#define CAT 1249
#define CATP 1280
#define SS 256
#define ROWS 4096
#define TROWS 8192

#define F_X 0
#define F_J 99
#define F_MC 162
#define F_PCN 674
#define F_ATT 1186

// ---------------------------------------------------------------------------
// Scratch
// ---------------------------------------------------------------------------
__device__ float g_feat_l[ROWS * CATP];
__device__ float g_feat_r[ROWS * CATP];
__device__ float g_x [TROWS * DD];
__device__ float g_q [TROWS * DD];
__device__ float g_k [TROWS * DD];
__device__ float g_v [TROWS * DD];
__device__ float g_ao [TROWS * DD];
__device__ float g_proj[TROWS * DD];
__device__ float g_x1 [TROWS * DD];
__device__ float g_h [TROWS * DFF];
__device__ float g_f [TROWS * DD];
__device__ float g_x2 [TROWS * DD];
__device__ float g_woutl[DD * 128];
__device__ float g_woutr[DD * 128];

// ---------------------------------------------------------------------------
// Feature build
// ---------------------------------------------------------------------------
__global__ void build_features_kernel(
    const float* __restrict__ x_l, const float* __restrict__ x_r,
    const float* __restrict__ j_l, const float* __restrict__ j_r,
    const float* __restrict__ m_contact, const float* __restrict__ pc,
    float* __restrict__ feat_l, float* __restrict__ feat_r)
{
    int m = blockIdx.x;
    int b = m >> 7;
    __shared__ float px[NN], py[NN], pz[NN];
    int tid = threadIdx.x;

    const float* pcb = pc + (size_t)m * NN * 3;
    for (int n = tid; n < NN; n += 256) {
        px[n] = pcb[n*3+0]; py[n] = pcb[n*3+1]; pz[n] = pcb[n*3+2];
    }
    __syncthreads();

    float* fl = feat_l + (size_t)m * CATP;
    float* fr = feat_r + (size_t)m * CATP;

    for (int i = tid; i < HAND_DIM; i += 256) {
        fl[F_X+i] = x_l[(size_t)m*HAND_DIM + i];
        fr[F_X+i] = x_r[(size_t)m*HAND_DIM + i];
    }
    for (int i = tid; i < JJ*3; i += 256) {
        fl[F_J+i] = j_l[(size_t)m*JJ*3 + i];
        fr[F_J+i] = j_r[(size_t)m*JJ*3 + i];
    }
    for (int n = tid; n < NN; n += 256) {
        float mc = m_contact[b*NN + n];
        fl[F_MC+n] = mc; fr[F_MC+n] = mc;
        float nm = sqrtf(px[n]*px[n] + py[n]*py[n] + pz[n]*pz[n]);
        fl[F_PCN+n] = nm; fr[F_PCN+n] = nm;
    }
    for (int i = CAT + tid; i < CATP; i += 256) { fl[i] = 0.f; fr[i] = 0.f; }

    int w = tid >> 5, lane = tid & 31;
    for (int task = w; task < 2*JJ; task += 8) {
        int hand = task / JJ, joint = task % JJ;
        const float* jb = (hand == 0 ? j_l : j_r) + ((size_t)m*JJ + joint)*3;
        float jx = jb[0], jy = jb[1], jz = jb[2];
        float best = 3.402823466e+38f; int bi = 0;
        for (int n = lane; n < NN; n += 32) {
            float dx = jx - px[n], dy = jy - py[n], dz = jz - pz[n];
            float d2 = dx*dx + dy*dy + dz*dz;
            if (d2 < best) { best = d2; bi = n; }
        }
        for (int off = 16; off; off >>= 1) {
            float ob = __shfl_xor_sync(0xffffffffu, best, off);
            int   oi = __shfl_xor_sync(0xffffffffu, bi, off);
            if (ob < best || (ob == best && oi < bi)) { best = ob; bi = oi; }
        }
        if (lane == 0) {
            float dx = jx - px[bi], dy = jy - py[bi], dz = jz - pz[bi];
            float* f = (hand == 0 ? fl : fr);
            f[F_ATT + joint*3 + 0] = expf(-50.f * dx * dx);
            f[F_ATT + joint*3 + 1] = expf(-50.f * dy * dy);
            f[F_ATT + joint*3 + 2] = expf(-50.f * dz * dz);
        }
    }
}

// ---------------------------------------------------------------------------
// Pad output-head weights: [512][99] -> [512][128] (zeros beyond 99)
// ---------------------------------------------------------------------------
__global__ void pad_wout_kernel(const float* __restrict__ Wl, const float* __restrict__ Wr,
                                float* __restrict__ dl, float* __restrict__ dr)
{
    int idx = blockIdx.x * 256 + threadIdx.x;   // 65536 total
    int row = idx >> 7, col = idx & 127;
    float vl = (col < HAND_DIM) ? Wl[row*HAND_DIM + col] : 0.f;
    float vr = (col < HAND_DIM) ? Wr[row*HAND_DIM + col] : 0.f;
    dl[idx] = vl; dr[idx] = vr;
}

// ---------------------------------------------------------------------------
// Epilogues
// ---------------------------------------------------------------------------
struct EpiParams {
    const float* bias;
    const float* mask;           // [4096]
    const unsigned char* pad;    // [8192] bool
    int hand;
    int relu;
    int nreal;                   // GUARD: real column count
};

#define LN10000 9.2103403719761827f

template<int EPI>
__device__ __forceinline__ float apply_epi(float v, int row, int col, const EpiParams& ep)
{
    if (EPI == 0) {
        if (ep.bias) v += ep.bias[col];
        if (ep.relu) v = fmaxf(v, 0.f);
    } else if (EPI == 1) {
        int l = row & 127;
        int ii = col >> 1;
        float freq = expf(-LN10000 * (float)ii * (1.f/256.f));
        float angF = (float)l * freq;
        float angA = (float)ep.hand * freq;
        float pe = (col & 1) ? (cosf(angF) + cosf(angA))
                             : (sinf(angF) + sinf(angA));
        float mv = ep.mask[row] * (ep.pad[2*row + ep.hand] ? 0.f : 1.f);
        v = (v + ep.bias[col] + pe) * mv;
    } else { // EPI == 2
        float mv = ep.mask[row] * (ep.pad[2*row + ep.hand] ? 0.f : 1.f);
        v = (v + ep.bias[col]) * mv;
    }
    return v;
}

// ---------------------------------------------------------------------------
// Multi-job bf16x3 tensor-core GEMM (legacy mma.sync path).
// Block tile 128x64, BK=32, 8 warps (warp tile 32x32), 2 CTAs/SM.
// blockIdx.z selects an independent (A,B,C,epi) job with shared dims.
// ---------------------------------------------------------------------------
struct Job { const float* A; const float* B; float* C; EpiParams ep; };
template<int NJ> struct Jobs { Job j[NJ]; };

#define PA 80
#define PB 144
#define A_BYTES (128*PA)
#define B_BYTES (32*PB)
#define OFF_AH 0
#define OFF_AL (A_BYTES)
#define OFF_BH (2*A_BYTES)
#define OFF_BL (2*A_BYTES + B_BYTES)
#define BUF_BYTES (2*A_BYTES + 2*B_BYTES)   // 29696
#define TG_SMEM (2*BUF_BYTES)               // 59392

__device__ __forceinline__ unsigned smem_u32(const void* p) {
    return (unsigned)__cvta_generic_to_shared(p);
}
__device__ __forceinline__ void ldsm4(unsigned* r, unsigned addr) {
    asm volatile("ldmatrix.sync.aligned.m8n8.x4.shared.b16 {%0,%1,%2,%3}, [%4];"
        : "=r"(r[0]), "=r"(r[1]), "=r"(r[2]), "=r"(r[3]) : "r"(addr));
}
__device__ __forceinline__ void ldsm4t(unsigned* r, unsigned addr) {
    asm volatile("ldmatrix.sync.aligned.m8n8.x4.trans.shared.b16 {%0,%1,%2,%3}, [%4];"
        : "=r"(r[0]), "=r"(r[1]), "=r"(r[2]), "=r"(r[3]) : "r"(addr));
}
__device__ __forceinline__ void mma16816(float* c, const unsigned* a, unsigned b0, unsigned b1) {
    asm volatile(
        "mma.sync.aligned.m16n8k16.row.col.f32.bf16.bf16.f32 "
        "{%0,%1,%2,%3}, {%4,%5,%6,%7}, {%8,%9}, {%0,%1,%2,%3};"
        : "+f"(c[0]), "+f"(c[1]), "+f"(c[2]), "+f"(c[3])
        : "r"(a[0]), "r"(a[1]), "r"(a[2]), "r"(a[3]), "r"(b0), "r"(b1));
}
__device__ __forceinline__ void cvt4(const float4& v, uint2& hp, uint2& lp) {
    float vv[4] = {v.x, v.y, v.z, v.w};
    unsigned short hs[4], ls[4];
    #pragma unroll
    for (int e = 0; e < 4; e++) {
        __nv_bfloat16 h = __float2bfloat16_rn(vv[e]);
        float r = vv[e] - __bfloat162float(h);
        __nv_bfloat16 l = __float2bfloat16_rn(r);
        hs[e] = __bfloat16_as_ushort(h);
        ls[e] = __bfloat16_as_ushort(l);
    }
    hp.x = (unsigned)hs[0] | ((unsigned)hs[1] << 16);
    hp.y = (unsigned)hs[2] | ((unsigned)hs[3] << 16);
    lp.x = (unsigned)ls[0] | ((unsigned)ls[1] << 16);
    lp.y = (unsigned)ls[2] | ((unsigned)ls[3] << 16);
}

template<int EPI, int GUARD, int NJ>
__global__ __launch_bounds__(256, 2)
void tgemm(Jobs<NJ> jobs, int lda, int ldb, int ldc, int M, int N, int Kreal)
{
    const Job& jb = jobs.j[blockIdx.z];
    const float* __restrict__ A = jb.A;
    const float* __restrict__ B = jb.B;
    float* __restrict__ C = jb.C;
    EpiParams ep = jb.ep;

    extern __shared__ unsigned char smraw[];
    unsigned sbase = smem_u32(smraw);
    int tid = threadIdx.x, lane = tid & 31, wid = tid >> 5;
    int warp_m = wid & 3, warp_n = wid >> 2;
    int m0 = blockIdx.y * 128, n0 = blockIdx.x * 64;
    int g = lane >> 2, t = lane & 3;

    float acc[2][4][4];
    #pragma unroll
    for (int i = 0; i < 2; i++)
        #pragma unroll
        for (int j = 0; j < 4; j++)
            #pragma unroll
            for (int e = 0; e < 4; e++) acc[i][j][e] = 0.f;

    int ar[4], ak[4], br[2], bn[2];
    #pragma unroll
    for (int i = 0; i < 4; i++) {
        int f = tid + 256*i;
        ar[i] = f >> 3;  ak[i] = (f & 7) * 4;
    }
    #pragma unroll
    for (int i = 0; i < 2; i++) {
        int f = tid + 256*i;
        br[i] = f >> 4;  bn[i] = (f & 15) * 4;
    }

    int aRow = lane & 15;
    int aKof = ((lane >> 4) & 1) * 8;
    int bRow = lane & 15;
    int bNof = ((lane >> 4) & 1) * 8;

    int nk = (Kreal + 31) >> 5;
    float4 ra[4], rb[2];

    auto load_g = [&](int kt) {
        int k0 = kt * 32;
        #pragma unroll
        for (int i = 0; i < 4; i++)
            ra[i] = *(const float4*)(A + (size_t)(m0 + ar[i])*lda + k0 + ak[i]);
        #pragma unroll
        for (int i = 0; i < 2; i++) {
            int k = k0 + br[i];
            rb[i] = (k < Kreal) ? *(const float4*)(B + (size_t)k*ldb + n0 + bn[i])
                                : make_float4(0.f, 0.f, 0.f, 0.f);
        }
    };
    auto cvt_store = [&](int buf) {
        unsigned char* bp = smraw + buf * BUF_BYTES;
        #pragma unroll
        for (int i = 0; i < 4; i++) {
            uint2 hp, lp;
            cvt4(ra[i], hp, lp);
            int off = ar[i]*PA + ak[i]*2;
            *(uint2*)(bp + OFF_AH + off) = hp;
            *(uint2*)(bp + OFF_AL + off) = lp;
        }
        #pragma unroll
        for (int i = 0; i < 2; i++) {
            uint2 hp, lp;
            cvt4(rb[i], hp, lp);
            int off = br[i]*PB + bn[i]*2;
            *(uint2*)(bp + OFF_BH + off) = hp;
            *(uint2*)(bp + OFF_BL + off) = lp;
        }
    };

    load_g(0);
    cvt_store(0);
    __syncthreads();

    for (int kt = 0; kt < nk; kt++) {
        if (kt + 1 < nk) load_g(kt + 1);

        unsigned base = sbase + (kt & 1) * BUF_BYTES;
        #pragma unroll
        for (int ks = 0; ks < 2; ks++) {
            unsigned aAddrBase = base + (ks*16 + aKof) * 2;
            unsigned bAddrBase = base + (ks*16 + bRow) * PB;

            unsigned ah[2][4], bh[2][4];
            #pragma unroll
            for (int mt = 0; mt < 2; mt++)
                ldsm4(ah[mt], aAddrBase + OFF_AH + (warp_m*32 + mt*16 + aRow)*PA);
            #pragma unroll
            for (int np = 0; np < 2; np++)
                ldsm4t(bh[np], bAddrBase + OFF_BH + (warp_n*32 + np*16 + bNof)*2);

            #pragma unroll
            for (int mt = 0; mt < 2; mt++)
                #pragma unroll
                for (int nt = 0; nt < 4; nt++)
                    mma16816(acc[mt][nt], ah[mt], bh[nt>>1][(nt&1)*2], bh[nt>>1][(nt&1)*2+1]);

            unsigned bl[2][4];
            #pragma unroll
            for (int np = 0; np < 2; np++)
                ldsm4t(bl[np], bAddrBase + OFF_BL + (warp_n*32 + np*16 + bNof)*2);
            #pragma unroll
            for (int mt = 0; mt < 2; mt++)
                #pragma unroll
                for (int nt = 0; nt < 4; nt++)
                    mma16816(acc[mt][nt], ah[mt], bl[nt>>1][(nt&1)*2], bl[nt>>1][(nt&1)*2+1]);

            unsigned al[2][4];
            #pragma unroll
            for (int mt = 0; mt < 2; mt++)
                ldsm4(al[mt], aAddrBase + OFF_AL + (warp_m*32 + mt*16 + aRow)*PA);
            #pragma unroll
            for (int mt = 0; mt < 2; mt++)
                #pragma unroll
                for (int nt = 0; nt < 4; nt++)
                    mma16816(acc[mt][nt], al[mt], bh[nt>>1][(nt&1)*2], bh[nt>>1][(nt&1)*2+1]);
        }

        if (kt + 1 < nk) cvt_store((kt + 1) & 1);
        __syncthreads();
    }

    #pragma unroll
    for (int mt = 0; mt < 2; mt++) {
        int row0 = m0 + warp_m*32 + mt*16 + g;
        #pragma unroll
        for (int nt = 0; nt < 4; nt++) {
            int col = n0 + warp_n*32 + nt*8 + t*2;
            float* c = acc[mt][nt];
            if (GUARD) {
                if (col < ep.nreal)
                    C[(size_t)row0*ldc + col] = apply_epi<EPI>(c[0], row0, col, ep);
                if (col + 1 < ep.nreal)
                    C[(size_t)row0*ldc + col + 1] = apply_epi<EPI>(c[1], row0, col + 1, ep);
                if (col < ep.nreal)
                    C[(size_t)(row0+8)*ldc + col] = apply_epi<EPI>(c[2], row0 + 8, col, ep);
                if (col + 1 < ep.nreal)
                    C[(size_t)(row0+8)*ldc + col + 1] = apply_epi<EPI>(c[3], row0 + 8, col + 1, ep);
            } else {
                float v0 = apply_epi<EPI>(c[0], row0,     col,     ep);
                float v1 = apply_epi<EPI>(c[1], row0,     col + 1, ep);
                float v2 = apply_epi<EPI>(c[2], row0 + 8, col,     ep);
                float v3 = apply_epi<EPI>(c[3], row0 + 8, col + 1, ep);
                *(float2*)(C + (size_t)row0*ldc + col)       = make_float2(v0, v1);
                *(float2*)(C + (size_t)(row0 + 8)*ldc + col) = make_float2(v2, v3);
            }
        }
    }
}

// ---------------------------------------------------------------------------
// Fused attention: 2 q-rows/warp pass, float4 smem accesses, pitch 68
// ---------------------------------------------------------------------------
#define KV_PITCH 68
#define ATT_SMEM ((2*256*KV_PITCH + 16*256 + 8*128 + 256) * (int)sizeof(float))

__global__ void attention_kernel(const float* __restrict__ qb,
                                 const float* __restrict__ kb,
                                 const float* __restrict__ vb,
                                 const unsigned char* __restrict__ pad,
                                 float* __restrict__ ob)
{
    int bh = blockIdx.x;
    int b = bh >> 3, h = bh & 7;
    extern __shared__ float sm[];
    float* Ks = sm;                         // [256][68]
    float* Vs = Ks + 256*KV_PITCH;          // [256][68]
    float* Ps = Vs + 256*KV_PITCH;          // [16][256]
    float* Qs = Ps + 16*256;                // [8][128]
    float* Bsb = Qs + 8*128;                // [256]

    int tid = threadIdx.x, lane = tid & 31, w = tid >> 5;
    const float* kbase = kb + (size_t)(b*SS)*DD + h*DHH;
    const float* vbase = vb + (size_t)(b*SS)*DD + h*DHH;

    for (int idx = tid; idx < 256*64; idx += 256) {
        int r = idx >> 6, c = idx & 63;
        Ks[r*KV_PITCH + c] = kbase[(size_t)r*DD + c];
        Vs[r*KV_PITCH + c] = vbase[(size_t)r*DD + c];
    }
    if (tid < 256) Bsb[tid] = pad[b*SS + tid] ? -1e9f : 0.f;
    __syncthreads();

    float* Pw0 = Ps + (2*w + 0)*256;
    float* Pw1 = Ps + (2*w + 1)*256;
    float* Qw = Qs + w*128;

    for (int qi = 2*w; qi < SS; qi += 16) {
        const float* q0 = qb + (size_t)(b*SS + qi)*DD + h*DHH;
        Qw[lane]           = q0[lane];
        Qw[lane + 32]      = q0[lane + 32];
        Qw[64 + lane]      = q0[DD + lane];
        Qw[64 + lane + 32] = q0[DD + lane + 32];
        __syncwarp();

        const float4* q4a = (const float4*)Qw;
        const float4* q4b = (const float4*)(Qw + 64);

        float s0[8], s1[8];
        float mx0 = -3.402823466e+38f, mx1 = -3.402823466e+38f;
        #pragma unroll
        for (int k8 = 0; k8 < 8; k8++) {
            int j = lane + 32*k8;
            const float4* kr4 = (const float4*)(Ks + j*KV_PITCH);
            float a0 = 0.f, a1 = 0.f;
            #pragma unroll
            for (int d4 = 0; d4 < 16; d4++) {
                float4 kv = kr4[d4];
                float4 qa = q4a[d4];
                float4 qb4 = q4b[d4];
                a0 += qa.x*kv.x + qa.y*kv.y + qa.z*kv.z + qa.w*kv.w;
                a1 += qb4.x*kv.x + qb4.y*kv.y + qb4.z*kv.z + qb4.w*kv.w;
            }
            float bias = Bsb[j];
            a0 = a0 * 0.125f + bias;
            a1 = a1 * 0.125f + bias;
            s0[k8] = a0; s1[k8] = a1;
            mx0 = fmaxf(mx0, a0); mx1 = fmaxf(mx1, a1);
        }
        for (int off = 16; off; off >>= 1) {
            mx0 = fmaxf(mx0, __shfl_xor_sync(0xffffffffu, mx0, off));
            mx1 = fmaxf(mx1, __shfl_xor_sync(0xffffffffu, mx1, off));
        }
        float sm0 = 0.f, sm1 = 0.f;
        #pragma unroll
        for (int k8 = 0; k8 < 8; k8++) {
            s0[k8] = __expf(s0[k8] - mx0); sm0 += s0[k8];
            s1[k8] = __expf(s1[k8] - mx1); sm1 += s1[k8];
        }
        for (int off = 16; off; off >>= 1) {
            sm0 += __shfl_xor_sync(0xffffffffu, sm0, off);
            sm1 += __shfl_xor_sync(0xffffffffu, sm1, off);
        }
        float i0 = 1.f / sm0, i1 = 1.f / sm1;
        #pragma unroll
        for (int k8 = 0; k8 < 8; k8++) {
            Pw0[lane + 32*k8] = s0[k8]*i0;
            Pw1[lane + 32*k8] = s1[k8]*i1;
        }
        __syncwarp();

        const float4* P04 = (const float4*)Pw0;
        const float4* P14 = (const float4*)Pw1;
        float o00 = 0.f, o01 = 0.f, o10 = 0.f, o11 = 0.f;
        for (int j4 = 0; j4 < 64; j4++) {
            float4 p0 = P04[j4];
            float4 p1 = P14[j4];
            const float* vr = Vs + (j4*4)*KV_PITCH + lane;
            float va0 = vr[0],            vb0 = vr[32];
            float va1 = vr[KV_PITCH],     vb1 = vr[KV_PITCH + 32];
            float va2 = vr[2*KV_PITCH],   vb2 = vr[2*KV_PITCH + 32];
            float va3 = vr[3*KV_PITCH],   vb3 = vr[3*KV_PITCH + 32];
            o00 += p0.x*va0 + p0.y*va1 + p0.z*va2 + p0.w*va3;
            o01 += p0.x*vb0 + p0.y*vb1 + p0.z*vb2 + p0.w*vb3;
            o10 += p1.x*va0 + p1.y*va1 + p1.z*va2 + p1.w*va3;
            o11 += p1.x*vb0 + p1.y*vb1 + p1.z*vb2 + p1.w*vb3;
        }
        float* orow = ob + (size_t)(b*SS + qi)*DD + h*DHH;
        orow[lane]           = o00;
        orow[lane + 32]      = o01;
        orow[DD + lane]      = o10;
        orow[DD + lane + 32] = o11;
        __syncwarp();
    }
}

// ---------------------------------------------------------------------------
// Residual add + LayerNorm
// ---------------------------------------------------------------------------
__global__ void ln_kernel(const float* __restrict__ x, const float* __restrict__ add,
                          const float* __restrict__ g, const float* __restrict__ bv,
                          float* __restrict__ out)
{
    int t = blockIdx.x;
    int tid = threadIdx.x;
    const float* xr = x   + (size_t)t*DD;
    const float* ar = add + (size_t)t*DD;
    float v[4];
    float s = 0.f, ss = 0.f;
    #pragma unroll
    for (int i = 0; i < 4; i++) {
        float u = xr[tid + 128*i] + ar[tid + 128*i];
        v[i] = u; s += u; ss += u*u;
    }
    for (int off = 16; off; off >>= 1) {
        s  += __shfl_xor_sync(0xffffffffu, s,  off);
        ss += __shfl_xor_sync(0xffffffffu, ss, off);
    }
    __shared__ float rs[4], rss[4];
    int w = tid >> 5, lane = tid & 31;
    if (lane == 0) { rs[w] = s; rss[w] = ss; }
    __syncthreads();
    s  = rs[0]+rs[1]+rs[2]+rs[3];
    ss = rss[0]+rss[1]+rss[2]+rss[3];
    float mean = s * (1.f/512.f);
    float var  = ss * (1.f/512.f) - mean*mean;
    float rstd = rsqrtf(var + 1e-5f);
    #pragma unroll
    for (int i = 0; i < 4; i++) {
        int c = tid + 128*i;
        out[(size_t)t*DD + c] = (v[i]-mean)*rstd*g[c] + bv[c];
    }
}

// ---------------------------------------------------------------------------
// Launch
// ---------------------------------------------------------------------------
extern "C" void kernel_launch(void* const* d_in, const int* in_sizes, int n_in,
                              void* d_out, int out_size)
{
    const float* x_l  = (const float*)d_in[0];
    const float* x_r  = (const float*)d_in[1];
    const float* j_l  = (const float*)d_in[2];
    const float* j_r  = (const float*)d_in[3];
    const float* mcon = (const float*)d_in[4];
    const float* pc   = (const float*)d_in[5];
    const float* mask_l = (const float*)d_in[6];
    const float* mask_r = (const float*)d_in[7];
    const unsigned char* pad = (const unsigned char*)d_in[8];
    const float* W_fc_l = (const float*)d_in[9];
    const float* b_fc_l = (const float*)d_in[10];
    const float* W_fc_r = (const float*)d_in[11];
    const float* b_fc_r = (const float*)d_in[12];
    const float* Wq = (const float*)d_in[13];
    const float* Wk = (const float*)d_in[14];
    const float* Wv = (const float*)d_in[15];
    const float* Wo = (const float*)d_in[16];
    const float* W1 = (const float*)d_in[17];
    const float* b1 = (const float*)d_in[18];
    const float* W2 = (const float*)d_in[19];
    const float* b2 = (const float*)d_in[20];
    const float* ln1g = (const float*)d_in[21];
    const float* ln1b = (const float*)d_in[22];
    const float* ln2g = (const float*)d_in[23];
    const float* ln2b = (const float*)d_in[24];
    const float* W_out_l = (const float*)d_in[25];
    const float* b_out_l = (const float*)d_in[26];
    const float* W_out_r = (const float*)d_in[27];
    const float* b_out_r = (const float*)d_in[28];
    float* outp = (float*)d_out;

    float *pfl, *pfr, *px, *pq, *pk, *pv, *pao, *pproj, *px1, *ph, *pf, *px2, *pwl, *pwr;
    cudaGetSymbolAddress((void**)&pfl,  g_feat_l);
    cudaGetSymbolAddress((void**)&pfr,  g_feat_r);
    cudaGetSymbolAddress((void**)&px,   g_x);
    cudaGetSymbolAddress((void**)&pq,   g_q);
    cudaGetSymbolAddress((void**)&pk,   g_k);
    cudaGetSymbolAddress((void**)&pv,   g_v);
    cudaGetSymbolAddress((void**)&pao,  g_ao);
    cudaGetSymbolAddress((void**)&pproj,g_proj);
    cudaGetSymbolAddress((void**)&px1,  g_x1);
    cudaGetSymbolAddress((void**)&ph,   g_h);
    cudaGetSymbolAddress((void**)&pf,   g_f);
    cudaGetSymbolAddress((void**)&px2,  g_x2);
    cudaGetSymbolAddress((void**)&pwl,  g_woutl);
    cudaGetSymbolAddress((void**)&pwr,  g_woutr);

    cudaFuncSetAttribute((const void*)tgemm<0,0,1>, cudaFuncAttributeMaxDynamicSharedMemorySize, TG_SMEM);
    cudaFuncSetAttribute((const void*)tgemm<0,0,3>, cudaFuncAttributeMaxDynamicSharedMemorySize, TG_SMEM);
    cudaFuncSetAttribute((const void*)tgemm<1,0,2>, cudaFuncAttributeMaxDynamicSharedMemorySize, TG_SMEM);
    cudaFuncSetAttribute((const void*)tgemm<2,1,2>, cudaFuncAttributeMaxDynamicSharedMemorySize, TG_SMEM);
    cudaFuncSetAttribute(attention_kernel,
                         cudaFuncAttributeMaxDynamicSharedMemorySize, ATT_SMEM);

    EpiParams none = {nullptr, nullptr, nullptr, 0, 0, 0};

    // 0. pad head weights
    pad_wout_kernel<<<256, 256>>>(W_out_l, W_out_r, pwl, pwr);

    // 1. features
    build_features_kernel<<<ROWS, 256>>>(x_l, x_r, j_l, j_r, mcon, pc, pfl, pfr);

    // 2. fc projections (merged l+r)
    {
        Jobs<2> jb;
        jb.j[0] = { pfl, W_fc_l, px,      {b_fc_l, mask_l, pad, 0, 0, 0} };
        jb.j[1] = { pfr, W_fc_r, px + DD, {b_fc_r, mask_r, pad, 1, 0, 0} };
        tgemm<1,0,2><<<dim3(8,32,2), 256, TG_SMEM>>>(jb, CATP, DD, 2*DD, ROWS, DD, CAT);
    }

    // 3. QKV (merged)
    {
        Jobs<3> jb;
        jb.j[0] = { px, Wq, pq, none };
        jb.j[1] = { px, Wk, pk, none };
        jb.j[2] = { px, Wv, pv, none };
        tgemm<0,0,3><<<dim3(8,64,3), 256, TG_SMEM>>>(jb, DD, DD, DD, TROWS, DD, DD);
    }

    // 4. attention
    attention_kernel<<<BB*HH, 256, ATT_SMEM>>>(pq, pk, pv, pad, pao);

    // 5. Wo + LN1
    {
        Jobs<1> jb; jb.j[0] = { pao, Wo, pproj, none };
        tgemm<0,0,1><<<dim3(8,64,1), 256, TG_SMEM>>>(jb, DD, DD, DD, TROWS, DD, DD);
    }
    ln_kernel<<<TROWS, 128>>>(px, pproj, ln1g, ln1b, px1);

    // 6. FFN + LN2
    {
        Jobs<1> jb; jb.j[0] = { px1, W1, ph, {b1, nullptr, nullptr, 0, 1, 0} };
        tgemm<0,0,1><<<dim3(32,64,1), 256, TG_SMEM>>>(jb, DD, DFF, DFF, TROWS, DFF, DD);
    }
    {
        Jobs<1> jb; jb.j[0] = { ph, W2, pf, {b2, nullptr, nullptr, 0, 0, 0} };
        tgemm<0,0,1><<<dim3(8,64,1), 256, TG_SMEM>>>(jb, DFF, DD, DD, TROWS, DD, DFF);
    }
    ln_kernel<<<TROWS, 128>>>(px1, pf, ln2g, ln2b, px2);

    // 7. output heads (merged l+r, tensor path, guarded cols)
    {
        Jobs<2> jb;
        jb.j[0] = { px2,      pwl, outp,                 {b_out_l, mask_l, pad, 0, 0, HAND_DIM} };
        jb.j[1] = { px2 + DD, pwr, outp + ROWS*HAND_DIM, {b_out_r, mask_r, pad, 1, 0, HAND_DIM} };
        tgemm<2,1,2><<<dim3(2,32,2), 256, TG_SMEM>>>(jb, 2*DD, 128, HAND_DIM, ROWS, 128, DD);
    }
}

// round 9
// speedup vs baseline: 4.5127x; 1.1933x over previous
#include <cuda_runtime.h>
#include <cuda_fp16.h>
#include <math.h>

// ---------------------------------------------------------------------------
// Shapes
// ---------------------------------------------------------------------------
#define BB 32
#define LL 128
#define NN 512
#define JJ 21
#define HAND_DIM 99
#define DD 512
#define HH 8
#define DHH 64
#define DFF 2048
#define CAT 1249
#define CATP 1280
#define SS 256
#define ROWS 4096
#define TROWS 8192

#define F_X 0
#define F_J 99
#define F_MC 162
#define F_PCN 674
#define F_ATT 1186

// ---------------------------------------------------------------------------
// Scratch
// ---------------------------------------------------------------------------
__device__ float g_feat_l[ROWS * CATP];
__device__ float g_feat_r[ROWS * CATP];
__device__ float g_x [TROWS * DD];
__device__ float g_q [TROWS * DD];
__device__ float g_k [TROWS * DD];
__device__ float g_v [TROWS * DD];
__device__ float g_ao [TROWS * DD];
__device__ float g_proj[TROWS * DD];
__device__ float g_x1 [TROWS * DD];
__device__ float g_h [TROWS * DFF];
__device__ float g_f [TROWS * DD];
__device__ float g_x2 [TROWS * DD];

// fp16 weight copies (converted once per call)
__device__ __align__(16) __half g_wfc_l16[CAT * DD];
__device__ __align__(16) __half g_wfc_r16[CAT * DD];
__device__ __align__(16) __half g_wq16 [DD * DD];
__device__ __align__(16) __half g_wk16 [DD * DD];
__device__ __align__(16) __half g_wv16 [DD * DD];
__device__ __align__(16) __half g_wo16 [DD * DD];
__device__ __align__(16) __half g_w116 [DD * DFF];
__device__ __align__(16) __half g_w216 [DFF * DD];
__device__ __align__(16) __half g_woutl16[DD * 128];
__device__ __align__(16) __half g_woutr16[DD * 128];

// ---------------------------------------------------------------------------
// Weight conversion (fp32 -> fp16), 8 jobs in one kernel
// ---------------------------------------------------------------------------
struct CvtJobs {
    const float* src[8];
    __half* dst[8];
    int n4[8];                 // element count / 4
};
__global__ void cvt_weights_kernel(CvtJobs cj)
{
    int gid = blockIdx.x * blockDim.x + threadIdx.x;
    int stride = gridDim.x * blockDim.x;
    #pragma unroll
    for (int j = 0; j < 8; j++) {
        const float4* s = (const float4*)cj.src[j];
        __half2* d = (__half2*)cj.dst[j];
        int n4 = cj.n4[j];
        for (int i = gid; i < n4; i += stride) {
            float4 v = s[i];
            d[2*i]   = __floats2half2_rn(v.x, v.y);
            d[2*i+1] = __floats2half2_rn(v.z, v.w);
        }
    }
}

// pad output-head weights [512][99] -> [512][128] fp16 (zeros beyond 99)
__global__ void pad_wout_kernel(const float* __restrict__ Wl, const float* __restrict__ Wr,
                                __half* __restrict__ dl, __half* __restrict__ dr)
{
    int idx = blockIdx.x * 256 + threadIdx.x;   // 65536 total
    int row = idx >> 7, col = idx & 127;
    float vl = (col < HAND_DIM) ? Wl[row*HAND_DIM + col] : 0.f;
    float vr = (col < HAND_DIM) ? Wr[row*HAND_DIM + col] : 0.f;
    dl[idx] = __float2half_rn(vl);
    dr[idx] = __float2half_rn(vr);
}

// ---------------------------------------------------------------------------
// Feature build
// ---------------------------------------------------------------------------
__global__ void build_features_kernel(
    const float* __restrict__ x_l, const float* __restrict__ x_r,
    const float* __restrict__ j_l, const float* __restrict__ j_r,
    const float* __restrict__ m_contact, const float* __restrict__ pc,
    float* __restrict__ feat_l, float* __restrict__ feat_r)
{
    int m = blockIdx.x;
    int b = m >> 7;
    __shared__ float px[NN], py[NN], pz[NN];
    int tid = threadIdx.x;

    const float* pcb = pc + (size_t)m * NN * 3;
    for (int n = tid; n < NN; n += 256) {
        px[n] = pcb[n*3+0]; py[n] = pcb[n*3+1]; pz[n] = pcb[n*3+2];
    }
    __syncthreads();

    float* fl = feat_l + (size_t)m * CATP;
    float* fr = feat_r + (size_t)m * CATP;

    for (int i = tid; i < HAND_DIM; i += 256) {
        fl[F_X+i] = x_l[(size_t)m*HAND_DIM + i];
        fr[F_X+i] = x_r[(size_t)m*HAND_DIM + i];
    }
    for (int i = tid; i < JJ*3; i += 256) {
        fl[F_J+i] = j_l[(size_t)m*JJ*3 + i];
        fr[F_J+i] = j_r[(size_t)m*JJ*3 + i];
    }
    for (int n = tid; n < NN; n += 256) {
        float mc = m_contact[b*NN + n];
        fl[F_MC+n] = mc; fr[F_MC+n] = mc;
        float nm = sqrtf(px[n]*px[n] + py[n]*py[n] + pz[n]*pz[n]);
        fl[F_PCN+n] = nm; fr[F_PCN+n] = nm;
    }
    for (int i = CAT + tid; i < CATP; i += 256) { fl[i] = 0.f; fr[i] = 0.f; }

    int w = tid >> 5, lane = tid & 31;
    for (int task = w; task < 2*JJ; task += 8) {
        int hand = task / JJ, joint = task % JJ;
        const float* jb = (hand == 0 ? j_l : j_r) + ((size_t)m*JJ + joint)*3;
        float jx = jb[0], jy = jb[1], jz = jb[2];
        float best = 3.402823466e+38f; int bi = 0;
        for (int n = lane; n < NN; n += 32) {
            float dx = jx - px[n], dy = jy - py[n], dz = jz - pz[n];
            float d2 = dx*dx + dy*dy + dz*dz;
            if (d2 < best) { best = d2; bi = n; }
        }
        for (int off = 16; off; off >>= 1) {
            float ob = __shfl_xor_sync(0xffffffffu, best, off);
            int   oi = __shfl_xor_sync(0xffffffffu, bi, off);
            if (ob < best || (ob == best && oi < bi)) { best = ob; bi = oi; }
        }
        if (lane == 0) {
            float dx = jx - px[bi], dy = jy - py[bi], dz = jz - pz[bi];
            float* f = (hand == 0 ? fl : fr);
            f[F_ATT + joint*3 + 0] = expf(-50.f * dx * dx);
            f[F_ATT + joint*3 + 1] = expf(-50.f * dy * dy);
            f[F_ATT + joint*3 + 2] = expf(-50.f * dz * dz);
        }
    }
}

// ---------------------------------------------------------------------------
// Epilogues
// ---------------------------------------------------------------------------
struct EpiParams {
    const float* bias;
    const float* mask;           // [4096]
    const unsigned char* pad;    // [8192] bool
    int hand;
    int relu;
    int nreal;
};

#define LN10000 9.2103403719761827f

template<int EPI>
__device__ __forceinline__ float apply_epi(float v, int row, int col, const EpiParams& ep)
{
    if (EPI == 0) {
        if (ep.bias) v += ep.bias[col];
        if (ep.relu) v = fmaxf(v, 0.f);
    } else if (EPI == 1) {
        int l = row & 127;
        int ii = col >> 1;
        float freq = expf(-LN10000 * (float)ii * (1.f/256.f));
        float angF = (float)l * freq;
        float angA = (float)ep.hand * freq;
        float pe = (col & 1) ? (cosf(angF) + cosf(angA))
                             : (sinf(angF) + sinf(angA));
        float mv = ep.mask[row] * (ep.pad[2*row + ep.hand] ? 0.f : 1.f);
        v = (v + ep.bias[col] + pe) * mv;
    } else { // EPI == 2
        float mv = ep.mask[row] * (ep.pad[2*row + ep.hand] ? 0.f : 1.f);
        v = (v + ep.bias[col]) * mv;
    }
    return v;
}

// ---------------------------------------------------------------------------
// Multi-job fp16x2 tensor-core GEMM (A split hi/lo fp16; B single fp16).
// Block tile 128x64, BK=32, 8 warps (warp tile 32x32), 2 CTAs/SM.
// A [M][K] fp32 (lda); B [K][N] fp16 (ldb) pre-converted. 2 mma passes:
// Ah*B + Al*B. Per-product error ~2^-11 from B rounding.
// ---------------------------------------------------------------------------
struct Job { const float* A; const __half* B; float* C; EpiParams ep; };
template<int NJ> struct Jobs { Job j[NJ]; };

#define PA 80                          // A pitch bytes (odd granule count)
#define PB 144                         // B pitch bytes
#define A_BYTES (128*PA)               // 10240
#define B_BYTES (32*PB)                // 4608
#define OFF_AH 0
#define OFF_AL (A_BYTES)
#define OFF_BH (2*A_BYTES)
#define BUF_BYTES (2*A_BYTES + B_BYTES)   // 25088
#define TG_SMEM (2*BUF_BYTES)             // 50176

__device__ __forceinline__ unsigned smem_u32(const void* p) {
    return (unsigned)__cvta_generic_to_shared(p);
}
__device__ __forceinline__ void ldsm4(unsigned* r, unsigned addr) {
    asm volatile("ldmatrix.sync.aligned.m8n8.x4.shared.b16 {%0,%1,%2,%3}, [%4];"
        : "=r"(r[0]), "=r"(r[1]), "=r"(r[2]), "=r"(r[3]) : "r"(addr));
}
__device__ __forceinline__ void ldsm4t(unsigned* r, unsigned addr) {
    asm volatile("ldmatrix.sync.aligned.m8n8.x4.trans.shared.b16 {%0,%1,%2,%3}, [%4];"
        : "=r"(r[0]), "=r"(r[1]), "=r"(r[2]), "=r"(r[3]) : "r"(addr));
}
__device__ __forceinline__ void mma16816(float* c, const unsigned* a, unsigned b0, unsigned b1) {
    asm volatile(
        "mma.sync.aligned.m16n8k16.row.col.f32.f16.f16.f32 "
        "{%0,%1,%2,%3}, {%4,%5,%6,%7}, {%8,%9}, {%0,%1,%2,%3};"
        : "+f"(c[0]), "+f"(c[1]), "+f"(c[2]), "+f"(c[3])
        : "r"(a[0]), "r"(a[1]), "r"(a[2]), "r"(a[3]), "r"(b0), "r"(b1));
}
// 4 floats -> fp16 hi + fp16 lo (residual)
__device__ __forceinline__ void cvt4(const float4& v, uint2& hp, uint2& lp) {
    float vv[4] = {v.x, v.y, v.z, v.w};
    unsigned short hs[4], ls[4];
    #pragma unroll
    for (int e = 0; e < 4; e++) {
        __half h = __float2half_rn(vv[e]);
        float r = vv[e] - __half2float(h);   // exact
        __half l = __float2half_rn(r);
        hs[e] = __half_as_ushort(h);
        ls[e] = __half_as_ushort(l);
    }
    hp.x = (unsigned)hs[0] | ((unsigned)hs[1] << 16);
    hp.y = (unsigned)hs[2] | ((unsigned)hs[3] << 16);
    lp.x = (unsigned)ls[0] | ((unsigned)ls[1] << 16);
    lp.y = (unsigned)ls[2] | ((unsigned)ls[3] << 16);
}

template<int EPI, int GUARD, int NJ>
__global__ __launch_bounds__(256, 2)
void tgemm(Jobs<NJ> jobs, int lda, int ldb, int ldc, int M, int N, int Kreal)
{
    const Job& jb = jobs.j[blockIdx.z];
    const float* __restrict__ A = jb.A;
    const __half* __restrict__ B = jb.B;
    float* __restrict__ C = jb.C;
    EpiParams ep = jb.ep;

    extern __shared__ unsigned char smraw[];
    unsigned sbase = smem_u32(smraw);
    int tid = threadIdx.x, lane = tid & 31, wid = tid >> 5;
    int warp_m = wid & 3, warp_n = wid >> 2;
    int m0 = blockIdx.y * 128, n0 = blockIdx.x * 64;
    int g = lane >> 2, t = lane & 3;

    float acc[2][4][4];
    #pragma unroll
    for (int i = 0; i < 2; i++)
        #pragma unroll
        for (int j = 0; j < 4; j++)
            #pragma unroll
            for (int e = 0; e < 4; e++) acc[i][j][e] = 0.f;

    int ar[4], ak[4];
    #pragma unroll
    for (int i = 0; i < 4; i++) {
        int f = tid + 256*i;
        ar[i] = f >> 3;  ak[i] = (f & 7) * 4;
    }
    int brw = tid >> 3;            // k row 0..31
    int bc8 = (tid & 7) * 8;       // n col 0..56 step 8

    int aRow = lane & 15;
    int aKof = ((lane >> 4) & 1) * 8;
    int bRow = lane & 15;
    int bNof = ((lane >> 4) & 1) * 8;

    int nk = (Kreal + 31) >> 5;
    float4 ra[4];
    uint4 rbh;

    auto load_g = [&](int kt) {
        int k0 = kt * 32;
        #pragma unroll
        for (int i = 0; i < 4; i++)
            ra[i] = *(const float4*)(A + (size_t)(m0 + ar[i])*lda + k0 + ak[i]);
        int k = k0 + brw;
        rbh = (k < Kreal) ? *(const uint4*)(B + (size_t)k*ldb + n0 + bc8)
                          : make_uint4(0u, 0u, 0u, 0u);
    };
    auto cvt_store = [&](int buf) {
        unsigned char* bp = smraw + buf * BUF_BYTES;
        #pragma unroll
        for (int i = 0; i < 4; i++) {
            uint2 hp, lp;
            cvt4(ra[i], hp, lp);
            int off = ar[i]*PA + ak[i]*2;
            *(uint2*)(bp + OFF_AH + off) = hp;
            *(uint2*)(bp + OFF_AL + off) = lp;
        }
        *(uint4*)(bp + OFF_BH + brw*PB + bc8*2) = rbh;
    };

    load_g(0);
    cvt_store(0);
    __syncthreads();

    for (int kt = 0; kt < nk; kt++) {
        if (kt + 1 < nk) load_g(kt + 1);

        unsigned base = sbase + (kt & 1) * BUF_BYTES;
        #pragma unroll
        for (int ks = 0; ks < 2; ks++) {
            unsigned aAddrBase = base + (ks*16 + aKof) * 2;
            unsigned bAddrBase = base + (ks*16 + bRow) * PB;

            unsigned ah[2][4], bh[2][4];
            #pragma unroll
            for (int mt = 0; mt < 2; mt++)
                ldsm4(ah[mt], aAddrBase + OFF_AH + (warp_m*32 + mt*16 + aRow)*PA);
            #pragma unroll
            for (int np = 0; np < 2; np++)
                ldsm4t(bh[np], bAddrBase + OFF_BH + (warp_n*32 + np*16 + bNof)*2);

            // pass 1: Ah * B
            #pragma unroll
            for (int mt = 0; mt < 2; mt++)
                #pragma unroll
                for (int nt = 0; nt < 4; nt++)
                    mma16816(acc[mt][nt], ah[mt], bh[nt>>1][(nt&1)*2], bh[nt>>1][(nt&1)*2+1]);

            // pass 2: Al * B
            unsigned al[2][4];
            #pragma unroll
            for (int mt = 0; mt < 2; mt++)
                ldsm4(al[mt], aAddrBase + OFF_AL + (warp_m*32 + mt*16 + aRow)*PA);
            #pragma unroll
            for (int mt = 0; mt < 2; mt++)
                #pragma unroll
                for (int nt = 0; nt < 4; nt++)
                    mma16816(acc[mt][nt], al[mt], bh[nt>>1][(nt&1)*2], bh[nt>>1][(nt&1)*2+1]);
        }

        if (kt + 1 < nk) cvt_store((kt + 1) & 1);
        __syncthreads();
    }

    #pragma unroll
    for (int mt = 0; mt < 2; mt++) {
        int row0 = m0 + warp_m*32 + mt*16 + g;
        #pragma unroll
        for (int nt = 0; nt < 4; nt++) {
            int col = n0 + warp_n*32 + nt*8 + t*2;
            float* c = acc[mt][nt];
            if (GUARD) {
                if (col < ep.nreal)
                    C[(size_t)row0*ldc + col] = apply_epi<EPI>(c[0], row0, col, ep);
                if (col + 1 < ep.nreal)
                    C[(size_t)row0*ldc + col + 1] = apply_epi<EPI>(c[1], row0, col + 1, ep);
                if (col < ep.nreal)
                    C[(size_t)(row0+8)*ldc + col] = apply_epi<EPI>(c[2], row0 + 8, col, ep);
                if (col + 1 < ep.nreal)
                    C[(size_t)(row0+8)*ldc + col + 1] = apply_epi<EPI>(c[3], row0 + 8, col + 1, ep);
            } else {
                float v0 = apply_epi<EPI>(c[0], row0,     col,     ep);
                float v1 = apply_epi<EPI>(c[1], row0,     col + 1, ep);
                float v2 = apply_epi<EPI>(c[2], row0 + 8, col,     ep);
                float v3 = apply_epi<EPI>(c[3], row0 + 8, col + 1, ep);
                *(float2*)(C + (size_t)row0*ldc + col)       = make_float2(v0, v1);
                *(float2*)(C + (size_t)(row0 + 8)*ldc + col) = make_float2(v2, v3);
            }
        }
    }
}

// ---------------------------------------------------------------------------
// Fused attention: 2 q-rows/warp pass, float4 smem accesses, pitch 68
// ---------------------------------------------------------------------------
#define KV_PITCH 68
#define ATT_SMEM ((2*256*KV_PITCH + 16*256 + 8*128 + 256) * (int)sizeof(float))

__global__ void attention_kernel(const float* __restrict__ qb,
                                 const float* __restrict__ kb,
                                 const float* __restrict__ vb,
                                 const unsigned char* __restrict__ pad,
                                 float* __restrict__ ob)
{
    int bh = blockIdx.x;
    int b = bh >> 3, h = bh & 7;
    extern __shared__ float sm[];
    float* Ks = sm;
    float* Vs = Ks + 256*KV_PITCH;
    float* Ps = Vs + 256*KV_PITCH;     // [16][256]
    float* Qs = Ps + 16*256;           // [8][128]
    float* Bsb = Qs + 8*128;

    int tid = threadIdx.x, lane = tid & 31, w = tid >> 5;
    const float* kbase = kb + (size_t)(b*SS)*DD + h*DHH;
    const float* vbase = vb + (size_t)(b*SS)*DD + h*DHH;

    for (int idx = tid; idx < 256*64; idx += 256) {
        int r = idx >> 6, c = idx & 63;
        Ks[r*KV_PITCH + c] = kbase[(size_t)r*DD + c];
        Vs[r*KV_PITCH + c] = vbase[(size_t)r*DD + c];
    }
    if (tid < 256) Bsb[tid] = pad[b*SS + tid] ? -1e9f : 0.f;
    __syncthreads();

    float* Pw0 = Ps + (2*w + 0)*256;
    float* Pw1 = Ps + (2*w + 1)*256;
    float* Qw = Qs + w*128;

    for (int qi = 2*w; qi < SS; qi += 16) {
        const float* q0 = qb + (size_t)(b*SS + qi)*DD + h*DHH;
        Qw[lane]           = q0[lane];
        Qw[lane + 32]      = q0[lane + 32];
        Qw[64 + lane]      = q0[DD + lane];
        Qw[64 + lane + 32] = q0[DD + lane + 32];
        __syncwarp();

        const float4* q4a = (const float4*)Qw;
        const float4* q4b = (const float4*)(Qw + 64);

        float s0[8], s1[8];
        float mx0 = -3.402823466e+38f, mx1 = -3.402823466e+38f;
        #pragma unroll
        for (int k8 = 0; k8 < 8; k8++) {
            int j = lane + 32*k8;
            const float4* kr4 = (const float4*)(Ks + j*KV_PITCH);
            float a0 = 0.f, a1 = 0.f;
            #pragma unroll
            for (int d4 = 0; d4 < 16; d4++) {
                float4 kv = kr4[d4];
                float4 qa = q4a[d4];
                float4 qb4 = q4b[d4];
                a0 += qa.x*kv.x + qa.y*kv.y + qa.z*kv.z + qa.w*kv.w;
                a1 += qb4.x*kv.x + qb4.y*kv.y + qb4.z*kv.z + qb4.w*kv.w;
            }
            float bias = Bsb[j];
            a0 = a0 * 0.125f + bias;
            a1 = a1 * 0.125f + bias;
            s0[k8] = a0; s1[k8] = a1;
            mx0 = fmaxf(mx0, a0); mx1 = fmaxf(mx1, a1);
        }
        for (int off = 16; off; off >>= 1) {
            mx0 = fmaxf(mx0, __shfl_xor_sync(0xffffffffu, mx0, off));
            mx1 = fmaxf(mx1, __shfl_xor_sync(0xffffffffu, mx1, off));
        }
        float sm0 = 0.f, sm1 = 0.f;
        #pragma unroll
        for (int k8 = 0; k8 < 8; k8++) {
            s0[k8] = __expf(s0[k8] - mx0); sm0 += s0[k8];
            s1[k8] = __expf(s1[k8] - mx1); sm1 += s1[k8];
        }
        for (int off = 16; off; off >>= 1) {
            sm0 += __shfl_xor_sync(0xffffffffu, sm0, off);
            sm1 += __shfl_xor_sync(0xffffffffu, sm1, off);
        }
        float i0 = 1.f / sm0, i1 = 1.f / sm1;
        #pragma unroll
        for (int k8 = 0; k8 < 8; k8++) {
            Pw0[lane + 32*k8] = s0[k8]*i0;
            Pw1[lane + 32*k8] = s1[k8]*i1;
        }
        __syncwarp();

        const float4* P04 = (const float4*)Pw0;
        const float4* P14 = (const float4*)Pw1;
        float o00 = 0.f, o01 = 0.f, o10 = 0.f, o11 = 0.f;
        for (int j4 = 0; j4 < 64; j4++) {
            float4 p0 = P04[j4];
            float4 p1 = P14[j4];
            const float* vr = Vs + (j4*4)*KV_PITCH + lane;
            float va0 = vr[0],            vb0 = vr[32];
            float va1 = vr[KV_PITCH],     vb1 = vr[KV_PITCH + 32];
            float va2 = vr[2*KV_PITCH],   vb2 = vr[2*KV_PITCH + 32];
            float va3 = vr[3*KV_PITCH],   vb3 = vr[3*KV_PITCH + 32];
            o00 += p0.x*va0 + p0.y*va1 + p0.z*va2 + p0.w*va3;
            o01 += p0.x*vb0 + p0.y*vb1 + p0.z*vb2 + p0.w*vb3;
            o10 += p1.x*va0 + p1.y*va1 + p1.z*va2 + p1.w*va3;
            o11 += p1.x*vb0 + p1.y*vb1 + p1.z*vb2 + p1.w*vb3;
        }
        float* orow = ob + (size_t)(b*SS + qi)*DD + h*DHH;
        orow[lane]           = o00;
        orow[lane + 32]      = o01;
        orow[DD + lane]      = o10;
        orow[DD + lane + 32] = o11;
        __syncwarp();
    }
}

// ---------------------------------------------------------------------------
// Residual add + LayerNorm
// ---------------------------------------------------------------------------
__global__ void ln_kernel(const float* __restrict__ x, const float* __restrict__ add,
                          const float* __restrict__ g, const float* __restrict__ bv,
                          float* __restrict__ out)
{
    int t = blockIdx.x;
    int tid = threadIdx.x;
    const float* xr = x   + (size_t)t*DD;
    const float* ar = add + (size_t)t*DD;
    float v[4];
    float s = 0.f, ss = 0.f;
    #pragma unroll
    for (int i = 0; i < 4; i++) {
        float u = xr[tid + 128*i] + ar[tid + 128*i];
        v[i] = u; s += u; ss += u*u;
    }
    for (int off = 16; off; off >>= 1) {
        s  += __shfl_xor_sync(0xffffffffu, s,  off);
        ss += __shfl_xor_sync(0xffffffffu, ss, off);
    }
    __shared__ float rs[4], rss[4];
    int w = tid >> 5, lane = tid & 31;
    if (lane == 0) { rs[w] = s; rss[w] = ss; }
    __syncthreads();
    s  = rs[0]+rs[1]+rs[2]+rs[3];
    ss = rss[0]+rss[1]+rss[2]+rss[3];
    float mean = s * (1.f/512.f);
    float var  = ss * (1.f/512.f) - mean*mean;
    float rstd = rsqrtf(var + 1e-5f);
    #pragma unroll
    for (int i = 0; i < 4; i++) {
        int c = tid + 128*i;
        out[(size_t)t*DD + c] = (v[i]-mean)*rstd*g[c] + bv[c];
    }
}

// ---------------------------------------------------------------------------
// Launch
// ---------------------------------------------------------------------------
extern "C" void kernel_launch(void* const* d_in, const int* in_sizes, int n_in,
                              void* d_out, int out_size)
{
    const float* x_l  = (const float*)d_in[0];
    const float* x_r  = (const float*)d_in[1];
    const float* j_l  = (const float*)d_in[2];
    const float* j_r  = (const float*)d_in[3];
    const float* mcon = (const float*)d_in[4];
    const float* pc   = (const float*)d_in[5];
    const float* mask_l = (const float*)d_in[6];
    const float* mask_r = (const float*)d_in[7];
    const unsigned char* pad = (const unsigned char*)d_in[8];
    const float* W_fc_l = (const float*)d_in[9];
    const float* b_fc_l = (const float*)d_in[10];
    const float* W_fc_r = (const float*)d_in[11];
    const float* b_fc_r = (const float*)d_in[12];
    const float* Wq = (const float*)d_in[13];
    const float* Wk = (const float*)d_in[14];
    const float* Wv = (const float*)d_in[15];
    const float* Wo = (const float*)d_in[16];
    const float* W1 = (const float*)d_in[17];
    const float* b1 = (const float*)d_in[18];
    const float* W2 = (const float*)d_in[19];
    const float* b2 = (const float*)d_in[20];
    const float* ln1g = (const float*)d_in[21];
    const float* ln1b = (const float*)d_in[22];
    const float* ln2g = (const float*)d_in[23];
    const float* ln2b = (const float*)d_in[24];
    const float* W_out_l = (const float*)d_in[25];
    const float* b_out_l = (const float*)d_in[26];
    const float* W_out_r = (const float*)d_in[27];
    const float* b_out_r = (const float*)d_in[28];
    float* outp = (float*)d_out;

    float *pfl, *pfr, *px, *pq, *pk, *pv, *pao, *pproj, *px1, *ph, *pf, *px2;
    __half *wfcl, *wfcr, *wq16, *wk16, *wv16, *wo16, *w116, *w216, *pwl, *pwr;
    cudaGetSymbolAddress((void**)&pfl,  g_feat_l);
    cudaGetSymbolAddress((void**)&pfr,  g_feat_r);
    cudaGetSymbolAddress((void**)&px,   g_x);
    cudaGetSymbolAddress((void**)&pq,   g_q);
    cudaGetSymbolAddress((void**)&pk,   g_k);
    cudaGetSymbolAddress((void**)&pv,   g_v);
    cudaGetSymbolAddress((void**)&pao,  g_ao);
    cudaGetSymbolAddress((void**)&pproj,g_proj);
    cudaGetSymbolAddress((void**)&px1,  g_x1);
    cudaGetSymbolAddress((void**)&ph,   g_h);
    cudaGetSymbolAddress((void**)&pf,   g_f);
    cudaGetSymbolAddress((void**)&px2,  g_x2);
    cudaGetSymbolAddress((void**)&wfcl, g_wfc_l16);
    cudaGetSymbolAddress((void**)&wfcr, g_wfc_r16);
    cudaGetSymbolAddress((void**)&wq16, g_wq16);
    cudaGetSymbolAddress((void**)&wk16, g_wk16);
    cudaGetSymbolAddress((void**)&wv16, g_wv16);
    cudaGetSymbolAddress((void**)&wo16, g_wo16);
    cudaGetSymbolAddress((void**)&w116, g_w116);
    cudaGetSymbolAddress((void**)&w216, g_w216);
    cudaGetSymbolAddress((void**)&pwl,  g_woutl16);
    cudaGetSymbolAddress((void**)&pwr,  g_woutr16);

    cudaFuncSetAttribute((const void*)tgemm<0,0,1>, cudaFuncAttributeMaxDynamicSharedMemorySize, TG_SMEM);
    cudaFuncSetAttribute((const void*)tgemm<0,0,3>, cudaFuncAttributeMaxDynamicSharedMemorySize, TG_SMEM);
    cudaFuncSetAttribute((const void*)tgemm<1,0,2>, cudaFuncAttributeMaxDynamicSharedMemorySize, TG_SMEM);
    cudaFuncSetAttribute((const void*)tgemm<2,1,2>, cudaFuncAttributeMaxDynamicSharedMemorySize, TG_SMEM);
    cudaFuncSetAttribute(attention_kernel,
                         cudaFuncAttributeMaxDynamicSharedMemorySize, ATT_SMEM);

    EpiParams none = {nullptr, nullptr, nullptr, 0, 0, 0};

    // 0. weight conversion (fp32 -> fp16) + head-weight padding
    {
        CvtJobs cj;
        cj.src[0] = W_fc_l; cj.dst[0] = wfcl; cj.n4[0] = (CAT*DD)/4;
        cj.src[1] = W_fc_r; cj.dst[1] = wfcr; cj.n4[1] = (CAT*DD)/4;
        cj.src[2] = Wq;     cj.dst[2] = wq16; cj.n4[2] = (DD*DD)/4;
        cj.src[3] = Wk;     cj.dst[3] = wk16; cj.n4[3] = (DD*DD)/4;
        cj.src[4] = Wv;     cj.dst[4] = wv16; cj.n4[4] = (DD*DD)/4;
        cj.src[5] = Wo;     cj.dst[5] = wo16; cj.n4[5] = (DD*DD)/4;
        cj.src[6] = W1;     cj.dst[6] = w116; cj.n4[6] = (DD*DFF)/4;
        cj.src[7] = W2;     cj.dst[7] = w216; cj.n4[7] = (DFF*DD)/4;
        cvt_weights_kernel<<<1024, 256>>>(cj);
    }
    pad_wout_kernel<<<256, 256>>>(W_out_l, W_out_r, pwl, pwr);

    // 1. features
    build_features_kernel<<<ROWS, 256>>>(x_l, x_r, j_l, j_r, mcon, pc, pfl, pfr);

    // 2. fc projections (merged l+r)
    {
        Jobs<2> jb;
        jb.j[0] = { pfl, wfcl, px,      {b_fc_l, mask_l, pad, 0, 0, 0} };
        jb.j[1] = { pfr, wfcr, px + DD, {b_fc_r, mask_r, pad, 1, 0, 0} };
        tgemm<1,0,2><<<dim3(8,32,2), 256, TG_SMEM>>>(jb, CATP, DD, 2*DD, ROWS, DD, CAT);
    }

    // 3. QKV (merged)
    {
        Jobs<3> jb;
        jb.j[0] = { px, wq16, pq, none };
        jb.j[1] = { px, wk16, pk, none };
        jb.j[2] = { px, wv16, pv, none };
        tgemm<0,0,3><<<dim3(8,64,3), 256, TG_SMEM>>>(jb, DD, DD, DD, TROWS, DD, DD);
    }

    // 4. attention
    attention_kernel<<<BB*HH, 256, ATT_SMEM>>>(pq, pk, pv, pad, pao);

    // 5. Wo + LN1
    {
        Jobs<1> jb; jb.j[0] = { pao, wo16, pproj, none };
        tgemm<0,0,1><<<dim3(8,64,1), 256, TG_SMEM>>>(jb, DD, DD, DD, TROWS, DD, DD);
    }
    ln_kernel<<<TROWS, 128>>>(px, pproj, ln1g, ln1b, px1);

    // 6. FFN + LN2
    {
        Jobs<1> jb; jb.j[0] = { px1, w116, ph, {b1, nullptr, nullptr, 0, 1, 0} };
        tgemm<0,0,1><<<dim3(32,64,1), 256, TG_SMEM>>>(jb, DD, DFF, DFF, TROWS, DFF, DD);
    }
    {
        Jobs<1> jb; jb.j[0] = { ph, w216, pf, {b2, nullptr, nullptr, 0, 0, 0} };
        tgemm<0,0,1><<<dim3(8,64,1), 256, TG_SMEM>>>(jb, DFF, DD, DD, TROWS, DD, DFF);
    }
    ln_kernel<<<TROWS, 128>>>(px1, pf, ln2g, ln2b, px2);

    // 7. output heads (merged l+r, tensor path, guarded cols)
    {
        Jobs<2> jb;
        jb.j[0] = { px2,      pwl, outp,                 {b_out_l, mask_l, pad, 0, 0, HAND_DIM} };
        jb.j[1] = { px2 + DD, pwr, outp + ROWS*HAND_DIM, {b_out_r, mask_r, pad, 1, 0, HAND_DIM} };
        tgemm<2,1,2><<<dim3(2,32,2), 256, TG_SMEM>>>(jb, 2*DD, 128, HAND_DIM, ROWS, 128, DD);
    }
}

// round 10
// speedup vs baseline: 4.6939x; 1.0402x over previous
#include <cuda_runtime.h>
#include <cuda_fp16.h>
#include <math.h>

// ---------------------------------------------------------------------------
// Shapes
// ---------------------------------------------------------------------------
#define BB 32
#define LL 128
#define NN 512
#define JJ 21
#define HAND_DIM 99
#define DD 512
#define HH 8
#define DHH 64
#define DFF 2048
#define CAT 1249
#define CATP 1280
#define SS 256
#define ROWS 4096
#define TROWS 8192

#define F_X 0
#define F_J 99
#define F_MC 162
#define F_PCN 674
#define F_ATT 1186

// ---------------------------------------------------------------------------
// Scratch
// ---------------------------------------------------------------------------
__device__ float g_feat_l[ROWS * CATP];
__device__ float g_feat_r[ROWS * CATP];
__device__ float g_x [TROWS * DD];
__device__ float g_q [TROWS * DD];
__device__ float g_k [TROWS * DD];
__device__ float g_v [TROWS * DD];
__device__ float g_ao [TROWS * DD];
__device__ float g_proj[TROWS * DD];
__device__ float g_x1 [TROWS * DD];
__device__ float g_h [TROWS * DFF];
__device__ float g_f [TROWS * DD];
__device__ float g_x2 [TROWS * DD];

// fp16 weight copies (converted once per call)
__device__ __align__(16) __half g_wfc_l16[CAT * DD];
__device__ __align__(16) __half g_wfc_r16[CAT * DD];
__device__ __align__(16) __half g_wq16 [DD * DD];
__device__ __align__(16) __half g_wk16 [DD * DD];
__device__ __align__(16) __half g_wv16 [DD * DD];
__device__ __align__(16) __half g_wo16 [DD * DD];
__device__ __align__(16) __half g_w116 [DD * DFF];
__device__ __align__(16) __half g_w216 [DFF * DD];
__device__ __align__(16) __half g_woutl16[DD * 128];
__device__ __align__(16) __half g_woutr16[DD * 128];

// ---------------------------------------------------------------------------
// Weight conversion (fp32 -> fp16)
// ---------------------------------------------------------------------------
struct CvtJobs {
    const float* src[8];
    __half* dst[8];
    int n4[8];
};
__global__ void cvt_weights_kernel(CvtJobs cj)
{
    int gid = blockIdx.x * blockDim.x + threadIdx.x;
    int stride = gridDim.x * blockDim.x;
    #pragma unroll
    for (int j = 0; j < 8; j++) {
        const float4* s = (const float4*)cj.src[j];
        __half2* d = (__half2*)cj.dst[j];
        int n4 = cj.n4[j];
        for (int i = gid; i < n4; i += stride) {
            float4 v = s[i];
            d[2*i]   = __floats2half2_rn(v.x, v.y);
            d[2*i+1] = __floats2half2_rn(v.z, v.w);
        }
    }
}

__global__ void pad_wout_kernel(const float* __restrict__ Wl, const float* __restrict__ Wr,
                                __half* __restrict__ dl, __half* __restrict__ dr)
{
    int idx = blockIdx.x * 256 + threadIdx.x;
    int row = idx >> 7, col = idx & 127;
    float vl = (col < HAND_DIM) ? Wl[row*HAND_DIM + col] : 0.f;
    float vr = (col < HAND_DIM) ? Wr[row*HAND_DIM + col] : 0.f;
    dl[idx] = __float2half_rn(vl);
    dr[idx] = __float2half_rn(vr);
}

// ---------------------------------------------------------------------------
// Feature build
// ---------------------------------------------------------------------------
__global__ void build_features_kernel(
    const float* __restrict__ x_l, const float* __restrict__ x_r,
    const float* __restrict__ j_l, const float* __restrict__ j_r,
    const float* __restrict__ m_contact, const float* __restrict__ pc,
    float* __restrict__ feat_l, float* __restrict__ feat_r)
{
    int m = blockIdx.x;
    int b = m >> 7;
    __shared__ float px[NN], py[NN], pz[NN];
    int tid = threadIdx.x;

    const float* pcb = pc + (size_t)m * NN * 3;
    for (int n = tid; n < NN; n += 256) {
        px[n] = pcb[n*3+0]; py[n] = pcb[n*3+1]; pz[n] = pcb[n*3+2];
    }
    __syncthreads();

    float* fl = feat_l + (size_t)m * CATP;
    float* fr = feat_r + (size_t)m * CATP;

    for (int i = tid; i < HAND_DIM; i += 256) {
        fl[F_X+i] = x_l[(size_t)m*HAND_DIM + i];
        fr[F_X+i] = x_r[(size_t)m*HAND_DIM + i];
    }
    for (int i = tid; i < JJ*3; i += 256) {
        fl[F_J+i] = j_l[(size_t)m*JJ*3 + i];
        fr[F_J+i] = j_r[(size_t)m*JJ*3 + i];
    }
    for (int n = tid; n < NN; n += 256) {
        float mc = m_contact[b*NN + n];
        fl[F_MC+n] = mc; fr[F_MC+n] = mc;
        float nm = sqrtf(px[n]*px[n] + py[n]*py[n] + pz[n]*pz[n]);
        fl[F_PCN+n] = nm; fr[F_PCN+n] = nm;
    }
    for (int i = CAT + tid; i < CATP; i += 256) { fl[i] = 0.f; fr[i] = 0.f; }

    int w = tid >> 5, lane = tid & 31;
    for (int task = w; task < 2*JJ; task += 8) {
        int hand = task / JJ, joint = task % JJ;
        const float* jb = (hand == 0 ? j_l : j_r) + ((size_t)m*JJ + joint)*3;
        float jx = jb[0], jy = jb[1], jz = jb[2];
        float best = 3.402823466e+38f; int bi = 0;
        for (int n = lane; n < NN; n += 32) {
            float dx = jx - px[n], dy = jy - py[n], dz = jz - pz[n];
            float d2 = dx*dx + dy*dy + dz*dz;
            if (d2 < best) { best = d2; bi = n; }
        }
        for (int off = 16; off; off >>= 1) {
            float ob = __shfl_xor_sync(0xffffffffu, best, off);
            int   oi = __shfl_xor_sync(0xffffffffu, bi, off);
            if (ob < best || (ob == best && oi < bi)) { best = ob; bi = oi; }
        }
        if (lane == 0) {
            float dx = jx - px[bi], dy = jy - py[bi], dz = jz - pz[bi];
            float* f = (hand == 0 ? fl : fr);
            f[F_ATT + joint*3 + 0] = expf(-50.f * dx * dx);
            f[F_ATT + joint*3 + 1] = expf(-50.f * dy * dy);
            f[F_ATT + joint*3 + 2] = expf(-50.f * dz * dz);
        }
    }
}

// ---------------------------------------------------------------------------
// Epilogues
// ---------------------------------------------------------------------------
struct EpiParams {
    const float* bias;
    const float* mask;
    const unsigned char* pad;
    int hand;
    int relu;
    int nreal;
};

#define LN10000 9.2103403719761827f

template<int EPI>
__device__ __forceinline__ float apply_epi(float v, int row, int col, const EpiParams& ep)
{
    if (EPI == 0) {
        if (ep.bias) v += ep.bias[col];
        if (ep.relu) v = fmaxf(v, 0.f);
    } else if (EPI == 1) {
        int l = row & 127;
        int ii = col >> 1;
        float freq = expf(-LN10000 * (float)ii * (1.f/256.f));
        float angF = (float)l * freq;
        float angA = (float)ep.hand * freq;
        float pe = (col & 1) ? (cosf(angF) + cosf(angA))
                             : (sinf(angF) + sinf(angA));
        float mv = ep.mask[row] * (ep.pad[2*row + ep.hand] ? 0.f : 1.f);
        v = (v + ep.bias[col] + pe) * mv;
    } else { // EPI == 2
        float mv = ep.mask[row] * (ep.pad[2*row + ep.hand] ? 0.f : 1.f);
        v = (v + ep.bias[col]) * mv;
    }
    return v;
}

// ---------------------------------------------------------------------------
// Multi-job fp16x2 tensor-core GEMM. 128 threads, tile 64x64, BK=32,
// 4 warps in 2x2 grid (warp tile 32x32), 4 CTAs/SM.
// A [M][K] fp32 (lda) split hi/lo on the fly; B [K][N] fp16 pre-converted.
// ---------------------------------------------------------------------------
struct Job { const float* A; const __half* B; float* C; EpiParams ep; };
template<int NJ> struct Jobs { Job j[NJ]; };

#define PA 80                          // A pitch bytes (32 halves + pad; 5 granules)
#define PB 144                         // B pitch bytes (64 halves + pad; 9 granules)
#define A_BYTES (64*PA)                // 5120
#define B_BYTES (32*PB)                // 4608
#define OFF_AH 0
#define OFF_AL (A_BYTES)
#define OFF_BH (2*A_BYTES)
#define BUF_BYTES (2*A_BYTES + B_BYTES)   // 14848
#define TG_SMEM (2*BUF_BYTES)             // 29696

__device__ __forceinline__ unsigned smem_u32(const void* p) {
    return (unsigned)__cvta_generic_to_shared(p);
}
__device__ __forceinline__ void ldsm4(unsigned* r, unsigned addr) {
    asm volatile("ldmatrix.sync.aligned.m8n8.x4.shared.b16 {%0,%1,%2,%3}, [%4];"
        : "=r"(r[0]), "=r"(r[1]), "=r"(r[2]), "=r"(r[3]) : "r"(addr));
}
__device__ __forceinline__ void ldsm4t(unsigned* r, unsigned addr) {
    asm volatile("ldmatrix.sync.aligned.m8n8.x4.trans.shared.b16 {%0,%1,%2,%3}, [%4];"
        : "=r"(r[0]), "=r"(r[1]), "=r"(r[2]), "=r"(r[3]) : "r"(addr));
}
__device__ __forceinline__ void mma16816(float* c, const unsigned* a, unsigned b0, unsigned b1) {
    asm volatile(
        "mma.sync.aligned.m16n8k16.row.col.f32.f16.f16.f32 "
        "{%0,%1,%2,%3}, {%4,%5,%6,%7}, {%8,%9}, {%0,%1,%2,%3};"
        : "+f"(c[0]), "+f"(c[1]), "+f"(c[2]), "+f"(c[3])
        : "r"(a[0]), "r"(a[1]), "r"(a[2]), "r"(a[3]), "r"(b0), "r"(b1));
}
__device__ __forceinline__ void cvt4(const float4& v, uint2& hp, uint2& lp) {
    float vv[4] = {v.x, v.y, v.z, v.w};
    unsigned short hs[4], ls[4];
    #pragma unroll
    for (int e = 0; e < 4; e++) {
        __half h = __float2half_rn(vv[e]);
        float r = vv[e] - __half2float(h);   // exact
        __half l = __float2half_rn(r);
        hs[e] = __half_as_ushort(h);
        ls[e] = __half_as_ushort(l);
    }
    hp.x = (unsigned)hs[0] | ((unsigned)hs[1] << 16);
    hp.y = (unsigned)hs[2] | ((unsigned)hs[3] << 16);
    lp.x = (unsigned)ls[0] | ((unsigned)ls[1] << 16);
    lp.y = (unsigned)ls[2] | ((unsigned)ls[3] << 16);
}

template<int EPI, int GUARD, int NJ>
__global__ __launch_bounds__(128, 4)
void tgemm(Jobs<NJ> jobs, int lda, int ldb, int ldc, int M, int N, int Kreal)
{
    const Job& jb = jobs.j[blockIdx.z];
    const float* __restrict__ A = jb.A;
    const __half* __restrict__ B = jb.B;
    float* __restrict__ C = jb.C;
    EpiParams ep = jb.ep;

    extern __shared__ unsigned char smraw[];
    unsigned sbase = smem_u32(smraw);
    int tid = threadIdx.x, lane = tid & 31, wid = tid >> 5;
    int warp_m = wid & 1, warp_n = wid >> 1;
    int m0 = blockIdx.y * 64, n0 = blockIdx.x * 64;
    int g = lane >> 2, t = lane & 3;

    float acc[2][4][4];
    #pragma unroll
    for (int i = 0; i < 2; i++)
        #pragma unroll
        for (int j = 0; j < 4; j++)
            #pragma unroll
            for (int e = 0; e < 4; e++) acc[i][j][e] = 0.f;

    // staging coords: A tile 64x32 fp32 (4 float4/thread), B 32x64 fp16 (2 uint4/thread)
    int ar[4], ak[4];
    #pragma unroll
    for (int i = 0; i < 4; i++) {
        int f = tid + 128*i;
        ar[i] = f >> 3;  ak[i] = (f & 7) * 4;     // rows 0..63, k floats 0..28
    }
    int br[2], bn[2];
    #pragma unroll
    for (int i = 0; i < 2; i++) {
        int f = tid + 128*i;
        br[i] = f >> 3;  bn[i] = (f & 7) * 8;     // rows 0..31, n halves 0..56
    }

    int aRow = lane & 15;
    int aKof = ((lane >> 4) & 1) * 8;
    int bRow = lane & 15;
    int bNof = ((lane >> 4) & 1) * 8;

    int nk = (Kreal + 31) >> 5;
    float4 ra[4];
    uint4 rbh[2];

    auto load_g = [&](int kt) {
        int k0 = kt * 32;
        #pragma unroll
        for (int i = 0; i < 4; i++)
            ra[i] = *(const float4*)(A + (size_t)(m0 + ar[i])*lda + k0 + ak[i]);
        #pragma unroll
        for (int i = 0; i < 2; i++) {
            int k = k0 + br[i];
            rbh[i] = (k < Kreal) ? *(const uint4*)(B + (size_t)k*ldb + n0 + bn[i])
                                 : make_uint4(0u, 0u, 0u, 0u);
        }
    };
    auto cvt_store = [&](int buf) {
        unsigned char* bp = smraw + buf * BUF_BYTES;
        #pragma unroll
        for (int i = 0; i < 4; i++) {
            uint2 hp, lp;
            cvt4(ra[i], hp, lp);
            int off = ar[i]*PA + ak[i]*2;
            *(uint2*)(bp + OFF_AH + off) = hp;
            *(uint2*)(bp + OFF_AL + off) = lp;
        }
        #pragma unroll
        for (int i = 0; i < 2; i++)
            *(uint4*)(bp + OFF_BH + br[i]*PB + bn[i]*2) = rbh[i];
    };

    load_g(0);
    cvt_store(0);
    __syncthreads();

    for (int kt = 0; kt < nk; kt++) {
        if (kt + 1 < nk) load_g(kt + 1);

        unsigned base = sbase + (kt & 1) * BUF_BYTES;
        #pragma unroll
        for (int ks = 0; ks < 2; ks++) {
            unsigned aAddrBase = base + (ks*16 + aKof) * 2;
            unsigned bAddrBase = base + (ks*16 + bRow) * PB;

            unsigned ah[2][4], bh[2][4];
            #pragma unroll
            for (int mt = 0; mt < 2; mt++)
                ldsm4(ah[mt], aAddrBase + OFF_AH + (warp_m*32 + mt*16 + aRow)*PA);
            #pragma unroll
            for (int np = 0; np < 2; np++)
                ldsm4t(bh[np], bAddrBase + OFF_BH + (warp_n*32 + np*16 + bNof)*2);

            // pass 1: Ah * B
            #pragma unroll
            for (int mt = 0; mt < 2; mt++)
                #pragma unroll
                for (int nt = 0; nt < 4; nt++)
                    mma16816(acc[mt][nt], ah[mt], bh[nt>>1][(nt&1)*2], bh[nt>>1][(nt&1)*2+1]);

            // pass 2: Al * B
            unsigned al[2][4];
            #pragma unroll
            for (int mt = 0; mt < 2; mt++)
                ldsm4(al[mt], aAddrBase + OFF_AL + (warp_m*32 + mt*16 + aRow)*PA);
            #pragma unroll
            for (int mt = 0; mt < 2; mt++)
                #pragma unroll
                for (int nt = 0; nt < 4; nt++)
                    mma16816(acc[mt][nt], al[mt], bh[nt>>1][(nt&1)*2], bh[nt>>1][(nt&1)*2+1]);
        }

        if (kt + 1 < nk) cvt_store((kt + 1) & 1);
        __syncthreads();
    }

    #pragma unroll
    for (int mt = 0; mt < 2; mt++) {
        int row0 = m0 + warp_m*32 + mt*16 + g;
        #pragma unroll
        for (int nt = 0; nt < 4; nt++) {
            int col = n0 + warp_n*32 + nt*8 + t*2;
            float* c = acc[mt][nt];
            if (GUARD) {
                if (col < ep.nreal)
                    C[(size_t)row0*ldc + col] = apply_epi<EPI>(c[0], row0, col, ep);
                if (col + 1 < ep.nreal)
                    C[(size_t)row0*ldc + col + 1] = apply_epi<EPI>(c[1], row0, col + 1, ep);
                if (col < ep.nreal)
                    C[(size_t)(row0+8)*ldc + col] = apply_epi<EPI>(c[2], row0 + 8, col, ep);
                if (col + 1 < ep.nreal)
                    C[(size_t)(row0+8)*ldc + col + 1] = apply_epi<EPI>(c[3], row0 + 8, col + 1, ep);
            } else {
                float v0 = apply_epi<EPI>(c[0], row0,     col,     ep);
                float v1 = apply_epi<EPI>(c[1], row0,     col + 1, ep);
                float v2 = apply_epi<EPI>(c[2], row0 + 8, col,     ep);
                float v3 = apply_epi<EPI>(c[3], row0 + 8, col + 1, ep);
                *(float2*)(C + (size_t)row0*ldc + col)       = make_float2(v0, v1);
                *(float2*)(C + (size_t)(row0 + 8)*ldc + col) = make_float2(v2, v3);
            }
        }
    }
}

// ---------------------------------------------------------------------------
// Fused attention: fp16 K (row-major, pitch 72 halves) + fp16 V^T (pitch 258),
// 2 q-rows/warp pass, 2 CTAs/SM.
// smem layout (bytes): K 36864 | Vt 33024 | Ps 16384 | Qs 4096 | Bsb 1024
// ---------------------------------------------------------------------------
#define KP 72
#define VTP 258
#define ATT_K_OFF 0
#define ATT_VT_OFF 36864
#define ATT_PS_OFF 69888
#define ATT_QS_OFF 86272
#define ATT_BS_OFF 90368
#define ATT_SMEM 91392

__global__ __launch_bounds__(256, 2)
void attention_kernel(const float* __restrict__ qb,
                      const float* __restrict__ kb,
                      const float* __restrict__ vb,
                      const unsigned char* __restrict__ pad,
                      float* __restrict__ ob)
{
    int bh = blockIdx.x;
    int b = bh >> 3, h = bh & 7;
    extern __shared__ unsigned char smb[];
    __half* Ks = (__half*)(smb + ATT_K_OFF);    // [256][72]
    __half* Vt = (__half*)(smb + ATT_VT_OFF);   // [64][258]  (col-major V)
    float* Ps  = (float*)(smb + ATT_PS_OFF);    // [16][256]
    float* Qs  = (float*)(smb + ATT_QS_OFF);    // [8][128]
    float* Bsb = (float*)(smb + ATT_BS_OFF);    // [256]

    int tid = threadIdx.x, lane = tid & 31, w = tid >> 5;
    const float* kbase = kb + (size_t)(b*SS)*DD + h*DHH;
    const float* vbase = vb + (size_t)(b*SS)*DD + h*DHH;

    for (int idx = tid; idx < 256*64; idx += 256) {
        int r = idx >> 6, c = idx & 63;
        Ks[r*KP + c] = __float2half_rn(kbase[(size_t)r*DD + c]);
        Vt[c*VTP + r] = __float2half_rn(vbase[(size_t)r*DD + c]);
    }
    if (tid < 256) Bsb[tid] = pad[b*SS + tid] ? -1e9f : 0.f;
    __syncthreads();

    float* Pw0 = Ps + (2*w + 0)*256;
    float* Pw1 = Ps + (2*w + 1)*256;
    float* Qw = Qs + w*128;

    for (int qi = 2*w; qi < SS; qi += 16) {
        const float* q0 = qb + (size_t)(b*SS + qi)*DD + h*DHH;
        Qw[lane]           = q0[lane];
        Qw[lane + 32]      = q0[lane + 32];
        Qw[64 + lane]      = q0[DD + lane];
        Qw[64 + lane + 32] = q0[DD + lane + 32];
        __syncwarp();

        const float4* q4a = (const float4*)Qw;
        const float4* q4b = (const float4*)(Qw + 64);

        float s0[8], s1[8];
        float mx0 = -3.402823466e+38f, mx1 = -3.402823466e+38f;
        #pragma unroll
        for (int k8 = 0; k8 < 8; k8++) {
            int j = lane + 32*k8;
            const uint4* kr4 = (const uint4*)(Ks + j*KP);    // 8 halves per uint4
            float a0 = 0.f, a1 = 0.f;
            #pragma unroll
            for (int d8 = 0; d8 < 8; d8++) {
                uint4 kv = kr4[d8];
                float2 f0 = __half22float2(*(__half2*)&kv.x);
                float2 f1 = __half22float2(*(__half2*)&kv.y);
                float2 f2 = __half22float2(*(__half2*)&kv.z);
                float2 f3 = __half22float2(*(__half2*)&kv.w);
                float4 qa0 = q4a[d8*2],   qa1 = q4a[d8*2+1];
                float4 qb0 = q4b[d8*2],   qb1 = q4b[d8*2+1];
                a0 += qa0.x*f0.x + qa0.y*f0.y + qa0.z*f1.x + qa0.w*f1.y
                    + qa1.x*f2.x + qa1.y*f2.y + qa1.z*f3.x + qa1.w*f3.y;
                a1 += qb0.x*f0.x + qb0.y*f0.y + qb0.z*f1.x + qb0.w*f1.y
                    + qb1.x*f2.x + qb1.y*f2.y + qb1.z*f3.x + qb1.w*f3.y;
            }
            float bias = Bsb[j];
            a0 = a0 * 0.125f + bias;
            a1 = a1 * 0.125f + bias;
            s0[k8] = a0; s1[k8] = a1;
            mx0 = fmaxf(mx0, a0); mx1 = fmaxf(mx1, a1);
        }
        for (int off = 16; off; off >>= 1) {
            mx0 = fmaxf(mx0, __shfl_xor_sync(0xffffffffu, mx0, off));
            mx1 = fmaxf(mx1, __shfl_xor_sync(0xffffffffu, mx1, off));
        }
        float sm0 = 0.f, sm1 = 0.f;
        #pragma unroll
        for (int k8 = 0; k8 < 8; k8++) {
            s0[k8] = __expf(s0[k8] - mx0); sm0 += s0[k8];
            s1[k8] = __expf(s1[k8] - mx1); sm1 += s1[k8];
        }
        for (int off = 16; off; off >>= 1) {
            sm0 += __shfl_xor_sync(0xffffffffu, sm0, off);
            sm1 += __shfl_xor_sync(0xffffffffu, sm1, off);
        }
        float i0 = 1.f / sm0, i1 = 1.f / sm1;
        #pragma unroll
        for (int k8 = 0; k8 < 8; k8++) {
            Pw0[lane + 32*k8] = s0[k8]*i0;
            Pw1[lane + 32*k8] = s1[k8]*i1;
        }
        __syncwarp();

        // PV: V^T rows = output cols; half2 spans 2 consecutive k
        const __half2* vtA = (const __half2*)(Vt + (size_t)lane*VTP);
        const __half2* vtB = (const __half2*)(Vt + (size_t)(lane+32)*VTP);
        const float2* P02 = (const float2*)Pw0;
        const float2* P12 = (const float2*)Pw1;
        float o00 = 0.f, o01 = 0.f, o10 = 0.f, o11 = 0.f;
        for (int j2 = 0; j2 < 128; j2++) {
            float2 p0 = P02[j2];
            float2 p1 = P12[j2];
            float2 vA = __half22float2(vtA[j2]);
            float2 vB = __half22float2(vtB[j2]);
            o00 += p0.x*vA.x + p0.y*vA.y;
            o01 += p0.x*vB.x + p0.y*vB.y;
            o10 += p1.x*vA.x + p1.y*vA.y;
            o11 += p1.x*vB.x + p1.y*vB.y;
        }
        float* orow = ob + (size_t)(b*SS + qi)*DD + h*DHH;
        orow[lane]           = o00;
        orow[lane + 32]      = o01;
        orow[DD + lane]      = o10;
        orow[DD + lane + 32] = o11;
        __syncwarp();
    }
}

// ---------------------------------------------------------------------------
// Residual add + LayerNorm
// ---------------------------------------------------------------------------
__global__ void ln_kernel(const float* __restrict__ x, const float* __restrict__ add,
                          const float* __restrict__ g, const float* __restrict__ bv,
                          float* __restrict__ out)
{
    int t = blockIdx.x;
    int tid = threadIdx.x;
    const float* xr = x   + (size_t)t*DD;
    const float* ar = add + (size_t)t*DD;
    float v[4];
    float s = 0.f, ss = 0.f;
    #pragma unroll
    for (int i = 0; i < 4; i++) {
        float u = xr[tid + 128*i] + ar[tid + 128*i];
        v[i] = u; s += u; ss += u*u;
    }
    for (int off = 16; off; off >>= 1) {
        s  += __shfl_xor_sync(0xffffffffu, s,  off);
        ss += __shfl_xor_sync(0xffffffffu, ss, off);
    }
    __shared__ float rs[4], rss[4];
    int w = tid >> 5, lane = tid & 31;
    if (lane == 0) { rs[w] = s; rss[w] = ss; }
    __syncthreads();
    s  = rs[0]+rs[1]+rs[2]+rs[3];
    ss = rss[0]+rss[1]+rss[2]+rss[3];
    float mean = s * (1.f/512.f);
    float var  = ss * (1.f/512.f) - mean*mean;
    float rstd = rsqrtf(var + 1e-5f);
    #pragma unroll
    for (int i = 0; i < 4; i++) {
        int c = tid + 128*i;
        out[(size_t)t*DD + c] = (v[i]-mean)*rstd*g[c] + bv[c];
    }
}

// ---------------------------------------------------------------------------
// Launch
// ---------------------------------------------------------------------------
extern "C" void kernel_launch(void* const* d_in, const int* in_sizes, int n_in,
                              void* d_out, int out_size)
{
    const float* x_l  = (const float*)d_in[0];
    const float* x_r  = (const float*)d_in[1];
    const float* j_l  = (const float*)d_in[2];
    const float* j_r  = (const float*)d_in[3];
    const float* mcon = (const float*)d_in[4];
    const float* pc   = (const float*)d_in[5];
    const float* mask_l = (const float*)d_in[6];
    const float* mask_r = (const float*)d_in[7];
    const unsigned char* pad = (const unsigned char*)d_in[8];
    const float* W_fc_l = (const float*)d_in[9];
    const float* b_fc_l = (const float*)d_in[10];
    const float* W_fc_r = (const float*)d_in[11];
    const float* b_fc_r = (const float*)d_in[12];
    const float* Wq = (const float*)d_in[13];
    const float* Wk = (const float*)d_in[14];
    const float* Wv = (const float*)d_in[15];
    const float* Wo = (const float*)d_in[16];
    const float* W1 = (const float*)d_in[17];
    const float* b1 = (const float*)d_in[18];
    const float* W2 = (const float*)d_in[19];
    const float* b2 = (const float*)d_in[20];
    const float* ln1g = (const float*)d_in[21];
    const float* ln1b = (const float*)d_in[22];
    const float* ln2g = (const float*)d_in[23];
    const float* ln2b = (const float*)d_in[24];
    const float* W_out_l = (const float*)d_in[25];
    const float* b_out_l = (const float*)d_in[26];
    const float* W_out_r = (const float*)d_in[27];
    const float* b_out_r = (const float*)d_in[28];
    float* outp = (float*)d_out;

    float *pfl, *pfr, *px, *pq, *pk, *pv, *pao, *pproj, *px1, *ph, *pf, *px2;
    __half *wfcl, *wfcr, *wq16, *wk16, *wv16, *wo16, *w116, *w216, *pwl, *pwr;
    cudaGetSymbolAddress((void**)&pfl,  g_feat_l);
    cudaGetSymbolAddress((void**)&pfr,  g_feat_r);
    cudaGetSymbolAddress((void**)&px,   g_x);
    cudaGetSymbolAddress((void**)&pq,   g_q);
    cudaGetSymbolAddress((void**)&pk,   g_k);
    cudaGetSymbolAddress((void**)&pv,   g_v);
    cudaGetSymbolAddress((void**)&pao,  g_ao);
    cudaGetSymbolAddress((void**)&pproj,g_proj);
    cudaGetSymbolAddress((void**)&px1,  g_x1);
    cudaGetSymbolAddress((void**)&ph,   g_h);
    cudaGetSymbolAddress((void**)&pf,   g_f);
    cudaGetSymbolAddress((void**)&px2,  g_x2);
    cudaGetSymbolAddress((void**)&wfcl, g_wfc_l16);
    cudaGetSymbolAddress((void**)&wfcr, g_wfc_r16);
    cudaGetSymbolAddress((void**)&wq16, g_wq16);
    cudaGetSymbolAddress((void**)&wk16, g_wk16);
    cudaGetSymbolAddress((void**)&wv16, g_wv16);
    cudaGetSymbolAddress((void**)&wo16, g_wo16);
    cudaGetSymbolAddress((void**)&w116, g_w116);
    cudaGetSymbolAddress((void**)&w216, g_w216);
    cudaGetSymbolAddress((void**)&pwl,  g_woutl16);
    cudaGetSymbolAddress((void**)&pwr,  g_woutr16);

    cudaFuncSetAttribute((const void*)tgemm<0,0,1>, cudaFuncAttributeMaxDynamicSharedMemorySize, TG_SMEM);
    cudaFuncSetAttribute((const void*)tgemm<0,0,3>, cudaFuncAttributeMaxDynamicSharedMemorySize, TG_SMEM);
    cudaFuncSetAttribute((const void*)tgemm<1,0,2>, cudaFuncAttributeMaxDynamicSharedMemorySize, TG_SMEM);
    cudaFuncSetAttribute((const void*)tgemm<2,1,2>, cudaFuncAttributeMaxDynamicSharedMemorySize, TG_SMEM);
    cudaFuncSetAttribute(attention_kernel,
                         cudaFuncAttributeMaxDynamicSharedMemorySize, ATT_SMEM);

    EpiParams none = {nullptr, nullptr, nullptr, 0, 0, 0};

    // 0. weight conversion + head-weight padding
    {
        CvtJobs cj;
        cj.src[0] = W_fc_l; cj.dst[0] = wfcl; cj.n4[0] = (CAT*DD)/4;
        cj.src[1] = W_fc_r; cj.dst[1] = wfcr; cj.n4[1] = (CAT*DD)/4;
        cj.src[2] = Wq;     cj.dst[2] = wq16; cj.n4[2] = (DD*DD)/4;
        cj.src[3] = Wk;     cj.dst[3] = wk16; cj.n4[3] = (DD*DD)/4;
        cj.src[4] = Wv;     cj.dst[4] = wv16; cj.n4[4] = (DD*DD)/4;
        cj.src[5] = Wo;     cj.dst[5] = wo16; cj.n4[5] = (DD*DD)/4;
        cj.src[6] = W1;     cj.dst[6] = w116; cj.n4[6] = (DD*DFF)/4;
        cj.src[7] = W2;     cj.dst[7] = w216; cj.n4[7] = (DFF*DD)/4;
        cvt_weights_kernel<<<1024, 256>>>(cj);
    }
    pad_wout_kernel<<<256, 256>>>(W_out_l, W_out_r, pwl, pwr);

    // 1. features
    build_features_kernel<<<ROWS, 256>>>(x_l, x_r, j_l, j_r, mcon, pc, pfl, pfr);

    // 2. fc projections (merged l+r)
    {
        Jobs<2> jb;
        jb.j[0] = { pfl, wfcl, px,      {b_fc_l, mask_l, pad, 0, 0, 0} };
        jb.j[1] = { pfr, wfcr, px + DD, {b_fc_r, mask_r, pad, 1, 0, 0} };
        tgemm<1,0,2><<<dim3(8,64,2), 128, TG_SMEM>>>(jb, CATP, DD, 2*DD, ROWS, DD, CAT);
    }

    // 3. QKV (merged)
    {
        Jobs<3> jb;
        jb.j[0] = { px, wq16, pq, none };
        jb.j[1] = { px, wk16, pk, none };
        jb.j[2] = { px, wv16, pv, none };
        tgemm<0,0,3><<<dim3(8,128,3), 128, TG_SMEM>>>(jb, DD, DD, DD, TROWS, DD, DD);
    }

    // 4. attention
    attention_kernel<<<BB*HH, 256, ATT_SMEM>>>(pq, pk, pv, pad, pao);

    // 5. Wo + LN1
    {
        Jobs<1> jb; jb.j[0] = { pao, wo16, pproj, none };
        tgemm<0,0,1><<<dim3(8,128,1), 128, TG_SMEM>>>(jb, DD, DD, DD, TROWS, DD, DD);
    }
    ln_kernel<<<TROWS, 128>>>(px, pproj, ln1g, ln1b, px1);

    // 6. FFN + LN2
    {
        Jobs<1> jb; jb.j[0] = { px1, w116, ph, {b1, nullptr, nullptr, 0, 1, 0} };
        tgemm<0,0,1><<<dim3(32,128,1), 128, TG_SMEM>>>(jb, DD, DFF, DFF, TROWS, DFF, DD);
    }
    {
        Jobs<1> jb; jb.j[0] = { ph, w216, pf, {b2, nullptr, nullptr, 0, 0, 0} };
        tgemm<0,0,1><<<dim3(8,128,1), 128, TG_SMEM>>>(jb, DFF, DD, DD, TROWS, DD, DFF);
    }
    ln_kernel<<<TROWS, 128>>>(px1, pf, ln2g, ln2b, px2);

    // 7. output heads (merged l+r, guarded cols)
    {
        Jobs<2> jb;
        jb.j[0] = { px2,      pwl, outp,                 {b_out_l, mask_l, pad, 0, 0, HAND_DIM} };
        jb.j[1] = { px2 + DD, pwr, outp + ROWS*HAND_DIM, {b_out_r, mask_r, pad, 1, 0, HAND_DIM} };
        tgemm<2,1,2><<<dim3(2,64,2), 128, TG_SMEM>>>(jb, 2*DD, 128, HAND_DIM, ROWS, 128, DD);
    }
}

// round 11
// speedup vs baseline: 5.5772x; 1.1882x over previous
#include <cuda_runtime.h>
#include <cuda_fp16.h>
#include <math.h>

// ---------------------------------------------------------------------------
// Shapes
// ---------------------------------------------------------------------------
#define BB 32
#define LL 128
#define NN 512
#define JJ 21
#define HAND_DIM 99
#define DD 512
#define HH 8
#define DHH 64
#define DFF 2048
#define CAT 1249
#define CATP 1280
#define SS 256
#define ROWS 4096
#define TROWS 8192

#define F_X 0
#define F_J 99
#define F_MC 162
#define F_PCN 674
#define F_ATT 1186

// ---------------------------------------------------------------------------
// Scratch
// ---------------------------------------------------------------------------
__device__ float g_feat_l[ROWS * CATP];
__device__ float g_feat_r[ROWS * CATP];
__device__ float g_x [TROWS * DD];
__device__ float g_q [TROWS * DD];
__device__ float g_k [TROWS * DD];
__device__ float g_v [TROWS * DD];
__device__ float g_ao [TROWS * DD];
__device__ float g_proj[TROWS * DD];
__device__ float g_x1 [TROWS * DD];
__device__ float g_h [TROWS * DFF];
__device__ float g_f [TROWS * DD];
__device__ float g_x2 [TROWS * DD];

// fp16 weight copies (converted once per call)
__device__ __align__(16) __half g_wfc_l16[CAT * DD];
__device__ __align__(16) __half g_wfc_r16[CAT * DD];
__device__ __align__(16) __half g_wq16 [DD * DD];
__device__ __align__(16) __half g_wk16 [DD * DD];
__device__ __align__(16) __half g_wv16 [DD * DD];
__device__ __align__(16) __half g_wo16 [DD * DD];
__device__ __align__(16) __half g_w116 [DD * DFF];
__device__ __align__(16) __half g_w216 [DFF * DD];
__device__ __align__(16) __half g_woutl16[DD * 128];
__device__ __align__(16) __half g_woutr16[DD * 128];

// ---------------------------------------------------------------------------
// Weight conversion (fp32 -> fp16)
// ---------------------------------------------------------------------------
struct CvtJobs {
    const float* src[8];
    __half* dst[8];
    int n4[8];
};
__global__ void cvt_weights_kernel(CvtJobs cj)
{
    int gid = blockIdx.x * blockDim.x + threadIdx.x;
    int stride = gridDim.x * blockDim.x;
    #pragma unroll
    for (int j = 0; j < 8; j++) {
        const float4* s = (const float4*)cj.src[j];
        __half2* d = (__half2*)cj.dst[j];
        int n4 = cj.n4[j];
        for (int i = gid; i < n4; i += stride) {
            float4 v = s[i];
            d[2*i]   = __floats2half2_rn(v.x, v.y);
            d[2*i+1] = __floats2half2_rn(v.z, v.w);
        }
    }
}

__global__ void pad_wout_kernel(const float* __restrict__ Wl, const float* __restrict__ Wr,
                                __half* __restrict__ dl, __half* __restrict__ dr)
{
    int idx = blockIdx.x * 256 + threadIdx.x;
    int row = idx >> 7, col = idx & 127;
    float vl = (col < HAND_DIM) ? Wl[row*HAND_DIM + col] : 0.f;
    float vr = (col < HAND_DIM) ? Wr[row*HAND_DIM + col] : 0.f;
    dl[idx] = __float2half_rn(vl);
    dr[idx] = __float2half_rn(vr);
}

// ---------------------------------------------------------------------------
// Feature build
// ---------------------------------------------------------------------------
__global__ void build_features_kernel(
    const float* __restrict__ x_l, const float* __restrict__ x_r,
    const float* __restrict__ j_l, const float* __restrict__ j_r,
    const float* __restrict__ m_contact, const float* __restrict__ pc,
    float* __restrict__ feat_l, float* __restrict__ feat_r)
{
    int m = blockIdx.x;
    int b = m >> 7;
    __shared__ float px[NN], py[NN], pz[NN];
    int tid = threadIdx.x;

    const float* pcb = pc + (size_t)m * NN * 3;
    for (int n = tid; n < NN; n += 256) {
        px[n] = pcb[n*3+0]; py[n] = pcb[n*3+1]; pz[n] = pcb[n*3+2];
    }
    __syncthreads();

    float* fl = feat_l + (size_t)m * CATP;
    float* fr = feat_r + (size_t)m * CATP;

    for (int i = tid; i < HAND_DIM; i += 256) {
        fl[F_X+i] = x_l[(size_t)m*HAND_DIM + i];
        fr[F_X+i] = x_r[(size_t)m*HAND_DIM + i];
    }
    for (int i = tid; i < JJ*3; i += 256) {
        fl[F_J+i] = j_l[(size_t)m*JJ*3 + i];
        fr[F_J+i] = j_r[(size_t)m*JJ*3 + i];
    }
    for (int n = tid; n < NN; n += 256) {
        float mc = m_contact[b*NN + n];
        fl[F_MC+n] = mc; fr[F_MC+n] = mc;
        float nm = sqrtf(px[n]*px[n] + py[n]*py[n] + pz[n]*pz[n]);
        fl[F_PCN+n] = nm; fr[F_PCN+n] = nm;
    }
    for (int i = CAT + tid; i < CATP; i += 256) { fl[i] = 0.f; fr[i] = 0.f; }

    int w = tid >> 5, lane = tid & 31;
    for (int task = w; task < 2*JJ; task += 8) {
        int hand = task / JJ, joint = task % JJ;
        const float* jb = (hand == 0 ? j_l : j_r) + ((size_t)m*JJ + joint)*3;
        float jx = jb[0], jy = jb[1], jz = jb[2];
        float best = 3.402823466e+38f; int bi = 0;
        for (int n = lane; n < NN; n += 32) {
            float dx = jx - px[n], dy = jy - py[n], dz = jz - pz[n];
            float d2 = dx*dx + dy*dy + dz*dz;
            if (d2 < best) { best = d2; bi = n; }
        }
        for (int off = 16; off; off >>= 1) {
            float ob = __shfl_xor_sync(0xffffffffu, best, off);
            int   oi = __shfl_xor_sync(0xffffffffu, bi, off);
            if (ob < best || (ob == best && oi < bi)) { best = ob; bi = oi; }
        }
        if (lane == 0) {
            float dx = jx - px[bi], dy = jy - py[bi], dz = jz - pz[bi];
            float* f = (hand == 0 ? fl : fr);
            f[F_ATT + joint*3 + 0] = expf(-50.f * dx * dx);
            f[F_ATT + joint*3 + 1] = expf(-50.f * dy * dy);
            f[F_ATT + joint*3 + 2] = expf(-50.f * dz * dz);
        }
    }
}

// ---------------------------------------------------------------------------
// Epilogues
// ---------------------------------------------------------------------------
struct EpiParams {
    const float* bias;
    const float* mask;
    const unsigned char* pad;
    int hand;
    int relu;
    int nreal;
};

#define LN10000 9.2103403719761827f

template<int EPI>
__device__ __forceinline__ float apply_epi(float v, int row, int col, const EpiParams& ep)
{
    if (EPI == 0) {
        if (ep.bias) v += ep.bias[col];
        if (ep.relu) v = fmaxf(v, 0.f);
    } else if (EPI == 1) {
        int l = row & 127;
        int ii = col >> 1;
        float freq = expf(-LN10000 * (float)ii * (1.f/256.f));
        float angF = (float)l * freq;
        float angA = (float)ep.hand * freq;
        float pe = (col & 1) ? (cosf(angF) + cosf(angA))
                             : (sinf(angF) + sinf(angA));
        float mv = ep.mask[row] * (ep.pad[2*row + ep.hand] ? 0.f : 1.f);
        v = (v + ep.bias[col] + pe) * mv;
    } else { // EPI == 2
        float mv = ep.mask[row] * (ep.pad[2*row + ep.hand] ? 0.f : 1.f);
        v = (v + ep.bias[col]) * mv;
    }
    return v;
}

// ---------------------------------------------------------------------------
// Multi-job single-pass fp16 tensor-core GEMM. 128 threads, tile 64x64,
// BK=32, 4 warps (2x2, warp tile 32x32). A fp32 converted to fp16 in staging;
// B fp16 pre-converted. One mma pass (A~2^-11, B~2^-11 rounding).
// ---------------------------------------------------------------------------
struct Job { const float* A; const __half* B; float* C; EpiParams ep; };
template<int NJ> struct Jobs { Job j[NJ]; };

#define PA 80                          // A pitch bytes (32 halves + pad; 5 granules)
#define PB 144                         // B pitch bytes (64 halves + pad; 9 granules)
#define A_BYTES (64*PA)                // 5120
#define B_BYTES (32*PB)                // 4608
#define OFF_AH 0
#define OFF_BH (A_BYTES)
#define BUF_BYTES (A_BYTES + B_BYTES)     // 9728
#define TG_SMEM (2*BUF_BYTES)             // 19456

__device__ __forceinline__ unsigned smem_u32(const void* p) {
    return (unsigned)__cvta_generic_to_shared(p);
}
__device__ __forceinline__ void ldsm4(unsigned* r, unsigned addr) {
    asm volatile("ldmatrix.sync.aligned.m8n8.x4.shared.b16 {%0,%1,%2,%3}, [%4];"
        : "=r"(r[0]), "=r"(r[1]), "=r"(r[2]), "=r"(r[3]) : "r"(addr));
}
__device__ __forceinline__ void ldsm4t(unsigned* r, unsigned addr) {
    asm volatile("ldmatrix.sync.aligned.m8n8.x4.trans.shared.b16 {%0,%1,%2,%3}, [%4];"
        : "=r"(r[0]), "=r"(r[1]), "=r"(r[2]), "=r"(r[3]) : "r"(addr));
}
__device__ __forceinline__ void mma16816(float* c, const unsigned* a, unsigned b0, unsigned b1) {
    asm volatile(
        "mma.sync.aligned.m16n8k16.row.col.f32.f16.f16.f32 "
        "{%0,%1,%2,%3}, {%4,%5,%6,%7}, {%8,%9}, {%0,%1,%2,%3};"
        : "+f"(c[0]), "+f"(c[1]), "+f"(c[2]), "+f"(c[3])
        : "r"(a[0]), "r"(a[1]), "r"(a[2]), "r"(a[3]), "r"(b0), "r"(b1));
}
// 4 floats -> packed fp16 x4
__device__ __forceinline__ uint2 cvt4h(const float4& v) {
    uint2 r;
    __half2 h0 = __floats2half2_rn(v.x, v.y);
    __half2 h1 = __floats2half2_rn(v.z, v.w);
    r.x = *(unsigned*)&h0;
    r.y = *(unsigned*)&h1;
    return r;
}

template<int EPI, int GUARD, int NJ>
__global__ __launch_bounds__(128, 4)
void tgemm(Jobs<NJ> jobs, int lda, int ldb, int ldc, int M, int N, int Kreal)
{
    const Job& jb = jobs.j[blockIdx.z];
    const float* __restrict__ A = jb.A;
    const __half* __restrict__ B = jb.B;
    float* __restrict__ C = jb.C;
    EpiParams ep = jb.ep;

    extern __shared__ unsigned char smraw[];
    unsigned sbase = smem_u32(smraw);
    int tid = threadIdx.x, lane = tid & 31, wid = tid >> 5;
    int warp_m = wid & 1, warp_n = wid >> 1;
    int m0 = blockIdx.y * 64, n0 = blockIdx.x * 64;
    int g = lane >> 2, t = lane & 3;

    float acc[2][4][4];
    #pragma unroll
    for (int i = 0; i < 2; i++)
        #pragma unroll
        for (int j = 0; j < 4; j++)
            #pragma unroll
            for (int e = 0; e < 4; e++) acc[i][j][e] = 0.f;

    // staging coords: A tile 64x32 fp32 (4 float4/thread), B 32x64 fp16 (2 uint4/thread)
    int ar[4], ak[4];
    #pragma unroll
    for (int i = 0; i < 4; i++) {
        int f = tid + 128*i;
        ar[i] = f >> 3;  ak[i] = (f & 7) * 4;
    }
    int br[2], bn[2];
    #pragma unroll
    for (int i = 0; i < 2; i++) {
        int f = tid + 128*i;
        br[i] = f >> 3;  bn[i] = (f & 7) * 8;
    }

    int aRow = lane & 15;
    int aKof = ((lane >> 4) & 1) * 8;
    int bRow = lane & 15;
    int bNof = ((lane >> 4) & 1) * 8;

    int nk = (Kreal + 31) >> 5;
    float4 ra[4];
    uint4 rbh[2];

    auto load_g = [&](int kt) {
        int k0 = kt * 32;
        #pragma unroll
        for (int i = 0; i < 4; i++)
            ra[i] = *(const float4*)(A + (size_t)(m0 + ar[i])*lda + k0 + ak[i]);
        #pragma unroll
        for (int i = 0; i < 2; i++) {
            int k = k0 + br[i];
            rbh[i] = (k < Kreal) ? *(const uint4*)(B + (size_t)k*ldb + n0 + bn[i])
                                 : make_uint4(0u, 0u, 0u, 0u);
        }
    };
    auto cvt_store = [&](int buf) {
        unsigned char* bp = smraw + buf * BUF_BYTES;
        #pragma unroll
        for (int i = 0; i < 4; i++) {
            uint2 hp = cvt4h(ra[i]);
            *(uint2*)(bp + OFF_AH + ar[i]*PA + ak[i]*2) = hp;
        }
        #pragma unroll
        for (int i = 0; i < 2; i++)
            *(uint4*)(bp + OFF_BH + br[i]*PB + bn[i]*2) = rbh[i];
    };

    load_g(0);
    cvt_store(0);
    __syncthreads();

    for (int kt = 0; kt < nk; kt++) {
        if (kt + 1 < nk) load_g(kt + 1);

        unsigned base = sbase + (kt & 1) * BUF_BYTES;
        #pragma unroll
        for (int ks = 0; ks < 2; ks++) {
            unsigned aAddrBase = base + (ks*16 + aKof) * 2;
            unsigned bAddrBase = base + (ks*16 + bRow) * PB;

            unsigned ah[2][4], bh[2][4];
            #pragma unroll
            for (int mt = 0; mt < 2; mt++)
                ldsm4(ah[mt], aAddrBase + OFF_AH + (warp_m*32 + mt*16 + aRow)*PA);
            #pragma unroll
            for (int np = 0; np < 2; np++)
                ldsm4t(bh[np], bAddrBase + OFF_BH + (warp_n*32 + np*16 + bNof)*2);

            #pragma unroll
            for (int mt = 0; mt < 2; mt++)
                #pragma unroll
                for (int nt = 0; nt < 4; nt++)
                    mma16816(acc[mt][nt], ah[mt], bh[nt>>1][(nt&1)*2], bh[nt>>1][(nt&1)*2+1]);
        }

        if (kt + 1 < nk) cvt_store((kt + 1) & 1);
        __syncthreads();
    }

    #pragma unroll
    for (int mt = 0; mt < 2; mt++) {
        int row0 = m0 + warp_m*32 + mt*16 + g;
        #pragma unroll
        for (int nt = 0; nt < 4; nt++) {
            int col = n0 + warp_n*32 + nt*8 + t*2;
            float* c = acc[mt][nt];
            if (GUARD) {
                if (col < ep.nreal)
                    C[(size_t)row0*ldc + col] = apply_epi<EPI>(c[0], row0, col, ep);
                if (col + 1 < ep.nreal)
                    C[(size_t)row0*ldc + col + 1] = apply_epi<EPI>(c[1], row0, col + 1, ep);
                if (col < ep.nreal)
                    C[(size_t)(row0+8)*ldc + col] = apply_epi<EPI>(c[2], row0 + 8, col, ep);
                if (col + 1 < ep.nreal)
                    C[(size_t)(row0+8)*ldc + col + 1] = apply_epi<EPI>(c[3], row0 + 8, col + 1, ep);
            } else {
                float v0 = apply_epi<EPI>(c[0], row0,     col,     ep);
                float v1 = apply_epi<EPI>(c[1], row0,     col + 1, ep);
                float v2 = apply_epi<EPI>(c[2], row0 + 8, col,     ep);
                float v3 = apply_epi<EPI>(c[3], row0 + 8, col + 1, ep);
                *(float2*)(C + (size_t)row0*ldc + col)       = make_float2(v0, v1);
                *(float2*)(C + (size_t)(row0 + 8)*ldc + col) = make_float2(v2, v3);
            }
        }
    }
}

// ---------------------------------------------------------------------------
// Fused attention: fp16 K (pitch 72) + fp16 V^T (pitch 258), 2 q-rows/warp,
// 2 CTAs/SM.
// ---------------------------------------------------------------------------
#define KP 72
#define VTP 258
#define ATT_K_OFF 0
#define ATT_VT_OFF 36864
#define ATT_PS_OFF 69888
#define ATT_QS_OFF 86272
#define ATT_BS_OFF 90368
#define ATT_SMEM 91392

__global__ __launch_bounds__(256, 2)
void attention_kernel(const float* __restrict__ qb,
                      const float* __restrict__ kb,
                      const float* __restrict__ vb,
                      const unsigned char* __restrict__ pad,
                      float* __restrict__ ob)
{
    int bh = blockIdx.x;
    int b = bh >> 3, h = bh & 7;
    extern __shared__ unsigned char smb[];
    __half* Ks = (__half*)(smb + ATT_K_OFF);
    __half* Vt = (__half*)(smb + ATT_VT_OFF);
    float* Ps  = (float*)(smb + ATT_PS_OFF);
    float* Qs  = (float*)(smb + ATT_QS_OFF);
    float* Bsb = (float*)(smb + ATT_BS_OFF);

    int tid = threadIdx.x, lane = tid & 31, w = tid >> 5;
    const float* kbase = kb + (size_t)(b*SS)*DD + h*DHH;
    const float* vbase = vb + (size_t)(b*SS)*DD + h*DHH;

    for (int idx = tid; idx < 256*64; idx += 256) {
        int r = idx >> 6, c = idx & 63;
        Ks[r*KP + c] = __float2half_rn(kbase[(size_t)r*DD + c]);
        Vt[c*VTP + r] = __float2half_rn(vbase[(size_t)r*DD + c]);
    }
    if (tid < 256) Bsb[tid] = pad[b*SS + tid] ? -1e9f : 0.f;
    __syncthreads();

    float* Pw0 = Ps + (2*w + 0)*256;
    float* Pw1 = Ps + (2*w + 1)*256;
    float* Qw = Qs + w*128;

    for (int qi = 2*w; qi < SS; qi += 16) {
        const float* q0 = qb + (size_t)(b*SS + qi)*DD + h*DHH;
        Qw[lane]           = q0[lane];
        Qw[lane + 32]      = q0[lane + 32];
        Qw[64 + lane]      = q0[DD + lane];
        Qw[64 + lane + 32] = q0[DD + lane + 32];
        __syncwarp();

        const float4* q4a = (const float4*)Qw;
        const float4* q4b = (const float4*)(Qw + 64);

        float s0[8], s1[8];
        float mx0 = -3.402823466e+38f, mx1 = -3.402823466e+38f;
        #pragma unroll
        for (int k8 = 0; k8 < 8; k8++) {
            int j = lane + 32*k8;
            const uint4* kr4 = (const uint4*)(Ks + j*KP);
            float a0 = 0.f, a1 = 0.f;
            #pragma unroll
            for (int d8 = 0; d8 < 8; d8++) {
                uint4 kv = kr4[d8];
                float2 f0 = __half22float2(*(__half2*)&kv.x);
                float2 f1 = __half22float2(*(__half2*)&kv.y);
                float2 f2 = __half22float2(*(__half2*)&kv.z);
                float2 f3 = __half22float2(*(__half2*)&kv.w);
                float4 qa0 = q4a[d8*2],   qa1 = q4a[d8*2+1];
                float4 qb0 = q4b[d8*2],   qb1 = q4b[d8*2+1];
                a0 += qa0.x*f0.x + qa0.y*f0.y + qa0.z*f1.x + qa0.w*f1.y
                    + qa1.x*f2.x + qa1.y*f2.y + qa1.z*f3.x + qa1.w*f3.y;
                a1 += qb0.x*f0.x + qb0.y*f0.y + qb0.z*f1.x + qb0.w*f1.y
                    + qb1.x*f2.x + qb1.y*f2.y + qb1.z*f3.x + qb1.w*f3.y;
            }
            float bias = Bsb[j];
            a0 = a0 * 0.125f + bias;
            a1 = a1 * 0.125f + bias;
            s0[k8] = a0; s1[k8] = a1;
            mx0 = fmaxf(mx0, a0); mx1 = fmaxf(mx1, a1);
        }
        for (int off = 16; off; off >>= 1) {
            mx0 = fmaxf(mx0, __shfl_xor_sync(0xffffffffu, mx0, off));
            mx1 = fmaxf(mx1, __shfl_xor_sync(0xffffffffu, mx1, off));
        }
        float sm0 = 0.f, sm1 = 0.f;
        #pragma unroll
        for (int k8 = 0; k8 < 8; k8++) {
            s0[k8] = __expf(s0[k8] - mx0); sm0 += s0[k8];
            s1[k8] = __expf(s1[k8] - mx1); sm1 += s1[k8];
        }
        for (int off = 16; off; off >>= 1) {
            sm0 += __shfl_xor_sync(0xffffffffu, sm0, off);
            sm1 += __shfl_xor_sync(0xffffffffu, sm1, off);
        }
        float i0 = 1.f / sm0, i1 = 1.f / sm1;
        #pragma unroll
        for (int k8 = 0; k8 < 8; k8++) {
            Pw0[lane + 32*k8] = s0[k8]*i0;
            Pw1[lane + 32*k8] = s1[k8]*i1;
        }
        __syncwarp();

        const __half2* vtA = (const __half2*)(Vt + (size_t)lane*VTP);
        const __half2* vtB = (const __half2*)(Vt + (size_t)(lane+32)*VTP);
        const float2* P02 = (const float2*)Pw0;
        const float2* P12 = (const float2*)Pw1;
        float o00 = 0.f, o01 = 0.f, o10 = 0.f, o11 = 0.f;
        for (int j2 = 0; j2 < 128; j2++) {
            float2 p0 = P02[j2];
            float2 p1 = P12[j2];
            float2 vA = __half22float2(vtA[j2]);
            float2 vB = __half22float2(vtB[j2]);
            o00 += p0.x*vA.x + p0.y*vA.y;
            o01 += p0.x*vB.x + p0.y*vB.y;
            o10 += p1.x*vA.x + p1.y*vA.y;
            o11 += p1.x*vB.x + p1.y*vB.y;
        }
        float* orow = ob + (size_t)(b*SS + qi)*DD + h*DHH;
        orow[lane]           = o00;
        orow[lane + 32]      = o01;
        orow[DD + lane]      = o10;
        orow[DD + lane + 32] = o11;
        __syncwarp();
    }
}

// ---------------------------------------------------------------------------
// Residual add + LayerNorm
// ---------------------------------------------------------------------------
__global__ void ln_kernel(const float* __restrict__ x, const float* __restrict__ add,
                          const float* __restrict__ g, const float* __restrict__ bv,
                          float* __restrict__ out)
{
    int t = blockIdx.x;
    int tid = threadIdx.x;
    const float* xr = x   + (size_t)t*DD;
    const float* ar = add + (size_t)t*DD;
    float v[4];
    float s = 0.f, ss = 0.f;
    #pragma unroll
    for (int i = 0; i < 4; i++) {
        float u = xr[tid + 128*i] + ar[tid + 128*i];
        v[i] = u; s += u; ss += u*u;
    }
    for (int off = 16; off; off >>= 1) {
        s  += __shfl_xor_sync(0xffffffffu, s,  off);
        ss += __shfl_xor_sync(0xffffffffu, ss, off);
    }
    __shared__ float rs[4], rss[4];
    int w = tid >> 5, lane = tid & 31;
    if (lane == 0) { rs[w] = s; rss[w] = ss; }
    __syncthreads();
    s  = rs[0]+rs[1]+rs[2]+rs[3];
    ss = rss[0]+rss[1]+rss[2]+rss[3];
    float mean = s * (1.f/512.f);
    float var  = ss * (1.f/512.f) - mean*mean;
    float rstd = rsqrtf(var + 1e-5f);
    #pragma unroll
    for (int i = 0; i < 4; i++) {
        int c = tid + 128*i;
        out[(size_t)t*DD + c] = (v[i]-mean)*rstd*g[c] + bv[c];
    }
}

// ---------------------------------------------------------------------------
// Launch
// ---------------------------------------------------------------------------
extern "C" void kernel_launch(void* const* d_in, const int* in_sizes, int n_in,
                              void* d_out, int out_size)
{
    const float* x_l  = (const float*)d_in[0];
    const float* x_r  = (const float*)d_in[1];
    const float* j_l  = (const float*)d_in[2];
    const float* j_r  = (const float*)d_in[3];
    const float* mcon = (const float*)d_in[4];
    const float* pc   = (const float*)d_in[5];
    const float* mask_l = (const float*)d_in[6];
    const float* mask_r = (const float*)d_in[7];
    const unsigned char* pad = (const unsigned char*)d_in[8];
    const float* W_fc_l = (const float*)d_in[9];
    const float* b_fc_l = (const float*)d_in[10];
    const float* W_fc_r = (const float*)d_in[11];
    const float* b_fc_r = (const float*)d_in[12];
    const float* Wq = (const float*)d_in[13];
    const float* Wk = (const float*)d_in[14];
    const float* Wv = (const float*)d_in[15];
    const float* Wo = (const float*)d_in[16];
    const float* W1 = (const float*)d_in[17];
    const float* b1 = (const float*)d_in[18];
    const float* W2 = (const float*)d_in[19];
    const float* b2 = (const float*)d_in[20];
    const float* ln1g = (const float*)d_in[21];
    const float* ln1b = (const float*)d_in[22];
    const float* ln2g = (const float*)d_in[23];
    const float* ln2b = (const float*)d_in[24];
    const float* W_out_l = (const float*)d_in[25];
    const float* b_out_l = (const float*)d_in[26];
    const float* W_out_r = (const float*)d_in[27];
    const float* b_out_r = (const float*)d_in[28];
    float* outp = (float*)d_out;

    float *pfl, *pfr, *px, *pq, *pk, *pv, *pao, *pproj, *px1, *ph, *pf, *px2;
    __half *wfcl, *wfcr, *wq16, *wk16, *wv16, *wo16, *w116, *w216, *pwl, *pwr;
    cudaGetSymbolAddress((void**)&pfl,  g_feat_l);
    cudaGetSymbolAddress((void**)&pfr,  g_feat_r);
    cudaGetSymbolAddress((void**)&px,   g_x);
    cudaGetSymbolAddress((void**)&pq,   g_q);
    cudaGetSymbolAddress((void**)&pk,   g_k);
    cudaGetSymbolAddress((void**)&pv,   g_v);
    cudaGetSymbolAddress((void**)&pao,  g_ao);
    cudaGetSymbolAddress((void**)&pproj,g_proj);
    cudaGetSymbolAddress((void**)&px1,  g_x1);
    cudaGetSymbolAddress((void**)&ph,   g_h);
    cudaGetSymbolAddress((void**)&pf,   g_f);
    cudaGetSymbolAddress((void**)&px2,  g_x2);
    cudaGetSymbolAddress((void**)&wfcl, g_wfc_l16);
    cudaGetSymbolAddress((void**)&wfcr, g_wfc_r16);
    cudaGetSymbolAddress((void**)&wq16, g_wq16);
    cudaGetSymbolAddress((void**)&wk16, g_wk16);
    cudaGetSymbolAddress((void**)&wv16, g_wv16);
    cudaGetSymbolAddress((void**)&wo16, g_wo16);
    cudaGetSymbolAddress((void**)&w116, g_w116);
    cudaGetSymbolAddress((void**)&w216, g_w216);
    cudaGetSymbolAddress((void**)&pwl,  g_woutl16);
    cudaGetSymbolAddress((void**)&pwr,  g_woutr16);

    cudaFuncSetAttribute((const void*)tgemm<0,0,1>, cudaFuncAttributeMaxDynamicSharedMemorySize, TG_SMEM);
    cudaFuncSetAttribute((const void*)tgemm<0,0,3>, cudaFuncAttributeMaxDynamicSharedMemorySize, TG_SMEM);
    cudaFuncSetAttribute((const void*)tgemm<1,0,2>, cudaFuncAttributeMaxDynamicSharedMemorySize, TG_SMEM);
    cudaFuncSetAttribute((const void*)tgemm<2,1,2>, cudaFuncAttributeMaxDynamicSharedMemorySize, TG_SMEM);
    cudaFuncSetAttribute(attention_kernel,
                         cudaFuncAttributeMaxDynamicSharedMemorySize, ATT_SMEM);

    EpiParams none = {nullptr, nullptr, nullptr, 0, 0, 0};

    // 0. weight conversion + head-weight padding
    {
        CvtJobs cj;
        cj.src[0] = W_fc_l; cj.dst[0] = wfcl; cj.n4[0] = (CAT*DD)/4;
        cj.src[1] = W_fc_r; cj.dst[1] = wfcr; cj.n4[1] = (CAT*DD)/4;
        cj.src[2] = Wq;     cj.dst[2] = wq16; cj.n4[2] = (DD*DD)/4;
        cj.src[3] = Wk;     cj.dst[3] = wk16; cj.n4[3] = (DD*DD)/4;
        cj.src[4] = Wv;     cj.dst[4] = wv16; cj.n4[4] = (DD*DD)/4;
        cj.src[5] = Wo;     cj.dst[5] = wo16; cj.n4[5] = (DD*DD)/4;
        cj.src[6] = W1;     cj.dst[6] = w116; cj.n4[6] = (DD*DFF)/4;
        cj.src[7] = W2;     cj.dst[7] = w216; cj.n4[7] = (DFF*DD)/4;
        cvt_weights_kernel<<<1024, 256>>>(cj);
    }
    pad_wout_kernel<<<256, 256>>>(W_out_l, W_out_r, pwl, pwr);

    // 1. features
    build_features_kernel<<<ROWS, 256>>>(x_l, x_r, j_l, j_r, mcon, pc, pfl, pfr);

    // 2. fc projections (merged l+r)
    {
        Jobs<2> jb;
        jb.j[0] = { pfl, wfcl, px,      {b_fc_l, mask_l, pad, 0, 0, 0} };
        jb.j[1] = { pfr, wfcr, px + DD, {b_fc_r, mask_r, pad, 1, 0, 0} };
        tgemm<1,0,2><<<dim3(8,64,2), 128, TG_SMEM>>>(jb, CATP, DD, 2*DD, ROWS, DD, CAT);
    }

    // 3. QKV (merged)
    {
        Jobs<3> jb;
        jb.j[0] = { px, wq16, pq, none };
        jb.j[1] = { px, wk16, pk, none };
        jb.j[2] = { px, wv16, pv, none };
        tgemm<0,0,3><<<dim3(8,128,3), 128, TG_SMEM>>>(jb, DD, DD, DD, TROWS, DD, DD);
    }

    // 4. attention
    attention_kernel<<<BB*HH, 256, ATT_SMEM>>>(pq, pk, pv, pad, pao);

    // 5. Wo + LN1
    {
        Jobs<1> jb; jb.j[0] = { pao, wo16, pproj, none };
        tgemm<0,0,1><<<dim3(8,128,1), 128, TG_SMEM>>>(jb, DD, DD, DD, TROWS, DD, DD);
    }
    ln_kernel<<<TROWS, 128>>>(px, pproj, ln1g, ln1b, px1);

    // 6. FFN + LN2
    {
        Jobs<1> jb; jb.j[0] = { px1, w116, ph, {b1, nullptr, nullptr, 0, 1, 0} };
        tgemm<0,0,1><<<dim3(32,128,1), 128, TG_SMEM>>>(jb, DD, DFF, DFF, TROWS, DFF, DD);
    }
    {
        Jobs<1> jb; jb.j[0] = { ph, w216, pf, {b2, nullptr, nullptr, 0, 0, 0} };
        tgemm<0,0,1><<<dim3(8,128,1), 128, TG_SMEM>>>(jb, DFF, DD, DD, TROWS, DD, DFF);
    }
    ln_kernel<<<TROWS, 128>>>(px1, pf, ln2g, ln2b, px2);

    // 7. output heads (merged l+r, guarded cols)
    {
        Jobs<2> jb;
        jb.j[0] = { px2,      pwl, outp,                 {b_out_l, mask_l, pad, 0, 0, HAND_DIM} };
        jb.j[1] = { px2 + DD, pwr, outp + ROWS*HAND_DIM, {b_out_r, mask_r, pad, 1, 0, HAND_DIM} };
        tgemm<2,1,2><<<dim3(2,64,2), 128, TG_SMEM>>>(jb, 2*DD, 128, HAND_DIM, ROWS, 128, DD);
    }
}

// round 12
// speedup vs baseline: 6.5266x; 1.1702x over previous
#include <cuda_runtime.h>
#include <cuda_fp16.h>
#include <math.h>

// ---------------------------------------------------------------------------
// Shapes
// ---------------------------------------------------------------------------
#define BB 32
#define LL 128
#define NN 512
#define JJ 21
#define HAND_DIM 99
#define DD 512
#define HH 8
#define DHH 64
#define DFF 2048
#define CAT 1249
#define CATP 1280
#define SS 256
#define ROWS 4096
#define TROWS 8192

#define F_X 0
#define F_J 99
#define F_MC 162
#define F_PCN 674
#define F_ATT 1186

// ---------------------------------------------------------------------------
// Scratch: fp32 kept only where consumed by non-GEMM ops
// ---------------------------------------------------------------------------
__device__ float g_x   [TROWS * DD];   // LN1 residual
__device__ float g_q   [TROWS * DD];   // attention Q
__device__ float g_proj[TROWS * DD];   // LN1 input
__device__ float g_x1  [TROWS * DD];   // LN2 residual
__device__ float g_f   [TROWS * DD];   // LN2 input

// fp16 activation buffers (GEMM A inputs)
__device__ __align__(16) __half g_feat16_l[ROWS * CATP];
__device__ __align__(16) __half g_feat16_r[ROWS * CATP];
__device__ __align__(16) __half g_x16  [TROWS * DD];   // interleaved, QKV A
__device__ __align__(16) __half g_k16  [TROWS * DD];
__device__ __align__(16) __half g_v16  [TROWS * DD];
__device__ __align__(16) __half g_ao16 [TROWS * DD];
__device__ __align__(16) __half g_x116 [TROWS * DD];
__device__ __align__(16) __half g_h16  [TROWS * DFF];
__device__ __align__(16) __half g_x216 [TROWS * DD];

// fp16 weights
__device__ __align__(16) __half g_wfc_l16[CAT * DD];
__device__ __align__(16) __half g_wfc_r16[CAT * DD];
__device__ __align__(16) __half g_wq16 [DD * DD];
__device__ __align__(16) __half g_wk16 [DD * DD];
__device__ __align__(16) __half g_wv16 [DD * DD];
__device__ __align__(16) __half g_wo16 [DD * DD];
__device__ __align__(16) __half g_w116 [DD * DFF];
__device__ __align__(16) __half g_w216 [DFF * DD];
__device__ __align__(16) __half g_woutl16[DD * 128];
__device__ __align__(16) __half g_woutr16[DD * 128];

// ---------------------------------------------------------------------------
// Weight conversion
// ---------------------------------------------------------------------------
struct CvtJobs {
    const float* src[8];
    __half* dst[8];
    int n4[8];
};
__global__ void cvt_weights_kernel(CvtJobs cj)
{
    int gid = blockIdx.x * blockDim.x + threadIdx.x;
    int stride = gridDim.x * blockDim.x;
    #pragma unroll
    for (int j = 0; j < 8; j++) {
        const float4* s = (const float4*)cj.src[j];
        __half2* d = (__half2*)cj.dst[j];
        int n4 = cj.n4[j];
        for (int i = gid; i < n4; i += stride) {
            float4 v = s[i];
            d[2*i]   = __floats2half2_rn(v.x, v.y);
            d[2*i+1] = __floats2half2_rn(v.z, v.w);
        }
    }
}

__global__ void pad_wout_kernel(const float* __restrict__ Wl, const float* __restrict__ Wr,
                                __half* __restrict__ dl, __half* __restrict__ dr)
{
    int idx = blockIdx.x * 256 + threadIdx.x;
    int row = idx >> 7, col = idx & 127;
    float vl = (col < HAND_DIM) ? Wl[row*HAND_DIM + col] : 0.f;
    float vr = (col < HAND_DIM) ? Wr[row*HAND_DIM + col] : 0.f;
    dl[idx] = __float2half_rn(vl);
    dr[idx] = __float2half_rn(vr);
}

// ---------------------------------------------------------------------------
// Feature build -> fp16 feature rows
// ---------------------------------------------------------------------------
__global__ void build_features_kernel(
    const float* __restrict__ x_l, const float* __restrict__ x_r,
    const float* __restrict__ j_l, const float* __restrict__ j_r,
    const float* __restrict__ m_contact, const float* __restrict__ pc,
    __half* __restrict__ feat_l, __half* __restrict__ feat_r)
{
    int m = blockIdx.x;
    int b = m >> 7;
    __shared__ float px[NN], py[NN], pz[NN];
    int tid = threadIdx.x;

    const float* pcb = pc + (size_t)m * NN * 3;
    for (int n = tid; n < NN; n += 256) {
        px[n] = pcb[n*3+0]; py[n] = pcb[n*3+1]; pz[n] = pcb[n*3+2];
    }
    __syncthreads();

    __half* fl = feat_l + (size_t)m * CATP;
    __half* fr = feat_r + (size_t)m * CATP;

    for (int i = tid; i < HAND_DIM; i += 256) {
        fl[F_X+i] = __float2half_rn(x_l[(size_t)m*HAND_DIM + i]);
        fr[F_X+i] = __float2half_rn(x_r[(size_t)m*HAND_DIM + i]);
    }
    for (int i = tid; i < JJ*3; i += 256) {
        fl[F_J+i] = __float2half_rn(j_l[(size_t)m*JJ*3 + i]);
        fr[F_J+i] = __float2half_rn(j_r[(size_t)m*JJ*3 + i]);
    }
    for (int n = tid; n < NN; n += 256) {
        __half mc = __float2half_rn(m_contact[b*NN + n]);
        fl[F_MC+n] = mc; fr[F_MC+n] = mc;
        __half nm = __float2half_rn(sqrtf(px[n]*px[n] + py[n]*py[n] + pz[n]*pz[n]));
        fl[F_PCN+n] = nm; fr[F_PCN+n] = nm;
    }
    __half z = __float2half_rn(0.f);
    for (int i = CAT + tid; i < CATP; i += 256) { fl[i] = z; fr[i] = z; }

    int w = tid >> 5, lane = tid & 31;
    for (int task = w; task < 2*JJ; task += 8) {
        int hand = task / JJ, joint = task % JJ;
        const float* jb = (hand == 0 ? j_l : j_r) + ((size_t)m*JJ + joint)*3;
        float jx = jb[0], jy = jb[1], jz = jb[2];
        float best = 3.402823466e+38f; int bi = 0;
        for (int n = lane; n < NN; n += 32) {
            float dx = jx - px[n], dy = jy - py[n], dz = jz - pz[n];
            float d2 = dx*dx + dy*dy + dz*dz;
            if (d2 < best) { best = d2; bi = n; }
        }
        for (int off = 16; off; off >>= 1) {
            float ob = __shfl_xor_sync(0xffffffffu, best, off);
            int   oi = __shfl_xor_sync(0xffffffffu, bi, off);
            if (ob < best || (ob == best && oi < bi)) { best = ob; bi = oi; }
        }
        if (lane == 0) {
            float dx = jx - px[bi], dy = jy - py[bi], dz = jz - pz[bi];
            __half* f = (hand == 0 ? fl : fr);
            f[F_ATT + joint*3 + 0] = __float2half_rn(expf(-50.f * dx * dx));
            f[F_ATT + joint*3 + 1] = __float2half_rn(expf(-50.f * dy * dy));
            f[F_ATT + joint*3 + 2] = __float2half_rn(expf(-50.f * dz * dz));
        }
    }
}

// ---------------------------------------------------------------------------
// Epilogues
// ---------------------------------------------------------------------------
struct EpiParams {
    const float* bias;
    const float* mask;
    const unsigned char* pad;
    int hand;
    int relu;
    int nreal;
};

#define LN10000 9.2103403719761827f

template<int EPI>
__device__ __forceinline__ float apply_epi(float v, int row, int col, const EpiParams& ep)
{
    if (EPI == 0) {
        if (ep.bias) v += ep.bias[col];
        if (ep.relu) v = fmaxf(v, 0.f);
    } else if (EPI == 1) {
        int l = row & 127;
        int ii = col >> 1;
        float freq = expf(-LN10000 * (float)ii * (1.f/256.f));
        float angF = (float)l * freq;
        float angA = (float)ep.hand * freq;
        float pe = (col & 1) ? (cosf(angF) + cosf(angA))
                             : (sinf(angF) + sinf(angA));
        float mv = ep.mask[row] * (ep.pad[2*row + ep.hand] ? 0.f : 1.f);
        v = (v + ep.bias[col] + pe) * mv;
    } else { // EPI == 2
        float mv = ep.mask[row] * (ep.pad[2*row + ep.hand] ? 0.f : 1.f);
        v = (v + ep.bias[col]) * mv;
    }
    return v;
}

// ---------------------------------------------------------------------------
// Multi-job single-pass fp16 GEMM, cp.async staging.
// 128 threads, tile 64x64, BK=32, 4 warps (2x2, warp tile 32x32), 6 CTAs/SM.
// A fp16 [M][Kpad] (lda halves, rows 16B-aligned, zero-padded K);
// B fp16 [K][N] (ldb halves). C fp32 and/or C16 fp16 outputs.
// ---------------------------------------------------------------------------
struct Job { const __half* A; const __half* B; float* C; __half* C16; EpiParams ep; };
template<int NJ> struct Jobs { Job j[NJ]; };

#define PA 80                          // A pitch bytes (32 halves + pad)
#define PB 144                         // B pitch bytes (64 halves + pad)
#define A_BYTES (64*PA)                // 5120
#define B_BYTES (32*PB)                // 4608
#define OFF_AH 0
#define OFF_BH (A_BYTES)
#define BUF_BYTES (A_BYTES + B_BYTES)     // 9728
#define TG_SMEM (2*BUF_BYTES)             // 19456

__device__ __forceinline__ unsigned smem_u32(const void* p) {
    return (unsigned)__cvta_generic_to_shared(p);
}
__device__ __forceinline__ void ldsm4(unsigned* r, unsigned addr) {
    asm volatile("ldmatrix.sync.aligned.m8n8.x4.shared.b16 {%0,%1,%2,%3}, [%4];"
        : "=r"(r[0]), "=r"(r[1]), "=r"(r[2]), "=r"(r[3]) : "r"(addr));
}
__device__ __forceinline__ void ldsm4t(unsigned* r, unsigned addr) {
    asm volatile("ldmatrix.sync.aligned.m8n8.x4.trans.shared.b16 {%0,%1,%2,%3}, [%4];"
        : "=r"(r[0]), "=r"(r[1]), "=r"(r[2]), "=r"(r[3]) : "r"(addr));
}
__device__ __forceinline__ void mma16816(float* c, const unsigned* a, unsigned b0, unsigned b1) {
    asm volatile(
        "mma.sync.aligned.m16n8k16.row.col.f32.f16.f16.f32 "
        "{%0,%1,%2,%3}, {%4,%5,%6,%7}, {%8,%9}, {%0,%1,%2,%3};"
        : "+f"(c[0]), "+f"(c[1]), "+f"(c[2]), "+f"(c[3])
        : "r"(a[0]), "r"(a[1]), "r"(a[2]), "r"(a[3]), "r"(b0), "r"(b1));
}
__device__ __forceinline__ void cp16(unsigned dst, const void* src, bool full) {
    int sz = full ? 16 : 0;
    asm volatile("cp.async.cg.shared.global [%0], [%1], 16, %2;"
                 :: "r"(dst), "l"(src), "r"(sz) : "memory");
}
__device__ __forceinline__ void cp_commit() {
    asm volatile("cp.async.commit_group;" ::: "memory");
}
template<int N> __device__ __forceinline__ void cp_wait() {
    asm volatile("cp.async.wait_group %0;" :: "n"(N) : "memory");
}

template<int EPI, int GUARD, int NJ>
__global__ __launch_bounds__(128, 6)
void tgemm(Jobs<NJ> jobs, int lda, int ldb, int ldc, int M, int N, int Kreal)
{
    const Job& jb = jobs.j[blockIdx.z];
    const __half* __restrict__ A = jb.A;
    const __half* __restrict__ B = jb.B;
    float* __restrict__ C = jb.C;
    __half* __restrict__ C16 = jb.C16;
    EpiParams ep = jb.ep;

    extern __shared__ unsigned char smraw[];
    unsigned sbase = smem_u32(smraw);
    int tid = threadIdx.x, lane = tid & 31, wid = tid >> 5;
    int warp_m = wid & 1, warp_n = wid >> 1;
    int m0 = blockIdx.y * 64, n0 = blockIdx.x * 64;
    int g = lane >> 2, t = lane & 3;

    float acc[2][4][4];
    #pragma unroll
    for (int i = 0; i < 2; i++)
        #pragma unroll
        for (int j = 0; j < 4; j++)
            #pragma unroll
            for (int e = 0; e < 4; e++) acc[i][j][e] = 0.f;

    int aRow = lane & 15;
    int aKof = ((lane >> 4) & 1) * 8;
    int bRow = lane & 15;
    int bNof = ((lane >> 4) & 1) * 8;

    int nk = (Kreal + 31) >> 5;

    auto prefetch = [&](int kt) {
        int k0 = kt * 32;
        unsigned bufb = sbase + (kt & 1) * BUF_BYTES;
        // A: 64 rows x 64B = 256 x 16B chunks (zero-padded K in gmem, no guard)
        #pragma unroll
        for (int i = 0; i < 2; i++) {
            int c = tid + 128*i;
            int r = c >> 2, col8 = (c & 3) * 8;
            cp16(bufb + OFF_AH + r*PA + col8*2,
                 A + (size_t)(m0 + r)*lda + k0 + col8, true);
        }
        // B: 32 rows x 128B = 256 x 16B chunks (K guarded via zfill)
        #pragma unroll
        for (int i = 0; i < 2; i++) {
            int c = tid + 128*i;
            int r = c >> 3, col8 = (c & 7) * 8;
            int k = k0 + r;
            int ksafe = (k < Kreal) ? k : (Kreal - 1);
            cp16(bufb + OFF_BH + r*PB + col8*2,
                 B + (size_t)ksafe*ldb + n0 + col8, k < Kreal);
        }
        cp_commit();
    };

    prefetch(0);

    for (int kt = 0; kt < nk; kt++) {
        if (kt + 1 < nk) { prefetch(kt + 1); cp_wait<1>(); }
        else             { cp_wait<0>(); }
        __syncthreads();

        unsigned base = sbase + (kt & 1) * BUF_BYTES;
        #pragma unroll
        for (int ks = 0; ks < 2; ks++) {
            unsigned aAddrBase = base + (ks*16 + aKof) * 2;
            unsigned bAddrBase = base + (ks*16 + bRow) * PB;

            unsigned ah[2][4], bh[2][4];
            #pragma unroll
            for (int mt = 0; mt < 2; mt++)
                ldsm4(ah[mt], aAddrBase + OFF_AH + (warp_m*32 + mt*16 + aRow)*PA);
            #pragma unroll
            for (int np = 0; np < 2; np++)
                ldsm4t(bh[np], bAddrBase + OFF_BH + (warp_n*32 + np*16 + bNof)*2);

            #pragma unroll
            for (int mt = 0; mt < 2; mt++)
                #pragma unroll
                for (int nt = 0; nt < 4; nt++)
                    mma16816(acc[mt][nt], ah[mt], bh[nt>>1][(nt&1)*2], bh[nt>>1][(nt&1)*2+1]);
        }
        __syncthreads();
    }

    #pragma unroll
    for (int mt = 0; mt < 2; mt++) {
        int row0 = m0 + warp_m*32 + mt*16 + g;
        #pragma unroll
        for (int nt = 0; nt < 4; nt++) {
            int col = n0 + warp_n*32 + nt*8 + t*2;
            float* c = acc[mt][nt];
            float v0 = apply_epi<EPI>(c[0], row0,     col,     ep);
            float v1 = apply_epi<EPI>(c[1], row0,     col + 1, ep);
            float v2 = apply_epi<EPI>(c[2], row0 + 8, col,     ep);
            float v3 = apply_epi<EPI>(c[3], row0 + 8, col + 1, ep);
            if (GUARD) {
                if (C) {
                    if (col < ep.nreal)     C[(size_t)row0*ldc + col]         = v0;
                    if (col + 1 < ep.nreal) C[(size_t)row0*ldc + col + 1]     = v1;
                    if (col < ep.nreal)     C[(size_t)(row0+8)*ldc + col]     = v2;
                    if (col + 1 < ep.nreal) C[(size_t)(row0+8)*ldc + col + 1] = v3;
                }
            } else {
                if (C) {
                    *(float2*)(C + (size_t)row0*ldc + col)       = make_float2(v0, v1);
                    *(float2*)(C + (size_t)(row0 + 8)*ldc + col) = make_float2(v2, v3);
                }
                if (C16) {
                    __half2 h01 = __floats2half2_rn(v0, v1);
                    __half2 h23 = __floats2half2_rn(v2, v3);
                    *(__half2*)(C16 + (size_t)row0*ldc + col)       = h01;
                    *(__half2*)(C16 + (size_t)(row0 + 8)*ldc + col) = h23;
                }
            }
        }
    }
}

// ---------------------------------------------------------------------------
// Fused attention: Q fp32, K/V fp16 from gmem (raw copy staging), fp16 smem,
// ao written fp16. 2 q-rows/warp pass, 2 CTAs/SM.
// ---------------------------------------------------------------------------
#define KP 72
#define VTP 258
#define ATT_K_OFF 0
#define ATT_VT_OFF 36864
#define ATT_PS_OFF 69888
#define ATT_QS_OFF 86272
#define ATT_BS_OFF 90368
#define ATT_SMEM 91392

__global__ __launch_bounds__(256, 2)
void attention_kernel(const float* __restrict__ qb,
                      const __half* __restrict__ kb,
                      const __half* __restrict__ vb,
                      const unsigned char* __restrict__ pad,
                      __half* __restrict__ ob)
{
    int bh = blockIdx.x;
    int b = bh >> 3, h = bh & 7;
    extern __shared__ unsigned char smb[];
    __half* Ks = (__half*)(smb + ATT_K_OFF);
    __half* Vt = (__half*)(smb + ATT_VT_OFF);
    float* Ps  = (float*)(smb + ATT_PS_OFF);
    float* Qs  = (float*)(smb + ATT_QS_OFF);
    float* Bsb = (float*)(smb + ATT_BS_OFF);

    int tid = threadIdx.x, lane = tid & 31, w = tid >> 5;
    const __half* kbase = kb + (size_t)(b*SS)*DD + h*DHH;
    const __half* vbase = vb + (size_t)(b*SS)*DD + h*DHH;

    for (int idx = tid; idx < 256*64; idx += 256) {
        int r = idx >> 6, c = idx & 63;
        Ks[r*KP + c]  = kbase[(size_t)r*DD + c];
        Vt[c*VTP + r] = vbase[(size_t)r*DD + c];
    }
    if (tid < 256) Bsb[tid] = pad[b*SS + tid] ? -1e9f : 0.f;
    __syncthreads();

    float* Pw0 = Ps + (2*w + 0)*256;
    float* Pw1 = Ps + (2*w + 1)*256;
    float* Qw = Qs + w*128;

    for (int qi = 2*w; qi < SS; qi += 16) {
        const float* q0 = qb + (size_t)(b*SS + qi)*DD + h*DHH;
        Qw[lane]           = q0[lane];
        Qw[lane + 32]      = q0[lane + 32];
        Qw[64 + lane]      = q0[DD + lane];
        Qw[64 + lane + 32] = q0[DD + lane + 32];
        __syncwarp();

        const float4* q4a = (const float4*)Qw;
        const float4* q4b = (const float4*)(Qw + 64);

        float s0[8], s1[8];
        float mx0 = -3.402823466e+38f, mx1 = -3.402823466e+38f;
        #pragma unroll
        for (int k8 = 0; k8 < 8; k8++) {
            int j = lane + 32*k8;
            const uint4* kr4 = (const uint4*)(Ks + j*KP);
            float a0 = 0.f, a1 = 0.f;
            #pragma unroll
            for (int d8 = 0; d8 < 8; d8++) {
                uint4 kv = kr4[d8];
                float2 f0 = __half22float2(*(__half2*)&kv.x);
                float2 f1 = __half22float2(*(__half2*)&kv.y);
                float2 f2 = __half22float2(*(__half2*)&kv.z);
                float2 f3 = __half22float2(*(__half2*)&kv.w);
                float4 qa0 = q4a[d8*2],   qa1 = q4a[d8*2+1];
                float4 qb0 = q4b[d8*2],   qb1 = q4b[d8*2+1];
                a0 += qa0.x*f0.x + qa0.y*f0.y + qa0.z*f1.x + qa0.w*f1.y
                    + qa1.x*f2.x + qa1.y*f2.y + qa1.z*f3.x + qa1.w*f3.y;
                a1 += qb0.x*f0.x + qb0.y*f0.y + qb0.z*f1.x + qb0.w*f1.y
                    + qb1.x*f2.x + qb1.y*f2.y + qb1.z*f3.x + qb1.w*f3.y;
            }
            float bias = Bsb[j];
            a0 = a0 * 0.125f + bias;
            a1 = a1 * 0.125f + bias;
            s0[k8] = a0; s1[k8] = a1;
            mx0 = fmaxf(mx0, a0); mx1 = fmaxf(mx1, a1);
        }
        for (int off = 16; off; off >>= 1) {
            mx0 = fmaxf(mx0, __shfl_xor_sync(0xffffffffu, mx0, off));
            mx1 = fmaxf(mx1, __shfl_xor_sync(0xffffffffu, mx1, off));
        }
        float sm0 = 0.f, sm1 = 0.f;
        #pragma unroll
        for (int k8 = 0; k8 < 8; k8++) {
            s0[k8] = __expf(s0[k8] - mx0); sm0 += s0[k8];
            s1[k8] = __expf(s1[k8] - mx1); sm1 += s1[k8];
        }
        for (int off = 16; off; off >>= 1) {
            sm0 += __shfl_xor_sync(0xffffffffu, sm0, off);
            sm1 += __shfl_xor_sync(0xffffffffu, sm1, off);
        }
        float i0 = 1.f / sm0, i1 = 1.f / sm1;
        #pragma unroll
        for (int k8 = 0; k8 < 8; k8++) {
            Pw0[lane + 32*k8] = s0[k8]*i0;
            Pw1[lane + 32*k8] = s1[k8]*i1;
        }
        __syncwarp();

        const __half2* vtA = (const __half2*)(Vt + (size_t)lane*VTP);
        const __half2* vtB = (const __half2*)(Vt + (size_t)(lane+32)*VTP);
        const float2* P02 = (const float2*)Pw0;
        const float2* P12 = (const float2*)Pw1;
        float o00 = 0.f, o01 = 0.f, o10 = 0.f, o11 = 0.f;
        for (int j2 = 0; j2 < 128; j2++) {
            float2 p0 = P02[j2];
            float2 p1 = P12[j2];
            float2 vA = __half22float2(vtA[j2]);
            float2 vB = __half22float2(vtB[j2]);
            o00 += p0.x*vA.x + p0.y*vA.y;
            o01 += p0.x*vB.x + p0.y*vB.y;
            o10 += p1.x*vA.x + p1.y*vA.y;
            o11 += p1.x*vB.x + p1.y*vB.y;
        }
        __half* orow = ob + (size_t)(b*SS + qi)*DD + h*DHH;
        orow[lane]           = __float2half_rn(o00);
        orow[lane + 32]      = __float2half_rn(o01);
        orow[DD + lane]      = __float2half_rn(o10);
        orow[DD + lane + 32] = __float2half_rn(o11);
        __syncwarp();
    }
}

// ---------------------------------------------------------------------------
// Residual add + LayerNorm; optional fp32 and fp16 outputs
// ---------------------------------------------------------------------------
__global__ void ln_kernel(const float* __restrict__ x, const float* __restrict__ add,
                          const float* __restrict__ g, const float* __restrict__ bv,
                          float* __restrict__ out, __half* __restrict__ out16)
{
    int t = blockIdx.x;
    int tid = threadIdx.x;
    const float* xr = x   + (size_t)t*DD;
    const float* ar = add + (size_t)t*DD;
    float v[4];
    float s = 0.f, ss = 0.f;
    #pragma unroll
    for (int i = 0; i < 4; i++) {
        float u = xr[tid + 128*i] + ar[tid + 128*i];
        v[i] = u; s += u; ss += u*u;
    }
    for (int off = 16; off; off >>= 1) {
        s  += __shfl_xor_sync(0xffffffffu, s,  off);
        ss += __shfl_xor_sync(0xffffffffu, ss, off);
    }
    __shared__ float rs[4], rss[4];
    int w = tid >> 5, lane = tid & 31;
    if (lane == 0) { rs[w] = s; rss[w] = ss; }
    __syncthreads();
    s  = rs[0]+rs[1]+rs[2]+rs[3];
    ss = rss[0]+rss[1]+rss[2]+rss[3];
    float mean = s * (1.f/512.f);
    float var  = ss * (1.f/512.f) - mean*mean;
    float rstd = rsqrtf(var + 1e-5f);
    #pragma unroll
    for (int i = 0; i < 4; i++) {
        int c = tid + 128*i;
        float o = (v[i]-mean)*rstd*g[c] + bv[c];
        if (out)   out[(size_t)t*DD + c] = o;
        if (out16) out16[(size_t)t*DD + c] = __float2half_rn(o);
    }
}

// ---------------------------------------------------------------------------
// Launch
// ---------------------------------------------------------------------------
extern "C" void kernel_launch(void* const* d_in, const int* in_sizes, int n_in,
                              void* d_out, int out_size)
{
    const float* x_l  = (const float*)d_in[0];
    const float* x_r  = (const float*)d_in[1];
    const float* j_l  = (const float*)d_in[2];
    const float* j_r  = (const float*)d_in[3];
    const float* mcon = (const float*)d_in[4];
    const float* pc   = (const float*)d_in[5];
    const float* mask_l = (const float*)d_in[6];
    const float* mask_r = (const float*)d_in[7];
    const unsigned char* pad = (const unsigned char*)d_in[8];
    const float* W_fc_l = (const float*)d_in[9];
    const float* b_fc_l = (const float*)d_in[10];
    const float* W_fc_r = (const float*)d_in[11];
    const float* b_fc_r = (const float*)d_in[12];
    const float* Wq = (const float*)d_in[13];
    const float* Wk = (const float*)d_in[14];
    const float* Wv = (const float*)d_in[15];
    const float* Wo = (const float*)d_in[16];
    const float* W1 = (const float*)d_in[17];
    const float* b1 = (const float*)d_in[18];
    const float* W2 = (const float*)d_in[19];
    const float* b2 = (const float*)d_in[20];
    const float* ln1g = (const float*)d_in[21];
    const float* ln1b = (const float*)d_in[22];
    const float* ln2g = (const float*)d_in[23];
    const float* ln2b = (const float*)d_in[24];
    const float* W_out_l = (const float*)d_in[25];
    const float* b_out_l = (const float*)d_in[26];
    const float* W_out_r = (const float*)d_in[27];
    const float* b_out_r = (const float*)d_in[28];
    float* outp = (float*)d_out;

    float *px, *pq, *pproj, *px1, *pf;
    __half *pfl16, *pfr16, *px16, *pk16, *pv16, *pao16, *px116, *ph16, *px216;
    __half *wfcl, *wfcr, *wq16, *wk16, *wv16, *wo16, *w116, *w216, *pwl, *pwr;
    cudaGetSymbolAddress((void**)&px,    g_x);
    cudaGetSymbolAddress((void**)&pq,    g_q);
    cudaGetSymbolAddress((void**)&pproj, g_proj);
    cudaGetSymbolAddress((void**)&px1,   g_x1);
    cudaGetSymbolAddress((void**)&pf,    g_f);
    cudaGetSymbolAddress((void**)&pfl16, g_feat16_l);
    cudaGetSymbolAddress((void**)&pfr16, g_feat16_r);
    cudaGetSymbolAddress((void**)&px16,  g_x16);
    cudaGetSymbolAddress((void**)&pk16,  g_k16);
    cudaGetSymbolAddress((void**)&pv16,  g_v16);
    cudaGetSymbolAddress((void**)&pao16, g_ao16);
    cudaGetSymbolAddress((void**)&px116, g_x116);
    cudaGetSymbolAddress((void**)&ph16,  g_h16);
    cudaGetSymbolAddress((void**)&px216, g_x216);
    cudaGetSymbolAddress((void**)&wfcl,  g_wfc_l16);
    cudaGetSymbolAddress((void**)&wfcr,  g_wfc_r16);
    cudaGetSymbolAddress((void**)&wq16,  g_wq16);
    cudaGetSymbolAddress((void**)&wk16,  g_wk16);
    cudaGetSymbolAddress((void**)&wv16,  g_wv16);
    cudaGetSymbolAddress((void**)&wo16,  g_wo16);
    cudaGetSymbolAddress((void**)&w116,  g_w116);
    cudaGetSymbolAddress((void**)&w216,  g_w216);
    cudaGetSymbolAddress((void**)&pwl,   g_woutl16);
    cudaGetSymbolAddress((void**)&pwr,   g_woutr16);

    cudaFuncSetAttribute((const void*)tgemm<0,0,1>, cudaFuncAttributeMaxDynamicSharedMemorySize, TG_SMEM);
    cudaFuncSetAttribute((const void*)tgemm<0,0,3>, cudaFuncAttributeMaxDynamicSharedMemorySize, TG_SMEM);
    cudaFuncSetAttribute((const void*)tgemm<1,0,2>, cudaFuncAttributeMaxDynamicSharedMemorySize, TG_SMEM);
    cudaFuncSetAttribute((const void*)tgemm<2,1,2>, cudaFuncAttributeMaxDynamicSharedMemorySize, TG_SMEM);
    cudaFuncSetAttribute(attention_kernel,
                         cudaFuncAttributeMaxDynamicSharedMemorySize, ATT_SMEM);

    EpiParams none = {nullptr, nullptr, nullptr, 0, 0, 0};

    // 0. weight conversion + head-weight padding
    {
        CvtJobs cj;
        cj.src[0] = W_fc_l; cj.dst[0] = wfcl; cj.n4[0] = (CAT*DD)/4;
        cj.src[1] = W_fc_r; cj.dst[1] = wfcr; cj.n4[1] = (CAT*DD)/4;
        cj.src[2] = Wq;     cj.dst[2] = wq16; cj.n4[2] = (DD*DD)/4;
        cj.src[3] = Wk;     cj.dst[3] = wk16; cj.n4[3] = (DD*DD)/4;
        cj.src[4] = Wv;     cj.dst[4] = wv16; cj.n4[4] = (DD*DD)/4;
        cj.src[5] = Wo;     cj.dst[5] = wo16; cj.n4[5] = (DD*DD)/4;
        cj.src[6] = W1;     cj.dst[6] = w116; cj.n4[6] = (DD*DFF)/4;
        cj.src[7] = W2;     cj.dst[7] = w216; cj.n4[7] = (DFF*DD)/4;
        cvt_weights_kernel<<<1024, 256>>>(cj);
    }
    pad_wout_kernel<<<256, 256>>>(W_out_l, W_out_r, pwl, pwr);

    // 1. features (fp16)
    build_features_kernel<<<ROWS, 256>>>(x_l, x_r, j_l, j_r, mcon, pc, pfl16, pfr16);

    // 2. fc projections (merged l+r): fp32 x (residual) + fp16 x (QKV A)
    {
        Jobs<2> jb;
        jb.j[0] = { pfl16, wfcl, px,      px16,      {b_fc_l, mask_l, pad, 0, 0, 0} };
        jb.j[1] = { pfr16, wfcr, px + DD, px16 + DD, {b_fc_r, mask_r, pad, 1, 0, 0} };
        tgemm<1,0,2><<<dim3(8,64,2), 128, TG_SMEM>>>(jb, CATP, DD, 2*DD, ROWS, DD, CAT);
    }

    // 3. QKV (merged): q fp32; k,v fp16
    {
        Jobs<3> jb;
        jb.j[0] = { px16, wq16, pq,      nullptr, none };
        jb.j[1] = { px16, wk16, nullptr, pk16,    none };
        jb.j[2] = { px16, wv16, nullptr, pv16,    none };
        tgemm<0,0,3><<<dim3(8,128,3), 128, TG_SMEM>>>(jb, DD, DD, DD, TROWS, DD, DD);
    }

    // 4. attention (ao fp16)
    attention_kernel<<<BB*HH, 256, ATT_SMEM>>>(pq, pk16, pv16, pad, pao16);

    // 5. Wo + LN1
    {
        Jobs<1> jb; jb.j[0] = { pao16, wo16, pproj, nullptr, none };
        tgemm<0,0,1><<<dim3(8,128,1), 128, TG_SMEM>>>(jb, DD, DD, DD, TROWS, DD, DD);
    }
    ln_kernel<<<TROWS, 128>>>(px, pproj, ln1g, ln1b, px1, px116);

    // 6. FFN + LN2
    {
        Jobs<1> jb; jb.j[0] = { px116, w116, nullptr, ph16, {b1, nullptr, nullptr, 0, 1, 0} };
        tgemm<0,0,1><<<dim3(32,128,1), 128, TG_SMEM>>>(jb, DD, DFF, DFF, TROWS, DFF, DD);
    }
    {
        Jobs<1> jb; jb.j[0] = { ph16, w216, pf, nullptr, {b2, nullptr, nullptr, 0, 0, 0} };
        tgemm<0,0,1><<<dim3(8,128,1), 128, TG_SMEM>>>(jb, DFF, DD, DD, TROWS, DD, DFF);
    }
    ln_kernel<<<TROWS, 128>>>(px1, pf, ln2g, ln2b, nullptr, px216);

    // 7. output heads (merged l+r, guarded cols)
    {
        Jobs<2> jb;
        jb.j[0] = { px216,      pwl, outp,                 nullptr, {b_out_l, mask_l, pad, 0, 0, HAND_DIM} };
        jb.j[1] = { px216 + DD, pwr, outp + ROWS*HAND_DIM, nullptr, {b_out_r, mask_r, pad, 1, 0, HAND_DIM} };
        tgemm<2,1,2><<<dim3(2,64,2), 128, TG_SMEM>>>(jb, 2*DD, 128, HAND_DIM, ROWS, 128, DD);
    }
}